// round 1
// baseline (speedup 1.0000x reference)
#include <cuda_runtime.h>
#include <math.h>

// ---------------- problem constants ----------------
#define DD 8
#define HH 64
#define WW 64
#define LTOK 32768            // D*H*W
#define CCH 96
#define CMP 32
#define HID 384
#define HEADS 6
#define HDIM 16
#define NWIN 64               // (D/8)*(H/8)*(W/8)
#define NTOK 512              // 8^3 window tokens
#define TBL 3375

// ---------------- scratch (static device memory; no allocs allowed) ----------------
__device__ float g_xn   [LTOK * CCH];
__device__ float g_y1   [LTOK * CMP];
__device__ float g_y2   [LTOK * CCH];
__device__ float g_part [256 * CCH];
__device__ float g_att  [CCH];
__device__ float g_qkv  [LTOK * 3 * CCH];
__device__ float g_bias [HEADS * NTOK * NTOK];
__device__ float g_o    [LTOK * CCH];
__device__ float g_x1   [LTOK * CCH];
__device__ float g_xn2  [LTOK * CCH];
__device__ float g_h    [LTOK * HID];
__device__ float g_w1r  [27 * CMP * CCH];
__device__ float g_w2r  [27 * CCH * CMP];

__device__ __forceinline__ float gelu_exact(float v) {
    return 0.5f * v * (1.0f + erff(v * 0.70710678118654752f));
}

// ---------------- LayerNorm: one warp per 96-channel row ----------------
__global__ void ln_kernel(const float* __restrict__ x, const float* __restrict__ g,
                          const float* __restrict__ b, float* __restrict__ out)
{
    int row  = blockIdx.x * 8 + (threadIdx.x >> 5);
    int lane = threadIdx.x & 31;
    const float* xr = x + (size_t)row * CCH;
    float v0 = xr[lane], v1 = xr[lane + 32], v2 = xr[lane + 64];
    float s = v0 + v1 + v2;
    #pragma unroll
    for (int o = 16; o; o >>= 1) s += __shfl_xor_sync(0xffffffffu, s, o);
    float mu = s * (1.0f / 96.0f);
    float d0 = v0 - mu, d1 = v1 - mu, d2 = v2 - mu;
    float q = d0 * d0 + d1 * d1 + d2 * d2;
    #pragma unroll
    for (int o = 16; o; o >>= 1) q += __shfl_xor_sync(0xffffffffu, q, o);
    float inv = rsqrtf(q * (1.0f / 96.0f) + 1e-5f);
    float* orow = out + (size_t)row * CCH;
    orow[lane]      = d0 * inv * g[lane]      + b[lane];
    orow[lane + 32] = d1 * inv * g[lane + 32] + b[lane + 32];
    orow[lane + 64] = d2 * inv * g[lane + 64] + b[lane + 64];
}

// ---------------- weight reorders (coalesced conv weight layout) ----------------
// conv1_w: [o=32][c=96][tap=27]  -> w1r[tap][o][c]
__global__ void reorder_w1(const float* __restrict__ w, float* __restrict__ wr)
{
    int tid = blockIdx.x * 256 + threadIdx.x;
    if (tid >= CMP * CCH * 27) return;
    int o = tid / (CCH * 27);
    int rem = tid - o * (CCH * 27);
    int c = rem / 27;
    int tap = rem - c * 27;
    wr[(tap * CMP + o) * CCH + c] = w[tid];
}
// conv2_w: [o=96][i=32][tap=27] -> w2r[tap][o][i]
__global__ void reorder_w2(const float* __restrict__ w, float* __restrict__ wr)
{
    int tid = blockIdx.x * 256 + threadIdx.x;
    if (tid >= CCH * CMP * 27) return;
    int o = tid / (CMP * 27);
    int rem = tid - o * (CMP * 27);
    int i = rem / 27;
    int tap = rem - i * 27;
    wr[(tap * CCH + o) * CMP + i] = w[tid];
}

// ---------------- conv1 (96 -> 32, 3x3x3, GELU) ----------------
// block = one (d,h) row of 64 voxels x 32 out-ch; 128 threads; thread -> 4 voxels x 4 oc
__global__ void conv1_kernel(const float* __restrict__ xn, const float* __restrict__ w1r,
                             const float* __restrict__ b1, float* __restrict__ y1)
{
    extern __shared__ float sm[];
    float* in_s = sm;           // 66 * 100
    float* w_s  = sm + 6600;    // 3 * 32 * 100
    int d = blockIdx.x >> 6, h = blockIdx.x & 63;
    int tx = threadIdx.x;
    int og = tx >> 4, vg = tx & 15;
    float acc[4][4] = {};
    for (int kd = 0; kd < 3; kd++) {
        int dd = d + kd - 1;
        for (int kh = 0; kh < 3; kh++) {
            int hh = h + kh - 1;
            bool rv = ((unsigned)dd < (unsigned)DD) && ((unsigned)hh < (unsigned)HH);
            __syncthreads();
            const float* src_row = xn + ((size_t)(dd * HH + hh) * WW) * CCH;
            for (int idx = tx * 4; idx < 66 * 96; idx += 512) {
                int r = idx / 96, c = idx - r * 96;
                int wv = r - 1;
                float4 val = make_float4(0.f, 0.f, 0.f, 0.f);
                if (rv && (unsigned)wv < 64u) val = *(const float4*)(src_row + wv * CCH + c);
                *(float4*)(in_s + r * 100 + c) = val;
            }
            const float* wsrc = w1r + (kd * 3 + kh) * 3 * (CMP * CCH);
            for (int idx = tx * 4; idx < 3 * CMP * CCH; idx += 512) {
                int kw = idx / (CMP * CCH), r2 = idx - kw * (CMP * CCH);
                int o = r2 / CCH, c = r2 - o * CCH;
                *(float4*)(w_s + (kw * 32 + o) * 100 + c) = *(const float4*)(wsrc + idx);
            }
            __syncthreads();
            #pragma unroll
            for (int kw = 0; kw < 3; kw++) {
                #pragma unroll
                for (int c4 = 0; c4 < 24; c4++) {
                    float4 wv4[4];
                    #pragma unroll
                    for (int oi = 0; oi < 4; oi++)
                        wv4[oi] = *(float4*)(w_s + (kw * 32 + og * 4 + oi) * 100 + c4 * 4);
                    #pragma unroll
                    for (int vi = 0; vi < 4; vi++) {
                        float4 xv = *(float4*)(in_s + (vg + 16 * vi + kw) * 100 + c4 * 4);
                        #pragma unroll
                        for (int oi = 0; oi < 4; oi++)
                            acc[vi][oi] += xv.x * wv4[oi].x + xv.y * wv4[oi].y
                                         + xv.z * wv4[oi].z + xv.w * wv4[oi].w;
                    }
                }
            }
        }
    }
    float* orow = y1 + (size_t)(d * HH + h) * WW * CMP;
    #pragma unroll
    for (int vi = 0; vi < 4; vi++) {
        int v = vg + 16 * vi;
        #pragma unroll
        for (int oi = 0; oi < 4; oi++) {
            int oc = og * 4 + oi;
            orow[v * CMP + oc] = gelu_exact(acc[vi][oi] + b1[oc]);
        }
    }
}

// ---------------- conv2 (32 -> 96, 3x3x3, no act) ----------------
// block = one (d,h) row x 96 oc; 384 threads; thread -> 4 voxels x 4 oc
__global__ void conv2_kernel(const float* __restrict__ y1, const float* __restrict__ w2r,
                             const float* __restrict__ b2, float* __restrict__ y2)
{
    extern __shared__ float sm[];
    float* in_s = sm;           // 66 * 36
    float* w_s  = sm + 2376;    // 3 * 96 * 36
    int d = blockIdx.x >> 6, h = blockIdx.x & 63;
    int tx = threadIdx.x;
    int og = tx >> 4, vg = tx & 15;   // og 0..23
    float acc[4][4] = {};
    for (int kd = 0; kd < 3; kd++) {
        int dd = d + kd - 1;
        for (int kh = 0; kh < 3; kh++) {
            int hh = h + kh - 1;
            bool rv = ((unsigned)dd < (unsigned)DD) && ((unsigned)hh < (unsigned)HH);
            __syncthreads();
            const float* src_row = y1 + ((size_t)(dd * HH + hh) * WW) * CMP;
            for (int idx = tx * 4; idx < 66 * 32; idx += 1536) {
                int r = idx >> 5, c = idx & 31;
                int wv = r - 1;
                float4 val = make_float4(0.f, 0.f, 0.f, 0.f);
                if (rv && (unsigned)wv < 64u) val = *(const float4*)(src_row + wv * CMP + c);
                *(float4*)(in_s + r * 36 + c) = val;
            }
            const float* wsrc = w2r + (kd * 3 + kh) * 3 * (CCH * CMP);
            for (int idx = tx * 4; idx < 3 * CCH * CMP; idx += 1536) {
                int kw = idx / (CCH * CMP), r2 = idx - kw * (CCH * CMP);
                int o = r2 >> 5, c = r2 & 31;
                *(float4*)(w_s + (kw * 96 + o) * 36 + c) = *(const float4*)(wsrc + idx);
            }
            __syncthreads();
            #pragma unroll
            for (int kw = 0; kw < 3; kw++) {
                #pragma unroll
                for (int c4 = 0; c4 < 8; c4++) {
                    float4 wv4[4];
                    #pragma unroll
                    for (int oi = 0; oi < 4; oi++)
                        wv4[oi] = *(float4*)(w_s + (kw * 96 + og * 4 + oi) * 36 + c4 * 4);
                    #pragma unroll
                    for (int vi = 0; vi < 4; vi++) {
                        float4 xv = *(float4*)(in_s + (vg + 16 * vi + kw) * 36 + c4 * 4);
                        #pragma unroll
                        for (int oi = 0; oi < 4; oi++)
                            acc[vi][oi] += xv.x * wv4[oi].x + xv.y * wv4[oi].y
                                         + xv.z * wv4[oi].z + xv.w * wv4[oi].w;
                    }
                }
            }
        }
    }
    float* orow = y2 + (size_t)(d * HH + h) * WW * CCH;
    #pragma unroll
    for (int vi = 0; vi < 4; vi++) {
        int v = vg + 16 * vi;
        #pragma unroll
        for (int oi = 0; oi < 4; oi++) {
            int oc = og * 4 + oi;
            orow[v * CCH + oc] = acc[vi][oi] + b2[oc];
        }
    }
}

// ---------------- pooling (deterministic 2-stage) + channel attention ----------------
__global__ void pool_kernel(const float* __restrict__ y2, float* __restrict__ part)
{
    int c = threadIdx.x;                       // 96 threads
    const float* base = y2 + (size_t)blockIdx.x * 128 * CCH;
    float s = 0.f;
    for (int v = 0; v < 128; v++) s += base[v * CCH + c];
    part[blockIdx.x * CCH + c] = s;
}

__global__ void ca_kernel(const float* __restrict__ part,
                          const float* __restrict__ ca1w, const float* __restrict__ ca1b,
                          const float* __restrict__ ca2w, const float* __restrict__ ca2b,
                          float* __restrict__ att)
{
    __shared__ float p[CCH], hs[3];
    int tx = threadIdx.x;                      // 96 threads
    float s = 0.f;
    for (int b = 0; b < 256; b++) s += part[b * CCH + tx];
    p[tx] = s * (1.0f / (float)LTOK);
    __syncthreads();
    if (tx < 3) {
        float a = ca1b[tx];
        for (int c = 0; c < CCH; c++) a += ca1w[tx * CCH + c] * p[c];
        hs[tx] = fmaxf(a, 0.f);
    }
    __syncthreads();
    float a = ca2b[tx];
    #pragma unroll
    for (int k = 0; k < 3; k++) a += ca2w[tx * 3 + k] * hs[k];
    att[tx] = 1.0f / (1.0f + expf(-a));
}

// ---------------- relative position bias expansion: [6][512][512] ----------------
__global__ void expand_bias(const int* __restrict__ rpi, const float* __restrict__ rpbt,
                            float* __restrict__ bias)
{
    int tid = blockIdx.x * 256 + threadIdx.x;  // 6*512*512 = 1572864
    int h = tid >> 18;
    int r = tid & 262143;
    bias[tid] = rpbt[rpi[r] * HEADS + h];
}

// ---------------- generic GEMM: C[M][N] = A[M][K] @ W[N][K]^T + bias, fused epilogues ----------
// EPI: 0 none, 1 GELU, 2 proj-residual (res1 + v + res2*att[n]*0.01), 3 residual (res1 + v)
template <int EPI>
__global__ void gemm_kernel(const float* __restrict__ A, const float* __restrict__ Wm,
                            const float* __restrict__ bias, float* __restrict__ C,
                            int M, int Nn, int K,
                            const float* __restrict__ res1, const float* __restrict__ res2,
                            const float* __restrict__ att)
{
    extern __shared__ float sm[];
    float* a_s = sm;            // 64 * 100
    float* w_s = sm + 6400;     // 64 * 100
    int m0 = blockIdx.x * 64, n0 = blockIdx.y * 64;
    int tx = threadIdx.x;
    int mg = tx & 15, ng = tx >> 4;
    float acc[4][4] = {};
    for (int k0 = 0; k0 < K; k0 += 96) {
        __syncthreads();
        for (int idx = tx * 4; idx < 64 * 96; idx += 1024) {
            int r = idx / 96, c = idx - r * 96;
            *(float4*)(a_s + r * 100 + c) = *(const float4*)(A + (size_t)(m0 + r) * K + k0 + c);
        }
        for (int idx = tx * 4; idx < 64 * 96; idx += 1024) {
            int r = idx / 96, c = idx - r * 96;
            float4 v = make_float4(0.f, 0.f, 0.f, 0.f);
            if (n0 + r < Nn) v = *(const float4*)(Wm + (size_t)(n0 + r) * K + k0 + c);
            *(float4*)(w_s + r * 100 + c) = v;
        }
        __syncthreads();
        #pragma unroll
        for (int c4 = 0; c4 < 24; c4++) {
            float4 wv[4];
            #pragma unroll
            for (int ni = 0; ni < 4; ni++)
                wv[ni] = *(float4*)(w_s + (ng + 16 * ni) * 100 + c4 * 4);
            #pragma unroll
            for (int mi = 0; mi < 4; mi++) {
                float4 av = *(float4*)(a_s + (mg + 16 * mi) * 100 + c4 * 4);
                #pragma unroll
                for (int ni = 0; ni < 4; ni++)
                    acc[mi][ni] += av.x * wv[ni].x + av.y * wv[ni].y
                                 + av.z * wv[ni].z + av.w * wv[ni].w;
            }
        }
    }
    #pragma unroll
    for (int mi = 0; mi < 4; mi++) {
        int m = m0 + mg + 16 * mi;
        #pragma unroll
        for (int ni = 0; ni < 4; ni++) {
            int n = n0 + ng + 16 * ni;
            if (n < Nn) {
                float v = acc[mi][ni] + bias[n];
                size_t idx = (size_t)m * Nn + n;
                if (EPI == 1) v = gelu_exact(v);
                else if (EPI == 2) v = res1[idx] + v + res2[idx] * att[n] * 0.01f;
                else if (EPI == 3) v = res1[idx] + v;
                C[idx] = v;
            }
        }
    }
}

// ---------------- window attention: block = (window, head, 64-query chunk) ----------------
__global__ void attn_kernel(const float* __restrict__ qkv, const float* __restrict__ bias_g,
                            float* __restrict__ o)
{
    extern __shared__ float sm[];
    float* q_s = sm;            // 64 * 20
    float* k_s = sm + 1280;     // 512 * 20
    float* v_s = sm + 11520;    // 512 * 20
    float* sc  = sm + 21760;    // 64 * 516
    int b = blockIdx.x;
    int qc = b & 7;
    int head = (b >> 3) % 6;
    int win = b / 48;
    int wh = win >> 3, ww = win & 7;
    int base = wh * 512 + ww * 8;    // token of (id=0, ih=0, iw=0)
    int tx = threadIdx.x;

    for (int idx = tx; idx < 2048; idx += 256) {
        int j = idx >> 2, c4 = idx & 3;
        int t = ((j >> 6) << 12) + base + (((j >> 3) & 7) << 6) + (j & 7);
        const float* p = qkv + (size_t)t * 288 + head * HDIM + c4 * 4;
        *(float4*)(k_s + j * 20 + c4 * 4) = *(const float4*)(p + 96);
        *(float4*)(v_s + j * 20 + c4 * 4) = *(const float4*)(p + 192);
    }
    {
        int idx = tx;   // 256 = 64 rows * 4 float4
        int i = idx >> 2, c4 = idx & 3;
        int j = qc * 64 + i;
        int t = ((j >> 6) << 12) + base + (((j >> 3) & 7) << 6) + (j & 7);
        float4 v = *(const float4*)(qkv + (size_t)t * 288 + head * HDIM + c4 * 4);
        v.x *= 0.25f; v.y *= 0.25f; v.z *= 0.25f; v.w *= 0.25f;
        *(float4*)(q_s + i * 20 + c4 * 4) = v;
    }
    __syncthreads();

    // scores = (q*scale) @ k^T + bias
    const float* brow = bias_g + head * (NTOK * NTOK) + (qc * 64) * NTOK;
    for (int p = 0; p < 128; p++) {
        int idx = tx + p * 256;
        int i = idx >> 9, j = idx & 511;
        float acc = brow[i * NTOK + j];
        #pragma unroll
        for (int c4 = 0; c4 < 4; c4++) {
            float4 a = *(float4*)(q_s + i * 20 + c4 * 4);
            float4 kk = *(float4*)(k_s + j * 20 + c4 * 4);
            acc += a.x * kk.x + a.y * kk.y + a.z * kk.z + a.w * kk.w;
        }
        sc[i * 516 + j] = acc;
    }
    __syncthreads();

    // softmax: each warp does 8 rows
    int w = tx >> 5, lane = tx & 31;
    for (int r = 0; r < 8; r++) {
        float* srow = sc + (w * 8 + r) * 516;
        float m = -1e30f;
        #pragma unroll
        for (int jj = 0; jj < 16; jj++) m = fmaxf(m, srow[lane + jj * 32]);
        #pragma unroll
        for (int off = 16; off; off >>= 1) m = fmaxf(m, __shfl_xor_sync(0xffffffffu, m, off));
        float ssum = 0.f;
        #pragma unroll
        for (int jj = 0; jj < 16; jj++) {
            float e = __expf(srow[lane + jj * 32] - m);
            srow[lane + jj * 32] = e;
            ssum += e;
        }
        #pragma unroll
        for (int off = 16; off; off >>= 1) ssum += __shfl_xor_sync(0xffffffffu, ssum, off);
        float inv = 1.0f / ssum;
        #pragma unroll
        for (int jj = 0; jj < 16; jj++) srow[lane + jj * 32] *= inv;
    }
    __syncthreads();

    // o = P @ V ; write in window-reversed token order
    {
        int i = tx >> 2, dg = tx & 3;
        float4 acc = make_float4(0.f, 0.f, 0.f, 0.f);
        const float* srow = sc + i * 516;
        #pragma unroll 4
        for (int j = 0; j < 512; j++) {
            float pv = srow[j];
            float4 vv = *(float4*)(v_s + j * 20 + dg * 4);
            acc.x += pv * vv.x; acc.y += pv * vv.y;
            acc.z += pv * vv.z; acc.w += pv * vv.w;
        }
        int jg = qc * 64 + i;
        int t = ((jg >> 6) << 12) + base + (((jg >> 3) & 7) << 6) + (jg & 7);
        *(float4*)(o + (size_t)t * CCH + head * HDIM + dg * 4) = acc;
    }
}

// ---------------- launch ----------------
extern "C" void kernel_launch(void* const* d_in, const int* in_sizes, int n_in,
                              void* d_out, int out_size)
{
    (void)in_sizes; (void)n_in; (void)out_size;
    const float* x       = (const float*)d_in[0];
    const float* n1g     = (const float*)d_in[1];
    const float* n1b     = (const float*)d_in[2];
    const float* qkv_w   = (const float*)d_in[3];
    const float* qkv_b   = (const float*)d_in[4];
    const float* rpbt    = (const float*)d_in[5];
    const float* proj_w  = (const float*)d_in[6];
    const float* proj_b  = (const float*)d_in[7];
    const float* conv1_w = (const float*)d_in[8];
    const float* conv1_b = (const float*)d_in[9];
    const float* conv2_w = (const float*)d_in[10];
    const float* conv2_b = (const float*)d_in[11];
    const float* ca1_w   = (const float*)d_in[12];
    const float* ca1_b   = (const float*)d_in[13];
    const float* ca2_w   = (const float*)d_in[14];
    const float* ca2_b   = (const float*)d_in[15];
    const float* n2g     = (const float*)d_in[16];
    const float* n2b     = (const float*)d_in[17];
    const float* fc1_w   = (const float*)d_in[18];
    const float* fc1_b   = (const float*)d_in[19];
    const float* fc2_w   = (const float*)d_in[20];
    const float* fc2_b   = (const float*)d_in[21];
    const int*   rpi     = (const int*)d_in[22];
    float* out = (float*)d_out;

    float *xn, *y1, *y2, *part, *att, *qkvb, *biasb, *ob, *x1, *xn2, *hb, *w1r, *w2r;
    cudaGetSymbolAddress((void**)&xn,    g_xn);
    cudaGetSymbolAddress((void**)&y1,    g_y1);
    cudaGetSymbolAddress((void**)&y2,    g_y2);
    cudaGetSymbolAddress((void**)&part,  g_part);
    cudaGetSymbolAddress((void**)&att,   g_att);
    cudaGetSymbolAddress((void**)&qkvb,  g_qkv);
    cudaGetSymbolAddress((void**)&biasb, g_bias);
    cudaGetSymbolAddress((void**)&ob,    g_o);
    cudaGetSymbolAddress((void**)&x1,    g_x1);
    cudaGetSymbolAddress((void**)&xn2,   g_xn2);
    cudaGetSymbolAddress((void**)&hb,    g_h);
    cudaGetSymbolAddress((void**)&w1r,   g_w1r);
    cudaGetSymbolAddress((void**)&w2r,   g_w2r);

    const int SMEM_CONV1 = (6600 + 9600) * 4;          // 64800
    const int SMEM_CONV2 = (2376 + 10368) * 4;         // 50976
    const int SMEM_GEMM  = 12800 * 4;                  // 51200
    const int SMEM_ATTN  = (21760 + 64 * 516) * 4;     // 219136
    cudaFuncSetAttribute(conv1_kernel, cudaFuncAttributeMaxDynamicSharedMemorySize, SMEM_CONV1);
    cudaFuncSetAttribute(conv2_kernel, cudaFuncAttributeMaxDynamicSharedMemorySize, SMEM_CONV2);
    cudaFuncSetAttribute(gemm_kernel<0>, cudaFuncAttributeMaxDynamicSharedMemorySize, SMEM_GEMM);
    cudaFuncSetAttribute(gemm_kernel<1>, cudaFuncAttributeMaxDynamicSharedMemorySize, SMEM_GEMM);
    cudaFuncSetAttribute(gemm_kernel<2>, cudaFuncAttributeMaxDynamicSharedMemorySize, SMEM_GEMM);
    cudaFuncSetAttribute(gemm_kernel<3>, cudaFuncAttributeMaxDynamicSharedMemorySize, SMEM_GEMM);
    cudaFuncSetAttribute(attn_kernel, cudaFuncAttributeMaxDynamicSharedMemorySize, SMEM_ATTN);

    // weight reorders (deterministic, every call)
    reorder_w1<<<(CMP * CCH * 27 + 255) / 256, 256>>>(conv1_w, w1r);
    reorder_w2<<<(CCH * CMP * 27 + 255) / 256, 256>>>(conv2_w, w2r);

    // LN1
    ln_kernel<<<LTOK / 8, 256>>>(x, n1g, n1b, xn);

    // conv branch
    conv1_kernel<<<DD * HH, 128, SMEM_CONV1>>>(xn, w1r, conv1_b, y1);
    conv2_kernel<<<DD * HH, 384, SMEM_CONV2>>>(y1, w2r, conv2_b, y2);
    pool_kernel<<<256, CCH>>>(y2, part);
    ca_kernel<<<1, CCH>>>(part, ca1_w, ca1_b, ca2_w, ca2_b, att);

    // attention branch
    expand_bias<<<HEADS * NTOK * NTOK / 256, 256>>>(rpi, rpbt, biasb);
    gemm_kernel<0><<<dim3(LTOK / 64, (288 + 63) / 64), 256, SMEM_GEMM>>>(
        xn, qkv_w, qkv_b, qkvb, LTOK, 288, 96, nullptr, nullptr, nullptr);
    attn_kernel<<<NWIN * HEADS * 8, 256, SMEM_ATTN>>>(qkvb, biasb, ob);

    // proj + residual + conv branch merge:  x1 = x + (o@W+b) + y2*att*0.01
    gemm_kernel<2><<<dim3(LTOK / 64, 2), 256, SMEM_GEMM>>>(
        ob, proj_w, proj_b, x1, LTOK, 96, 96, x, y2, att);

    // MLP
    ln_kernel<<<LTOK / 8, 256>>>(x1, n2g, n2b, xn2);
    gemm_kernel<1><<<dim3(LTOK / 64, HID / 64), 256, SMEM_GEMM>>>(
        xn2, fc1_w, fc1_b, hb, LTOK, HID, 96, nullptr, nullptr, nullptr);
    gemm_kernel<3><<<dim3(LTOK / 64, 2), 256, SMEM_GEMM>>>(
        hb, fc2_w, fc2_b, out, LTOK, 96, HID, x1, nullptr, nullptr);
}

// round 2
// speedup vs baseline: 2.0516x; 2.0516x over previous
#include <cuda_runtime.h>
#include <math.h>
#include <stdint.h>

// ---------------- problem constants ----------------
#define DD 8
#define HH 64
#define WW 64
#define LTOK 32768            // D*H*W
#define CCH 96
#define CMP 32
#define HID 384
#define HEADS 6
#define HDIM 16
#define NWIN 64
#define NTOK 512
#define TBL 3375

// ---------------- scratch ----------------
__device__ float g_xn   [LTOK * CCH];
__device__ float g_y1   [LTOK * CMP];
__device__ float g_y2   [LTOK * CCH];
__device__ float g_part [256 * CCH];
__device__ float g_att  [CCH];
__device__ float g_qkv  [LTOK * 3 * CCH];
__device__ float g_bias [HEADS * NTOK * NTOK];
__device__ float g_o    [LTOK * CCH];
__device__ float g_x1   [LTOK * CCH];
__device__ float g_xn2  [LTOK * CCH];
__device__ float g_h    [LTOK * HID];
__device__ float g_w1r  [27 * CMP * CCH];
__device__ float g_w2r  [27 * CCH * CMP];

__device__ __forceinline__ float gelu_exact(float v) {
    return 0.5f * v * (1.0f + erff(v * 0.70710678118654752f));
}

// ---- tf32 m16n8k8 mma ----
__device__ __forceinline__ void mma8(float* d, const float* a, const float* b) {
    asm volatile(
        "mma.sync.aligned.m16n8k8.row.col.f32.tf32.tf32.f32 "
        "{%0,%1,%2,%3},{%4,%5,%6,%7},{%8,%9},{%0,%1,%2,%3};\n"
        : "+f"(d[0]), "+f"(d[1]), "+f"(d[2]), "+f"(d[3])
        : "r"(__float_as_uint(a[0])), "r"(__float_as_uint(a[1])),
          "r"(__float_as_uint(a[2])), "r"(__float_as_uint(a[3])),
          "r"(__float_as_uint(b[0])), "r"(__float_as_uint(b[1])));
}

// ---------------- LayerNorm ----------------
__global__ void ln_kernel(const float* __restrict__ x, const float* __restrict__ g,
                          const float* __restrict__ b, float* __restrict__ out)
{
    int row  = blockIdx.x * 8 + (threadIdx.x >> 5);
    int lane = threadIdx.x & 31;
    const float* xr = x + (size_t)row * CCH;
    float v0 = xr[lane], v1 = xr[lane + 32], v2 = xr[lane + 64];
    float s = v0 + v1 + v2;
    #pragma unroll
    for (int o = 16; o; o >>= 1) s += __shfl_xor_sync(0xffffffffu, s, o);
    float mu = s * (1.0f / 96.0f);
    float d0 = v0 - mu, d1 = v1 - mu, d2 = v2 - mu;
    float q = d0 * d0 + d1 * d1 + d2 * d2;
    #pragma unroll
    for (int o = 16; o; o >>= 1) q += __shfl_xor_sync(0xffffffffu, q, o);
    float inv = rsqrtf(q * (1.0f / 96.0f) + 1e-5f);
    float* orow = out + (size_t)row * CCH;
    orow[lane]      = d0 * inv * g[lane]      + b[lane];
    orow[lane + 32] = d1 * inv * g[lane + 32] + b[lane + 32];
    orow[lane + 64] = d2 * inv * g[lane + 64] + b[lane + 64];
}

// ---------------- weight reorders ----------------
__global__ void reorder_w1(const float* __restrict__ w, float* __restrict__ wr)
{
    int tid = blockIdx.x * 256 + threadIdx.x;
    if (tid >= CMP * CCH * 27) return;
    int o = tid / (CCH * 27);
    int rem = tid - o * (CCH * 27);
    int c = rem / 27;
    int tap = rem - c * 27;
    wr[(tap * CMP + o) * CCH + c] = w[tid];
}
__global__ void reorder_w2(const float* __restrict__ w, float* __restrict__ wr)
{
    int tid = blockIdx.x * 256 + threadIdx.x;
    if (tid >= CCH * CMP * 27) return;
    int o = tid / (CMP * 27);
    int rem = tid - o * (CMP * 27);
    int i = rem / 27;
    int tap = rem - i * 27;
    wr[(tap * CCH + o) * CMP + i] = w[tid];
}

// ---------------- conv1 (96->32, 3x3x3, GELU) via tf32 mma ----------------
// block = one (d,h) row: M=64 voxels, N=32 oc. 256 thr, 8 warps.
// warp: wm=warp>>1 -> m16 tile (4 of them), wn=warp&1 -> 16 cols (2 n8 tiles)
__global__ __launch_bounds__(256) void conv1_kernel(
    const float* __restrict__ xn, const float* __restrict__ w1r,
    const float* __restrict__ b1, float* __restrict__ y1)
{
    extern __shared__ float sm[];
    float* in_s = sm;           // 66 * 100
    float* w_s  = sm + 6600;    // 3 * 32 * 100
    int d = blockIdx.x >> 6, h = blockIdx.x & 63;
    int tx = threadIdx.x;
    int warp = tx >> 5, lane = tx & 31;
    int wm = warp >> 1, wn = warp & 1;
    int qrow = lane >> 2, qcol = lane & 3;
    float acc[2][4] = {};
    for (int kd = 0; kd < 3; kd++) {
        int dd = d + kd - 1;
        for (int kh = 0; kh < 3; kh++) {
            int hh = h + kh - 1;
            bool rv = ((unsigned)dd < (unsigned)DD) && ((unsigned)hh < (unsigned)HH);
            __syncthreads();
            const float* src_row = xn + ((size_t)(dd * HH + hh) * WW) * CCH;
            for (int idx = tx * 4; idx < 66 * 96; idx += 1024) {
                int r = idx / 96, c = idx - r * 96;
                int wv = r - 1;
                float4 val = make_float4(0.f, 0.f, 0.f, 0.f);
                if (rv && (unsigned)wv < 64u) val = *(const float4*)(src_row + wv * CCH + c);
                *(float4*)(in_s + r * 100 + c) = val;
            }
            const float* wsrc = w1r + (kd * 3 + kh) * 3 * (CMP * CCH);
            for (int idx = tx * 4; idx < 3 * CMP * CCH; idx += 1024) {
                int kw = idx / (CMP * CCH), r2 = idx - kw * (CMP * CCH);
                int o = r2 / CCH, c = r2 - o * CCH;
                *(float4*)(w_s + (kw * 32 + o) * 100 + c) = *(const float4*)(wsrc + idx);
            }
            __syncthreads();
            #pragma unroll
            for (int kw = 0; kw < 3; kw++) {
                #pragma unroll
                for (int ks = 0; ks < 12; ks++) {
                    int kk = ks * 8;
                    float a[4], b[2][2];
                    const float* ap = in_s + (wm * 16 + qrow + kw) * 100 + kk + qcol;
                    a[0] = ap[0]; a[1] = ap[800]; a[2] = ap[4]; a[3] = ap[804];
                    #pragma unroll
                    for (int nt = 0; nt < 2; nt++) {
                        const float* bp = w_s + (kw * 32 + wn * 16 + nt * 8 + qrow) * 100 + kk + qcol;
                        b[nt][0] = bp[0]; b[nt][1] = bp[4];
                    }
                    #pragma unroll
                    for (int nt = 0; nt < 2; nt++) mma8(acc[nt], a, b[nt]);
                }
            }
        }
    }
    float* orow = y1 + (size_t)(d * HH + h) * WW * CMP;
    #pragma unroll
    for (int nt = 0; nt < 2; nt++) {
        int oc = wn * 16 + nt * 8 + qcol * 2;
        float bb0 = b1[oc], bb1 = b1[oc + 1];
        #pragma unroll
        for (int half = 0; half < 2; half++) {
            int v = wm * 16 + qrow + half * 8;
            float2 o2;
            o2.x = gelu_exact(acc[nt][half * 2 + 0] + bb0);
            o2.y = gelu_exact(acc[nt][half * 2 + 1] + bb1);
            *(float2*)(orow + v * CMP + oc) = o2;
        }
    }
}

// ---------------- conv2 (32->96, 3x3x3) via tf32 mma ----------------
// block = one (d,h) row: M=64, N=96. 256 thr: wm=warp>>1 (m16), wn=warp&1 (48 cols = 6 n8)
__global__ __launch_bounds__(256) void conv2_kernel(
    const float* __restrict__ y1, const float* __restrict__ w2r,
    const float* __restrict__ b2, float* __restrict__ y2)
{
    extern __shared__ float sm[];
    float* in_s = sm;           // 66 * 36
    float* w_s  = sm + 2376;    // 3 * 96 * 36
    int d = blockIdx.x >> 6, h = blockIdx.x & 63;
    int tx = threadIdx.x;
    int warp = tx >> 5, lane = tx & 31;
    int wm = warp >> 1, wn = warp & 1;
    int qrow = lane >> 2, qcol = lane & 3;
    float acc[6][4] = {};
    for (int kd = 0; kd < 3; kd++) {
        int dd = d + kd - 1;
        for (int kh = 0; kh < 3; kh++) {
            int hh = h + kh - 1;
            bool rv = ((unsigned)dd < (unsigned)DD) && ((unsigned)hh < (unsigned)HH);
            __syncthreads();
            const float* src_row = y1 + ((size_t)(dd * HH + hh) * WW) * CMP;
            for (int idx = tx * 4; idx < 66 * 32; idx += 1024) {
                int r = idx >> 5, c = idx & 31;
                int wv = r - 1;
                float4 val = make_float4(0.f, 0.f, 0.f, 0.f);
                if (rv && (unsigned)wv < 64u) val = *(const float4*)(src_row + wv * CMP + c);
                *(float4*)(in_s + r * 36 + c) = val;
            }
            const float* wsrc = w2r + (kd * 3 + kh) * 3 * (CCH * CMP);
            for (int idx = tx * 4; idx < 3 * CCH * CMP; idx += 1024) {
                int kw = idx / (CCH * CMP), r2 = idx - kw * (CCH * CMP);
                int o = r2 >> 5, c = r2 & 31;
                *(float4*)(w_s + (kw * 96 + o) * 36 + c) = *(const float4*)(wsrc + idx);
            }
            __syncthreads();
            #pragma unroll
            for (int kw = 0; kw < 3; kw++) {
                #pragma unroll
                for (int ks = 0; ks < 4; ks++) {
                    int kk = ks * 8;
                    float a[4];
                    const float* ap = in_s + (wm * 16 + qrow + kw) * 36 + kk + qcol;
                    a[0] = ap[0]; a[1] = ap[288]; a[2] = ap[4]; a[3] = ap[292];
                    #pragma unroll
                    for (int nt = 0; nt < 6; nt++) {
                        const float* bp = w_s + (kw * 96 + wn * 48 + nt * 8 + qrow) * 36 + kk + qcol;
                        float b[2] = { bp[0], bp[4] };
                        mma8(acc[nt], a, b);
                    }
                }
            }
        }
    }
    float* orow = y2 + (size_t)(d * HH + h) * WW * CCH;
    #pragma unroll
    for (int nt = 0; nt < 6; nt++) {
        int oc = wn * 48 + nt * 8 + qcol * 2;
        float bb0 = b2[oc], bb1 = b2[oc + 1];
        #pragma unroll
        for (int half = 0; half < 2; half++) {
            int v = wm * 16 + qrow + half * 8;
            float2 o2;
            o2.x = acc[nt][half * 2 + 0] + bb0;
            o2.y = acc[nt][half * 2 + 1] + bb1;
            *(float2*)(orow + v * CCH + oc) = o2;
        }
    }
}

// ---------------- pooling + channel attention ----------------
__global__ void pool_kernel(const float* __restrict__ y2, float* __restrict__ part)
{
    int c = threadIdx.x;
    const float* base = y2 + (size_t)blockIdx.x * 128 * CCH;
    float s = 0.f;
    for (int v = 0; v < 128; v++) s += base[v * CCH + c];
    part[blockIdx.x * CCH + c] = s;
}

__global__ void ca_kernel(const float* __restrict__ part,
                          const float* __restrict__ ca1w, const float* __restrict__ ca1b,
                          const float* __restrict__ ca2w, const float* __restrict__ ca2b,
                          float* __restrict__ att)
{
    __shared__ float p[CCH], hs[3];
    int tx = threadIdx.x;
    float s = 0.f;
    for (int b = 0; b < 256; b++) s += part[b * CCH + tx];
    p[tx] = s * (1.0f / (float)LTOK);
    __syncthreads();
    if (tx < 3) {
        float a = ca1b[tx];
        for (int c = 0; c < CCH; c++) a += ca1w[tx * CCH + c] * p[c];
        hs[tx] = fmaxf(a, 0.f);
    }
    __syncthreads();
    float a = ca2b[tx];
    #pragma unroll
    for (int k = 0; k < 3; k++) a += ca2w[tx * 3 + k] * hs[k];
    att[tx] = 1.0f / (1.0f + expf(-a));
}

// ---------------- bias expansion ----------------
__global__ void expand_bias(const int* __restrict__ rpi, const float* __restrict__ rpbt,
                            float* __restrict__ bias)
{
    int tid = blockIdx.x * 256 + threadIdx.x;
    int h = tid >> 18;
    int r = tid & 262143;
    bias[tid] = rpbt[rpi[r] * HEADS + h];
}

// ---------------- GEMM via tf32 mma: C[M][N] = A[M][K] @ W[N][K]^T + bias ----------------
// block tile 128M x 64N; 256 thr, 8 warps: wm=warp>>1 (m32 = 2 m16), wn=warp&1 (n32 = 4 n8)
// EPI: 0 none, 1 GELU, 2 res1 + v + res2*att[n]*0.01, 3 res1 + v
template <int EPI>
__global__ __launch_bounds__(256) void gemm_tf32(
    const float* __restrict__ A, const float* __restrict__ Wm,
    const float* __restrict__ bias, float* __restrict__ C,
    int M, int Nn, int K,
    const float* __restrict__ res1, const float* __restrict__ res2,
    const float* __restrict__ att)
{
    extern __shared__ float sm[];
    float* a_s = sm;            // 128 * 100
    float* w_s = sm + 12800;    // 64 * 100
    int m0 = blockIdx.x * 128, n0 = blockIdx.y * 64;
    int tx = threadIdx.x;
    int warp = tx >> 5, lane = tx & 31;
    int wm = warp >> 1, wn = warp & 1;
    int qrow = lane >> 2, qcol = lane & 3;
    float acc[2][4][4] = {};
    for (int k0 = 0; k0 < K; k0 += 96) {
        __syncthreads();
        for (int idx = tx * 4; idx < 128 * 96; idx += 1024) {
            int r = idx / 96, c = idx - r * 96;
            *(float4*)(a_s + r * 100 + c) = *(const float4*)(A + (size_t)(m0 + r) * K + k0 + c);
        }
        for (int idx = tx * 4; idx < 64 * 96; idx += 1024) {
            int r = idx / 96, c = idx - r * 96;
            float4 v = make_float4(0.f, 0.f, 0.f, 0.f);
            if (n0 + r < Nn) v = *(const float4*)(Wm + (size_t)(n0 + r) * K + k0 + c);
            *(float4*)(w_s + r * 100 + c) = v;
        }
        __syncthreads();
        #pragma unroll
        for (int ks = 0; ks < 12; ks++) {
            int kk = ks * 8;
            float a[2][4], b[4][2];
            #pragma unroll
            for (int mt = 0; mt < 2; mt++) {
                const float* ap = a_s + (wm * 32 + mt * 16 + qrow) * 100 + kk + qcol;
                a[mt][0] = ap[0]; a[mt][1] = ap[800]; a[mt][2] = ap[4]; a[mt][3] = ap[804];
            }
            #pragma unroll
            for (int nt = 0; nt < 4; nt++) {
                const float* bp = w_s + (wn * 32 + nt * 8 + qrow) * 100 + kk + qcol;
                b[nt][0] = bp[0]; b[nt][1] = bp[4];
            }
            #pragma unroll
            for (int mt = 0; mt < 2; mt++)
                #pragma unroll
                for (int nt = 0; nt < 4; nt++) mma8(acc[mt][nt], a[mt], b[nt]);
        }
    }
    #pragma unroll
    for (int mt = 0; mt < 2; mt++) {
        #pragma unroll
        for (int nt = 0; nt < 4; nt++) {
            int cc = n0 + wn * 32 + nt * 8 + qcol * 2;
            if (cc >= Nn) continue;
            float bb0 = bias[cc], bb1 = bias[cc + 1];
            float av0 = (EPI == 2) ? att[cc] * 0.01f : 0.f;
            float av1 = (EPI == 2) ? att[cc + 1] * 0.01f : 0.f;
            #pragma unroll
            for (int half = 0; half < 2; half++) {
                int r = m0 + wm * 32 + mt * 16 + qrow + half * 8;
                size_t idx = (size_t)r * Nn + cc;
                float v0 = acc[mt][nt][half * 2 + 0] + bb0;
                float v1 = acc[mt][nt][half * 2 + 1] + bb1;
                if (EPI == 1) { v0 = gelu_exact(v0); v1 = gelu_exact(v1); }
                else if (EPI == 2) {
                    float2 r1 = *(const float2*)(res1 + idx);
                    float2 r2 = *(const float2*)(res2 + idx);
                    v0 = r1.x + v0 + r2.x * av0;
                    v1 = r1.y + v1 + r2.y * av1;
                } else if (EPI == 3) {
                    float2 r1 = *(const float2*)(res1 + idx);
                    v0 = r1.x + v0;
                    v1 = r1.y + v1;
                }
                float2 o2; o2.x = v0; o2.y = v1;
                *(float2*)(C + idx) = o2;
            }
        }
    }
}

// ---------------- window attention via tf32 mma ----------------
// block = (window, head, 64-query chunk); 256 thr, 8 warps
__global__ __launch_bounds__(256) void attn_kernel(
    const float* __restrict__ qkv, const float* __restrict__ bias_g,
    float* __restrict__ o)
{
    extern __shared__ float sm[];
    float* q_s = sm;            // 64 * 20
    float* k_s = sm + 1280;     // 512 * 20
    float* v_s = sm + 11520;    // 512 * 20
    float* sc  = sm + 21760;    // 64 * 516
    int blk = blockIdx.x;
    int qc = blk & 7;
    int head = (blk >> 3) % 6;
    int win = blk / 48;
    int wh = win >> 3, ww = win & 7;
    int base = wh * 512 + ww * 8;
    int tx = threadIdx.x;
    int warp = tx >> 5, lane = tx & 31;
    int qrow = lane >> 2, qcol = lane & 3;

    for (int idx = tx; idx < 2048; idx += 256) {
        int j = idx >> 2, c4 = idx & 3;
        int t = ((j >> 6) << 12) + base + (((j >> 3) & 7) << 6) + (j & 7);
        const float* p = qkv + (size_t)t * 288 + head * HDIM + c4 * 4;
        *(float4*)(k_s + j * 20 + c4 * 4) = *(const float4*)(p + 96);
        *(float4*)(v_s + j * 20 + c4 * 4) = *(const float4*)(p + 192);
    }
    {
        int i = tx >> 2, c4 = tx & 3;
        int j = qc * 64 + i;
        int t = ((j >> 6) << 12) + base + (((j >> 3) & 7) << 6) + (j & 7);
        float4 v = *(const float4*)(qkv + (size_t)t * 288 + head * HDIM + c4 * 4);
        v.x *= 0.25f; v.y *= 0.25f; v.z *= 0.25f; v.w *= 0.25f;
        *(float4*)(q_s + i * 20 + c4 * 4) = v;
    }
    __syncthreads();

    // ---- scores = q @ k^T + bias  (tf32 mma, M=64, N=512, K=16) ----
    {
        int wm = warp >> 1, whf = warp & 1;            // wm: m16 tile, whf: n half
        const float* brow = bias_g + (size_t)head * (NTOK * NTOK) + (size_t)(qc * 64) * NTOK;
        int r0 = wm * 16 + qrow;
        #pragma unroll 4
        for (int jt = 0; jt < 32; jt++) {
            int j8 = whf * 256 + jt * 8;
            float accq[4] = {};
            #pragma unroll
            for (int ks = 0; ks < 2; ks++) {
                int kk = ks * 8;
                float a[4], b[2];
                const float* ap = q_s + r0 * 20 + kk + qcol;
                a[0] = ap[0]; a[1] = ap[160]; a[2] = ap[4]; a[3] = ap[164];
                const float* bp = k_s + (j8 + qrow) * 20 + kk + qcol;
                b[0] = bp[0]; b[1] = bp[4];
                mma8(accq, a, b);
            }
            int cc = j8 + qcol * 2;
            float2 b0 = *(const float2*)(brow + r0 * NTOK + cc);
            float2 b1 = *(const float2*)(brow + (r0 + 8) * NTOK + cc);
            float2 s0; s0.x = accq[0] + b0.x; s0.y = accq[1] + b0.y;
            float2 s1; s1.x = accq[2] + b1.x; s1.y = accq[3] + b1.y;
            *(float2*)(sc + r0 * 516 + cc) = s0;
            *(float2*)(sc + (r0 + 8) * 516 + cc) = s1;
        }
    }
    __syncthreads();

    // ---- softmax (fp32), each warp 8 rows ----
    {
        int w = warp, ln = lane;
        for (int r = 0; r < 8; r++) {
            float* srow = sc + (w * 8 + r) * 516;
            float m = -1e30f;
            #pragma unroll
            for (int jj = 0; jj < 16; jj++) m = fmaxf(m, srow[ln + jj * 32]);
            #pragma unroll
            for (int off = 16; off; off >>= 1) m = fmaxf(m, __shfl_xor_sync(0xffffffffu, m, off));
            float ssum = 0.f;
            #pragma unroll
            for (int jj = 0; jj < 16; jj++) {
                float e = __expf(srow[ln + jj * 32] - m);
                srow[ln + jj * 32] = e;
                ssum += e;
            }
            #pragma unroll
            for (int off = 16; off; off >>= 1) ssum += __shfl_xor_sync(0xffffffffu, ssum, off);
            float inv = 1.0f / ssum;
            #pragma unroll
            for (int jj = 0; jj < 16; jj++) srow[ln + jj * 32] *= inv;
        }
    }
    __syncthreads();

    // ---- o = P @ V (tf32 mma, M=64, N=16, K=512) ----
    {
        int wm = warp >> 1, wn = warp & 1;
        int r0 = wm * 16 + qrow;
        float accp[4] = {};
        #pragma unroll 8
        for (int ks = 0; ks < 64; ks++) {
            int kk = ks * 8;
            float a[4], b[2];
            const float* ap = sc + r0 * 516 + kk + qcol;
            a[0] = ap[0]; a[1] = ap[4128]; a[2] = ap[4]; a[3] = ap[4132];
            const float* bp = v_s + (kk + qcol) * 20 + wn * 8 + qrow;
            b[0] = bp[0]; b[1] = bp[80];
            mma8(accp, a, b);
        }
        int col = wn * 8 + qcol * 2;
        #pragma unroll
        for (int half = 0; half < 2; half++) {
            int i = r0 + half * 8;
            int jg = qc * 64 + i;
            int t = ((jg >> 6) << 12) + base + (((jg >> 3) & 7) << 6) + (jg & 7);
            float2 o2; o2.x = accp[half * 2 + 0]; o2.y = accp[half * 2 + 1];
            *(float2*)(o + (size_t)t * CCH + head * HDIM + col) = o2;
        }
    }
}

// ---------------- launch ----------------
extern "C" void kernel_launch(void* const* d_in, const int* in_sizes, int n_in,
                              void* d_out, int out_size)
{
    (void)in_sizes; (void)n_in; (void)out_size;
    const float* x       = (const float*)d_in[0];
    const float* n1g     = (const float*)d_in[1];
    const float* n1b     = (const float*)d_in[2];
    const float* qkv_w   = (const float*)d_in[3];
    const float* qkv_b   = (const float*)d_in[4];
    const float* rpbt    = (const float*)d_in[5];
    const float* proj_w  = (const float*)d_in[6];
    const float* proj_b  = (const float*)d_in[7];
    const float* conv1_w = (const float*)d_in[8];
    const float* conv1_b = (const float*)d_in[9];
    const float* conv2_w = (const float*)d_in[10];
    const float* conv2_b = (const float*)d_in[11];
    const float* ca1_w   = (const float*)d_in[12];
    const float* ca1_b   = (const float*)d_in[13];
    const float* ca2_w   = (const float*)d_in[14];
    const float* ca2_b   = (const float*)d_in[15];
    const float* n2g     = (const float*)d_in[16];
    const float* n2b     = (const float*)d_in[17];
    const float* fc1_w   = (const float*)d_in[18];
    const float* fc1_b   = (const float*)d_in[19];
    const float* fc2_w   = (const float*)d_in[20];
    const float* fc2_b   = (const float*)d_in[21];
    const int*   rpi     = (const int*)d_in[22];
    float* out = (float*)d_out;

    float *xn, *y1, *y2, *part, *att, *qkvb, *biasb, *ob, *x1, *xn2, *hb, *w1r, *w2r;
    cudaGetSymbolAddress((void**)&xn,    g_xn);
    cudaGetSymbolAddress((void**)&y1,    g_y1);
    cudaGetSymbolAddress((void**)&y2,    g_y2);
    cudaGetSymbolAddress((void**)&part,  g_part);
    cudaGetSymbolAddress((void**)&att,   g_att);
    cudaGetSymbolAddress((void**)&qkvb,  g_qkv);
    cudaGetSymbolAddress((void**)&biasb, g_bias);
    cudaGetSymbolAddress((void**)&ob,    g_o);
    cudaGetSymbolAddress((void**)&x1,    g_x1);
    cudaGetSymbolAddress((void**)&xn2,   g_xn2);
    cudaGetSymbolAddress((void**)&hb,    g_h);
    cudaGetSymbolAddress((void**)&w1r,   g_w1r);
    cudaGetSymbolAddress((void**)&w2r,   g_w2r);

    const int SMEM_CONV1 = (6600 + 9600) * 4;
    const int SMEM_CONV2 = (2376 + 10368) * 4;
    const int SMEM_GEMM  = (12800 + 6400) * 4;          // 76800
    const int SMEM_ATTN  = (21760 + 64 * 516) * 4;      // 219136
    cudaFuncSetAttribute(conv1_kernel, cudaFuncAttributeMaxDynamicSharedMemorySize, SMEM_CONV1);
    cudaFuncSetAttribute(conv2_kernel, cudaFuncAttributeMaxDynamicSharedMemorySize, SMEM_CONV2);
    cudaFuncSetAttribute(gemm_tf32<0>, cudaFuncAttributeMaxDynamicSharedMemorySize, SMEM_GEMM);
    cudaFuncSetAttribute(gemm_tf32<1>, cudaFuncAttributeMaxDynamicSharedMemorySize, SMEM_GEMM);
    cudaFuncSetAttribute(gemm_tf32<2>, cudaFuncAttributeMaxDynamicSharedMemorySize, SMEM_GEMM);
    cudaFuncSetAttribute(gemm_tf32<3>, cudaFuncAttributeMaxDynamicSharedMemorySize, SMEM_GEMM);
    cudaFuncSetAttribute(attn_kernel, cudaFuncAttributeMaxDynamicSharedMemorySize, SMEM_ATTN);

    reorder_w1<<<(CMP * CCH * 27 + 255) / 256, 256>>>(conv1_w, w1r);
    reorder_w2<<<(CCH * CMP * 27 + 255) / 256, 256>>>(conv2_w, w2r);

    ln_kernel<<<LTOK / 8, 256>>>(x, n1g, n1b, xn);

    conv1_kernel<<<DD * HH, 256, SMEM_CONV1>>>(xn, w1r, conv1_b, y1);
    conv2_kernel<<<DD * HH, 256, SMEM_CONV2>>>(y1, w2r, conv2_b, y2);
    pool_kernel<<<256, CCH>>>(y2, part);
    ca_kernel<<<1, CCH>>>(part, ca1_w, ca1_b, ca2_w, ca2_b, att);

    expand_bias<<<HEADS * NTOK * NTOK / 256, 256>>>(rpi, rpbt, biasb);
    gemm_tf32<0><<<dim3(LTOK / 128, 5), 256, SMEM_GEMM>>>(
        xn, qkv_w, qkv_b, qkvb, LTOK, 288, 96, nullptr, nullptr, nullptr);
    attn_kernel<<<NWIN * HEADS * 8, 256, SMEM_ATTN>>>(qkvb, biasb, ob);

    gemm_tf32<2><<<dim3(LTOK / 128, 2), 256, SMEM_GEMM>>>(
        ob, proj_w, proj_b, x1, LTOK, 96, 96, x, y2, att);

    ln_kernel<<<LTOK / 8, 256>>>(x1, n2g, n2b, xn2);
    gemm_tf32<1><<<dim3(LTOK / 128, 6), 256, SMEM_GEMM>>>(
        xn2, fc1_w, fc1_b, hb, LTOK, HID, 96, nullptr, nullptr, nullptr);
    gemm_tf32<3><<<dim3(LTOK / 128, 2), 256, SMEM_GEMM>>>(
        hb, fc2_w, fc2_b, out, LTOK, 96, HID, x1, nullptr, nullptr);
}

// round 3
// speedup vs baseline: 4.2854x; 2.0888x over previous
#include <cuda_runtime.h>
#include <cuda_bf16.h>
#include <math.h>
#include <stdint.h>

#define DD 8
#define HH 64
#define WW 64
#define LTOK 32768
#define CCH 96
#define CMP 32
#define HID 384
#define HEADS 6
#define HDIM 16
#define NWIN 64
#define NTOK 512

// ---------------- scratch ----------------
__device__ __nv_bfloat16 g_xn  [LTOK * CCH];
__device__ __nv_bfloat16 g_y1  [LTOK * CMP];
__device__ float         g_y2  [LTOK * CCH];
__device__ float         g_part[256 * CCH];
__device__ float         g_att [CCH];
__device__ __nv_bfloat16 g_qkv [LTOK * 3 * CCH];
__device__ __nv_bfloat16 g_bias[HEADS * NTOK * NTOK];
__device__ __nv_bfloat16 g_o   [LTOK * CCH];
__device__ float         g_x1  [LTOK * CCH];
__device__ __nv_bfloat16 g_xn2 [LTOK * CCH];
__device__ __nv_bfloat16 g_h   [LTOK * HID];
__device__ __nv_bfloat16 g_w1r [27 * CMP * CCH];
__device__ __nv_bfloat16 g_w2r [27 * CCH * CMP];
__device__ __nv_bfloat16 g_qw  [288 * 96];
__device__ __nv_bfloat16 g_pw  [96 * 96];
__device__ __nv_bfloat16 g_f1w [384 * 96];
__device__ __nv_bfloat16 g_f2w [96 * 384];

__device__ __forceinline__ float gelu_exact(float v) {
    return 0.5f * v * (1.0f + erff(v * 0.70710678118654752f));
}
__device__ __forceinline__ unsigned pack2(float a, float b) {
    __nv_bfloat162 t = __floats2bfloat162_rn(a, b);
    return *reinterpret_cast<unsigned*>(&t);
}
__device__ __forceinline__ void ldsm4(unsigned* r, unsigned addr) {
    asm volatile("ldmatrix.sync.aligned.m8n8.x4.shared.b16 {%0,%1,%2,%3},[%4];"
                 : "=r"(r[0]), "=r"(r[1]), "=r"(r[2]), "=r"(r[3]) : "r"(addr));
}
__device__ __forceinline__ void mma16(float* d, const unsigned* a, const unsigned* b) {
    asm volatile(
        "mma.sync.aligned.m16n8k16.row.col.f32.bf16.bf16.f32 "
        "{%0,%1,%2,%3},{%4,%5,%6,%7},{%8,%9},{%0,%1,%2,%3};"
        : "+f"(d[0]), "+f"(d[1]), "+f"(d[2]), "+f"(d[3])
        : "r"(a[0]), "r"(a[1]), "r"(a[2]), "r"(a[3]), "r"(b[0]), "r"(b[1]));
}

// ---------------- LayerNorm (fp32 in -> bf16 out) ----------------
__global__ void ln_kernel(const float* __restrict__ x, const float* __restrict__ g,
                          const float* __restrict__ b, __nv_bfloat16* __restrict__ out)
{
    int row  = blockIdx.x * 8 + (threadIdx.x >> 5);
    int lane = threadIdx.x & 31;
    const float* xr = x + (size_t)row * CCH;
    float v0 = xr[lane], v1 = xr[lane + 32], v2 = xr[lane + 64];
    float s = v0 + v1 + v2;
    #pragma unroll
    for (int o = 16; o; o >>= 1) s += __shfl_xor_sync(0xffffffffu, s, o);
    float mu = s * (1.0f / 96.0f);
    float d0 = v0 - mu, d1 = v1 - mu, d2 = v2 - mu;
    float q = d0 * d0 + d1 * d1 + d2 * d2;
    #pragma unroll
    for (int o = 16; o; o >>= 1) q += __shfl_xor_sync(0xffffffffu, q, o);
    float inv = rsqrtf(q * (1.0f / 96.0f) + 1e-5f);
    __nv_bfloat16* orow = out + (size_t)row * CCH;
    orow[lane]      = __float2bfloat16(d0 * inv * g[lane]      + b[lane]);
    orow[lane + 32] = __float2bfloat16(d1 * inv * g[lane + 32] + b[lane + 32]);
    orow[lane + 64] = __float2bfloat16(d2 * inv * g[lane + 64] + b[lane + 64]);
}

// ---------------- conversions / reorders ----------------
__global__ void cvt_bf16(const float* __restrict__ s, __nv_bfloat16* __restrict__ d, int n)
{
    int i = blockIdx.x * 256 + threadIdx.x;
    if (i < n) d[i] = __float2bfloat16(s[i]);
}
__global__ void reorder_w1(const float* __restrict__ w, __nv_bfloat16* __restrict__ wr)
{
    int tid = blockIdx.x * 256 + threadIdx.x;
    if (tid >= CMP * CCH * 27) return;
    int o = tid / (CCH * 27);
    int rem = tid - o * (CCH * 27);
    int c = rem / 27;
    int tap = rem - c * 27;
    wr[(tap * CMP + o) * CCH + c] = __float2bfloat16(w[tid]);
}
__global__ void reorder_w2(const float* __restrict__ w, __nv_bfloat16* __restrict__ wr)
{
    int tid = blockIdx.x * 256 + threadIdx.x;
    if (tid >= CCH * CMP * 27) return;
    int o = tid / (CMP * 27);
    int rem = tid - o * (CMP * 27);
    int i = rem / 27;
    int tap = rem - i * 27;
    wr[(tap * CCH + o) * CMP + i] = __float2bfloat16(w[tid]);
}
__global__ void expand_bias(const int* __restrict__ rpi, const float* __restrict__ rpbt,
                            __nv_bfloat16* __restrict__ bias)
{
    int tid = blockIdx.x * 256 + threadIdx.x;
    int h = tid >> 18;
    int r = tid & 262143;
    bias[tid] = __float2bfloat16(rpbt[rpi[r] * HEADS + h]);
}

// ---------------- conv1: 96->32 + GELU (bf16 mma) ----------------
// block = (d,h) row; M=64 voxels, N=32. 8 warps: wm=warp>>1 (m16), wn=warp&1 (2 n8)
__global__ __launch_bounds__(256) void conv1_kernel(
    const __nv_bfloat16* __restrict__ xn, const __nv_bfloat16* __restrict__ w1r,
    const float* __restrict__ b1, __nv_bfloat16* __restrict__ y1)
{
    extern __shared__ __nv_bfloat16 smb[];
    __nv_bfloat16* in_s = smb;              // 66 x 104
    __nv_bfloat16* w_s  = smb + 66 * 104;   // 96 x 104
    unsigned in_u = (unsigned)__cvta_generic_to_shared(in_s);
    int d = blockIdx.x >> 6, h = blockIdx.x & 63;
    int tx = threadIdx.x;
    int warp = tx >> 5, lane = tx & 31;
    int wm = warp >> 1, wn = warp & 1;
    int gid = lane >> 2, tig = lane & 3;
    float acc[2][4] = {};
    for (int kd = 0; kd < 3; kd++) {
        int dd = d + kd - 1;
        for (int kh = 0; kh < 3; kh++) {
            int hh = h + kh - 1;
            bool rv = ((unsigned)dd < (unsigned)DD) && ((unsigned)hh < (unsigned)HH);
            __syncthreads();
            const __nv_bfloat16* src_row = xn + ((size_t)(dd * HH + hh) * WW) * CCH;
            for (int idx = tx; idx < 792; idx += 256) {
                int r = idx / 12, c = idx - r * 12;
                int wv = r - 1;
                uint4 val = make_uint4(0u, 0u, 0u, 0u);
                if (rv && (unsigned)wv < 64u) val = *(const uint4*)(src_row + wv * CCH + c * 8);
                *(uint4*)(in_s + r * 104 + c * 8) = val;
            }
            const __nv_bfloat16* wsrc = w1r + (kd * 3 + kh) * 3 * (CMP * CCH);
            for (int idx = tx; idx < 1152; idx += 256) {
                int r = idx / 12, c = idx - r * 12;
                *(uint4*)(w_s + r * 104 + c * 8) = *(const uint4*)(wsrc + idx * 8);
            }
            __syncthreads();
            #pragma unroll
            for (int kw = 0; kw < 3; kw++) {
                #pragma unroll
                for (int ks = 0; ks < 6; ks++) {
                    unsigned af[4];
                    ldsm4(af, in_u + 2u * ((wm * 16 + (lane & 15) + kw) * 104 + ks * 16 + ((lane >> 4) << 3)));
                    #pragma unroll
                    for (int nt = 0; nt < 2; nt++) {
                        const __nv_bfloat16* bp = w_s + (kw * 32 + wn * 16 + nt * 8 + gid) * 104 + ks * 16 + tig * 2;
                        unsigned bf[2];
                        bf[0] = *(const unsigned*)bp;
                        bf[1] = *(const unsigned*)(bp + 8);
                        mma16(acc[nt], af, bf);
                    }
                }
            }
        }
    }
    __nv_bfloat16* orow = y1 + (size_t)(d * HH + h) * WW * CMP;
    #pragma unroll
    for (int nt = 0; nt < 2; nt++) {
        int oc = wn * 16 + nt * 8 + tig * 2;
        float bb0 = b1[oc], bb1 = b1[oc + 1];
        #pragma unroll
        for (int half = 0; half < 2; half++) {
            int v = wm * 16 + gid + half * 8;
            *(unsigned*)(orow + v * CMP + oc) =
                pack2(gelu_exact(acc[nt][half * 2 + 0] + bb0),
                      gelu_exact(acc[nt][half * 2 + 1] + bb1));
        }
    }
}

// ---------------- conv2: 32->96 (bf16 mma, fp32 out) ----------------
__global__ __launch_bounds__(256) void conv2_kernel(
    const __nv_bfloat16* __restrict__ y1, const __nv_bfloat16* __restrict__ w2r,
    const float* __restrict__ b2, float* __restrict__ y2)
{
    extern __shared__ __nv_bfloat16 smb[];
    __nv_bfloat16* in_s = smb;              // 66 x 40
    __nv_bfloat16* w_s  = smb + 66 * 40;    // 288 x 40
    unsigned in_u = (unsigned)__cvta_generic_to_shared(in_s);
    int d = blockIdx.x >> 6, h = blockIdx.x & 63;
    int tx = threadIdx.x;
    int warp = tx >> 5, lane = tx & 31;
    int wm = warp >> 1, wn = warp & 1;
    int gid = lane >> 2, tig = lane & 3;
    float acc[6][4] = {};
    for (int kd = 0; kd < 3; kd++) {
        int dd = d + kd - 1;
        for (int kh = 0; kh < 3; kh++) {
            int hh = h + kh - 1;
            bool rv = ((unsigned)dd < (unsigned)DD) && ((unsigned)hh < (unsigned)HH);
            __syncthreads();
            const __nv_bfloat16* src_row = y1 + ((size_t)(dd * HH + hh) * WW) * CMP;
            for (int idx = tx; idx < 264; idx += 256) {
                int r = idx >> 2, c = idx & 3;
                int wv = r - 1;
                uint4 val = make_uint4(0u, 0u, 0u, 0u);
                if (rv && (unsigned)wv < 64u) val = *(const uint4*)(src_row + wv * CMP + c * 8);
                *(uint4*)(in_s + r * 40 + c * 8) = val;
            }
            const __nv_bfloat16* wsrc = w2r + (kd * 3 + kh) * 3 * (CCH * CMP);
            for (int idx = tx; idx < 1152; idx += 256) {
                int r = idx >> 2, c = idx & 3;
                *(uint4*)(w_s + r * 40 + c * 8) = *(const uint4*)(wsrc + idx * 8);
            }
            __syncthreads();
            #pragma unroll
            for (int kw = 0; kw < 3; kw++) {
                #pragma unroll
                for (int ks = 0; ks < 2; ks++) {
                    unsigned af[4];
                    ldsm4(af, in_u + 2u * ((wm * 16 + (lane & 15) + kw) * 40 + ks * 16 + ((lane >> 4) << 3)));
                    #pragma unroll
                    for (int nt = 0; nt < 6; nt++) {
                        const __nv_bfloat16* bp = w_s + (kw * 96 + wn * 48 + nt * 8 + gid) * 40 + ks * 16 + tig * 2;
                        unsigned bf[2];
                        bf[0] = *(const unsigned*)bp;
                        bf[1] = *(const unsigned*)(bp + 8);
                        mma16(acc[nt], af, bf);
                    }
                }
            }
        }
    }
    float* orow = y2 + (size_t)(d * HH + h) * WW * CCH;
    #pragma unroll
    for (int nt = 0; nt < 6; nt++) {
        int oc = wn * 48 + nt * 8 + tig * 2;
        float bb0 = b2[oc], bb1 = b2[oc + 1];
        #pragma unroll
        for (int half = 0; half < 2; half++) {
            int v = wm * 16 + gid + half * 8;
            float2 o2;
            o2.x = acc[nt][half * 2 + 0] + bb0;
            o2.y = acc[nt][half * 2 + 1] + bb1;
            *(float2*)(orow + v * CCH + oc) = o2;
        }
    }
}

// ---------------- pooling + channel attention ----------------
__global__ void pool_kernel(const float* __restrict__ y2, float* __restrict__ part)
{
    int c = threadIdx.x;
    const float* base = y2 + (size_t)blockIdx.x * 128 * CCH;
    float s = 0.f;
    for (int v = 0; v < 128; v++) s += base[v * CCH + c];
    part[blockIdx.x * CCH + c] = s;
}
__global__ void ca_kernel(const float* __restrict__ part,
                          const float* __restrict__ ca1w, const float* __restrict__ ca1b,
                          const float* __restrict__ ca2w, const float* __restrict__ ca2b,
                          float* __restrict__ att)
{
    __shared__ float p[CCH], hs[3];
    int tx = threadIdx.x;
    float s = 0.f;
    for (int b = 0; b < 256; b++) s += part[b * CCH + tx];
    p[tx] = s * (1.0f / (float)LTOK);
    __syncthreads();
    if (tx < 3) {
        float a = ca1b[tx];
        for (int c = 0; c < CCH; c++) a += ca1w[tx * CCH + c] * p[c];
        hs[tx] = fmaxf(a, 0.f);
    }
    __syncthreads();
    float a = ca2b[tx];
    #pragma unroll
    for (int k = 0; k < 3; k++) a += ca2w[tx * 3 + k] * hs[k];
    att[tx] = 1.0f / (1.0f + expf(-a));
}

// ---------------- bf16 GEMM: C = A[M,K] @ W[N,K]^T + bias ----------------
// tile M=128, N=96; 8 warps: wm=warp>>1 (m32), wn=warp&1 (n48)
// EPI: 0 bf16-out, 1 gelu->bf16, 2 fp32 res1+v+res2*att*0.01, 3 fp32 res1+v
template <int EPI>
__global__ __launch_bounds__(256) void gemm_bf16(
    const __nv_bfloat16* __restrict__ A, const __nv_bfloat16* __restrict__ Wt,
    const float* __restrict__ bias, void* __restrict__ Cout, int Ktot, int Nn,
    const float* __restrict__ res1, const float* __restrict__ res2,
    const float* __restrict__ att)
{
    extern __shared__ __nv_bfloat16 smb[];
    __nv_bfloat16* a_s = smb;               // 128 x 104
    __nv_bfloat16* w_s = smb + 128 * 104;   // 96 x 104
    unsigned a_u = (unsigned)__cvta_generic_to_shared(a_s);
    int m0 = blockIdx.x * 128, n0 = blockIdx.y * 96;
    int tx = threadIdx.x;
    int warp = tx >> 5, lane = tx & 31;
    int wm = warp >> 1, wn = warp & 1;
    int gid = lane >> 2, tig = lane & 3;
    float acc[2][6][4] = {};
    int nchunk = Ktot / 96;
    for (int kc = 0; kc < nchunk; kc++) {
        int k0 = kc * 96;
        __syncthreads();
        for (int idx = tx; idx < 1536; idx += 256) {
            int r = idx / 12, c = idx - r * 12;
            *(uint4*)(a_s + r * 104 + c * 8) = *(const uint4*)(A + (size_t)(m0 + r) * Ktot + k0 + c * 8);
        }
        for (int idx = tx; idx < 1152; idx += 256) {
            int r = idx / 12, c = idx - r * 12;
            *(uint4*)(w_s + r * 104 + c * 8) = *(const uint4*)(Wt + (size_t)(n0 + r) * Ktot + k0 + c * 8);
        }
        __syncthreads();
        #pragma unroll
        for (int ks = 0; ks < 6; ks++) {
            unsigned af[2][4];
            #pragma unroll
            for (int mt = 0; mt < 2; mt++)
                ldsm4(af[mt], a_u + 2u * ((wm * 32 + mt * 16 + (lane & 15)) * 104 + ks * 16 + ((lane >> 4) << 3)));
            #pragma unroll
            for (int nt = 0; nt < 6; nt++) {
                const __nv_bfloat16* bp = w_s + (wn * 48 + nt * 8 + gid) * 104 + ks * 16 + tig * 2;
                unsigned bf[2];
                bf[0] = *(const unsigned*)bp;
                bf[1] = *(const unsigned*)(bp + 8);
                #pragma unroll
                for (int mt = 0; mt < 2; mt++) mma16(acc[mt][nt], af[mt], bf);
            }
        }
    }
    #pragma unroll
    for (int mt = 0; mt < 2; mt++) {
        #pragma unroll
        for (int nt = 0; nt < 6; nt++) {
            int cc = n0 + wn * 48 + nt * 8 + tig * 2;
            float bb0 = bias[cc], bb1 = bias[cc + 1];
            #pragma unroll
            for (int half = 0; half < 2; half++) {
                int r = m0 + wm * 32 + mt * 16 + gid + half * 8;
                size_t idx = (size_t)r * Nn + cc;
                float v0 = acc[mt][nt][half * 2 + 0] + bb0;
                float v1 = acc[mt][nt][half * 2 + 1] + bb1;
                if (EPI == 0) {
                    *(unsigned*)((__nv_bfloat16*)Cout + idx) = pack2(v0, v1);
                } else if (EPI == 1) {
                    *(unsigned*)((__nv_bfloat16*)Cout + idx) = pack2(gelu_exact(v0), gelu_exact(v1));
                } else if (EPI == 2) {
                    float2 r1 = *(const float2*)(res1 + idx);
                    float2 r2 = *(const float2*)(res2 + idx);
                    float2 o2;
                    o2.x = r1.x + v0 + r2.x * att[cc] * 0.01f;
                    o2.y = r1.y + v1 + r2.y * att[cc + 1] * 0.01f;
                    *(float2*)((float*)Cout + idx) = o2;
                } else {
                    float2 r1 = *(const float2*)(res1 + idx);
                    float2 o2;
                    o2.x = r1.x + v0;
                    o2.y = r1.y + v1;
                    *(float2*)((float*)Cout + idx) = o2;
                }
            }
        }
    }
}

// ---------------- attention (bf16 mma, register softmax) ----------------
// block = (window, head, 32-query chunk); 256 thr
#define OFF_Q  0
#define OFF_K  1536
#define OFF_V  26112
#define OFF_P  42752
#define OFF_R1 77056
#define OFF_R2 77568
#define OFF_OR 78080
#define SMEM_ATTN 82176

__device__ __forceinline__ int wtok(int j, int base) {
    return ((j >> 6) << 12) + base + (((j >> 3) & 7) << 6) + (j & 7);
}

__global__ __launch_bounds__(256) void attn_kernel(
    const __nv_bfloat16* __restrict__ qkv, const __nv_bfloat16* __restrict__ biasb,
    __nv_bfloat16* __restrict__ o)
{
    extern __shared__ char smc[];
    __nv_bfloat16* q_s = (__nv_bfloat16*)(smc + OFF_Q);   // 32 x 24
    __nv_bfloat16* k_s = (__nv_bfloat16*)(smc + OFF_K);   // 512 x 24
    __nv_bfloat16* v_t = (__nv_bfloat16*)(smc + OFF_V);   // 16 x 520
    __nv_bfloat16* p_s = (__nv_bfloat16*)(smc + OFF_P);   // 32 x 536
    float* red1 = (float*)(smc + OFF_R1);                  // 32 x 4
    float* red2 = (float*)(smc + OFF_R2);
    float* o_red = (float*)(smc + OFF_OR);                 // 2 x 32 x 16
    unsigned q_u = (unsigned)__cvta_generic_to_shared(q_s);
    unsigned p_u = (unsigned)__cvta_generic_to_shared(p_s);

    int blk = blockIdx.x;
    int qc = blk & 15;
    int head = (blk >> 4) % 6;
    int win = blk / 96;
    int base = (win >> 3) * 512 + (win & 7) * 8;
    int m0 = qc * 32;
    int tx = threadIdx.x;
    int warp = tx >> 5, lane = tx & 31;
    int gid = lane >> 2, tig = lane & 3;

    // load K, V
    for (int idx = tx; idx < 1024; idx += 256) {
        int j = idx >> 1, half = idx & 1;
        int t = wtok(j, base);
        const __nv_bfloat16* p = qkv + (size_t)t * 288 + head * 16 + half * 8;
        *(uint4*)(k_s + j * 24 + half * 8) = *(const uint4*)(p + 96);
        uint4 v4 = *(const uint4*)(p + 192);
        const __nv_bfloat16* vp = (const __nv_bfloat16*)&v4;
        #pragma unroll
        for (int dd2 = 0; dd2 < 8; dd2++)
            v_t[(half * 8 + dd2) * 520 + j] = vp[dd2];
    }
    // load Q scaled by hd^-0.5 = 0.25
    if (tx < 64) {
        int i = tx >> 1, half = tx & 1;
        int t = wtok(m0 + i, base);
        uint4 raw = *(const uint4*)(qkv + (size_t)t * 288 + head * 16 + half * 8);
        const __nv_bfloat16* rp = (const __nv_bfloat16*)&raw;
        unsigned pk[4];
        #pragma unroll
        for (int e = 0; e < 4; e++)
            pk[e] = pack2(__bfloat162float(rp[e * 2]) * 0.25f,
                          __bfloat162float(rp[e * 2 + 1]) * 0.25f);
        *(uint4*)(q_s + i * 24 + half * 8) = *(uint4*)pk;
    }
    __syncthreads();

    // QK: warp = 16 rows x 128 cols
    int wm = warp >> 2, wn = warp & 3;
    int r0 = wm * 16, j0 = wn * 128;
    float acc[16][4] = {};
    {
        unsigned aq[4];
        ldsm4(aq, q_u + 2u * ((r0 + (lane & 15)) * 24 + ((lane >> 4) << 3)));
        #pragma unroll
        for (int nt = 0; nt < 16; nt++) {
            const __nv_bfloat16* bp = k_s + (j0 + nt * 8 + gid) * 24 + tig * 2;
            unsigned bf[2];
            bf[0] = *(const unsigned*)bp;
            bf[1] = *(const unsigned*)(bp + 8);
            mma16(acc[nt], aq, bf);
        }
        // add bias
        const __nv_bfloat16* bbA = biasb + ((size_t)head * 512 + (m0 + r0 + gid)) * 512 + j0 + tig * 2;
        const __nv_bfloat16* bbB = bbA + 8 * 512;
        #pragma unroll
        for (int nt = 0; nt < 16; nt++) {
            float2 fa = __bfloat1622float2(*(const __nv_bfloat162*)(bbA + nt * 8));
            float2 fb = __bfloat1622float2(*(const __nv_bfloat162*)(bbB + nt * 8));
            acc[nt][0] += fa.x; acc[nt][1] += fa.y;
            acc[nt][2] += fb.x; acc[nt][3] += fb.y;
        }
    }
    // softmax
    {
        float mA = -1e30f, mB = -1e30f;
        #pragma unroll
        for (int nt = 0; nt < 16; nt++) {
            mA = fmaxf(mA, fmaxf(acc[nt][0], acc[nt][1]));
            mB = fmaxf(mB, fmaxf(acc[nt][2], acc[nt][3]));
        }
        mA = fmaxf(mA, __shfl_xor_sync(0xffffffffu, mA, 1));
        mA = fmaxf(mA, __shfl_xor_sync(0xffffffffu, mA, 2));
        mB = fmaxf(mB, __shfl_xor_sync(0xffffffffu, mB, 1));
        mB = fmaxf(mB, __shfl_xor_sync(0xffffffffu, mB, 2));
        if (tig == 0) {
            red1[(r0 + gid) * 4 + wn] = mA;
            red1[(r0 + gid + 8) * 4 + wn] = mB;
        }
        __syncthreads();
        mA = fmaxf(fmaxf(red1[(r0 + gid) * 4 + 0], red1[(r0 + gid) * 4 + 1]),
                   fmaxf(red1[(r0 + gid) * 4 + 2], red1[(r0 + gid) * 4 + 3]));
        mB = fmaxf(fmaxf(red1[(r0 + gid + 8) * 4 + 0], red1[(r0 + gid + 8) * 4 + 1]),
                   fmaxf(red1[(r0 + gid + 8) * 4 + 2], red1[(r0 + gid + 8) * 4 + 3]));
        float sA = 0.f, sB = 0.f;
        #pragma unroll
        for (int nt = 0; nt < 16; nt++) {
            acc[nt][0] = __expf(acc[nt][0] - mA);
            acc[nt][1] = __expf(acc[nt][1] - mA);
            acc[nt][2] = __expf(acc[nt][2] - mB);
            acc[nt][3] = __expf(acc[nt][3] - mB);
            sA += acc[nt][0] + acc[nt][1];
            sB += acc[nt][2] + acc[nt][3];
        }
        sA += __shfl_xor_sync(0xffffffffu, sA, 1);
        sA += __shfl_xor_sync(0xffffffffu, sA, 2);
        sB += __shfl_xor_sync(0xffffffffu, sB, 1);
        sB += __shfl_xor_sync(0xffffffffu, sB, 2);
        if (tig == 0) {
            red2[(r0 + gid) * 4 + wn] = sA;
            red2[(r0 + gid + 8) * 4 + wn] = sB;
        }
        __syncthreads();
        sA = red2[(r0 + gid) * 4 + 0] + red2[(r0 + gid) * 4 + 1]
           + red2[(r0 + gid) * 4 + 2] + red2[(r0 + gid) * 4 + 3];
        sB = red2[(r0 + gid + 8) * 4 + 0] + red2[(r0 + gid + 8) * 4 + 1]
           + red2[(r0 + gid + 8) * 4 + 2] + red2[(r0 + gid + 8) * 4 + 3];
        float iA = 1.0f / sA, iB = 1.0f / sB;
        #pragma unroll
        for (int nt = 0; nt < 16; nt++) {
            int cc = j0 + nt * 8 + tig * 2;
            *(unsigned*)(p_s + (r0 + gid) * 536 + cc) = pack2(acc[nt][0] * iA, acc[nt][1] * iA);
            *(unsigned*)(p_s + (r0 + gid + 8) * 536 + cc) = pack2(acc[nt][2] * iB, acc[nt][3] * iB);
        }
    }
    __syncthreads();

    // PV: O[32][16]; warps: mt = w&1, vn = (w>>1)&1, kh = w>>2
    {
        int mt = warp & 1, vn = (warp >> 1) & 1, kh = warp >> 2;
        float oa[4] = {};
        #pragma unroll 4
        for (int ks = 0; ks < 16; ks++) {
            int k = kh * 256 + ks * 16;
            unsigned af[4];
            ldsm4(af, p_u + 2u * ((mt * 16 + (lane & 15)) * 536 + k + ((lane >> 4) << 3)));
            const __nv_bfloat16* bp = v_t + (vn * 8 + gid) * 520 + k + tig * 2;
            unsigned bf[2];
            bf[0] = *(const unsigned*)bp;
            bf[1] = *(const unsigned*)(bp + 8);
            mma16(oa, af, bf);
        }
        int col = vn * 8 + tig * 2;
        float* orp = o_red + kh * 512;
        *(float2*)(orp + (mt * 16 + gid) * 16 + col) = make_float2(oa[0], oa[1]);
        *(float2*)(orp + (mt * 16 + gid + 8) * 16 + col) = make_float2(oa[2], oa[3]);
    }
    __syncthreads();
    {
        int row = tx >> 3, d2 = tx & 7;
        int dim = d2 * 2;
        float v0 = o_red[row * 16 + dim] + o_red[512 + row * 16 + dim];
        float v1 = o_red[row * 16 + dim + 1] + o_red[512 + row * 16 + dim + 1];
        int t = wtok(m0 + row, base);
        *(unsigned*)(o + (size_t)t * CCH + head * 16 + dim) = pack2(v0, v1);
    }
}

// ---------------- launch ----------------
extern "C" void kernel_launch(void* const* d_in, const int* in_sizes, int n_in,
                              void* d_out, int out_size)
{
    (void)in_sizes; (void)n_in; (void)out_size;
    const float* x       = (const float*)d_in[0];
    const float* n1g     = (const float*)d_in[1];
    const float* n1b     = (const float*)d_in[2];
    const float* qkv_w   = (const float*)d_in[3];
    const float* qkv_b   = (const float*)d_in[4];
    const float* rpbt    = (const float*)d_in[5];
    const float* proj_w  = (const float*)d_in[6];
    const float* proj_b  = (const float*)d_in[7];
    const float* conv1_w = (const float*)d_in[8];
    const float* conv1_b = (const float*)d_in[9];
    const float* conv2_w = (const float*)d_in[10];
    const float* conv2_b = (const float*)d_in[11];
    const float* ca1_w   = (const float*)d_in[12];
    const float* ca1_b   = (const float*)d_in[13];
    const float* ca2_w   = (const float*)d_in[14];
    const float* ca2_b   = (const float*)d_in[15];
    const float* n2g     = (const float*)d_in[16];
    const float* n2b     = (const float*)d_in[17];
    const float* fc1_w   = (const float*)d_in[18];
    const float* fc1_b   = (const float*)d_in[19];
    const float* fc2_w   = (const float*)d_in[20];
    const float* fc2_b   = (const float*)d_in[21];
    const int*   rpi     = (const int*)d_in[22];
    float* out = (float*)d_out;

    __nv_bfloat16 *xn, *y1, *qkvb, *biasb, *ob, *xn2, *hb, *w1r, *w2r, *qw, *pw, *f1w, *f2w;
    float *y2, *part, *att, *x1;
    cudaGetSymbolAddress((void**)&xn,    g_xn);
    cudaGetSymbolAddress((void**)&y1,    g_y1);
    cudaGetSymbolAddress((void**)&y2,    g_y2);
    cudaGetSymbolAddress((void**)&part,  g_part);
    cudaGetSymbolAddress((void**)&att,   g_att);
    cudaGetSymbolAddress((void**)&qkvb,  g_qkv);
    cudaGetSymbolAddress((void**)&biasb, g_bias);
    cudaGetSymbolAddress((void**)&ob,    g_o);
    cudaGetSymbolAddress((void**)&x1,    g_x1);
    cudaGetSymbolAddress((void**)&xn2,   g_xn2);
    cudaGetSymbolAddress((void**)&hb,    g_h);
    cudaGetSymbolAddress((void**)&w1r,   g_w1r);
    cudaGetSymbolAddress((void**)&w2r,   g_w2r);
    cudaGetSymbolAddress((void**)&qw,    g_qw);
    cudaGetSymbolAddress((void**)&pw,    g_pw);
    cudaGetSymbolAddress((void**)&f1w,   g_f1w);
    cudaGetSymbolAddress((void**)&f2w,   g_f2w);

    const int SMEM_CONV1 = (66 * 104 + 96 * 104) * 2;   // 33696
    const int SMEM_CONV2 = (66 * 40 + 288 * 40) * 2;    // 28320
    const int SMEM_GEMM  = (128 * 104 + 96 * 104) * 2;  // 46592
    cudaFuncSetAttribute(conv1_kernel, cudaFuncAttributeMaxDynamicSharedMemorySize, SMEM_CONV1);
    cudaFuncSetAttribute(conv2_kernel, cudaFuncAttributeMaxDynamicSharedMemorySize, SMEM_CONV2);
    cudaFuncSetAttribute(gemm_bf16<0>, cudaFuncAttributeMaxDynamicSharedMemorySize, SMEM_GEMM);
    cudaFuncSetAttribute(gemm_bf16<1>, cudaFuncAttributeMaxDynamicSharedMemorySize, SMEM_GEMM);
    cudaFuncSetAttribute(gemm_bf16<2>, cudaFuncAttributeMaxDynamicSharedMemorySize, SMEM_GEMM);
    cudaFuncSetAttribute(gemm_bf16<3>, cudaFuncAttributeMaxDynamicSharedMemorySize, SMEM_GEMM);
    cudaFuncSetAttribute(attn_kernel, cudaFuncAttributeMaxDynamicSharedMemorySize, SMEM_ATTN);

    // weight conversions
    cvt_bf16<<<(288 * 96 + 255) / 256, 256>>>(qkv_w, qw, 288 * 96);
    cvt_bf16<<<(96 * 96 + 255) / 256, 256>>>(proj_w, pw, 96 * 96);
    cvt_bf16<<<(384 * 96 + 255) / 256, 256>>>(fc1_w, f1w, 384 * 96);
    cvt_bf16<<<(96 * 384 + 255) / 256, 256>>>(fc2_w, f2w, 96 * 384);
    reorder_w1<<<(CMP * CCH * 27 + 255) / 256, 256>>>(conv1_w, w1r);
    reorder_w2<<<(CCH * CMP * 27 + 255) / 256, 256>>>(conv2_w, w2r);

    ln_kernel<<<LTOK / 8, 256>>>(x, n1g, n1b, xn);

    conv1_kernel<<<DD * HH, 256, SMEM_CONV1>>>(xn, w1r, conv1_b, y1);
    conv2_kernel<<<DD * HH, 256, SMEM_CONV2>>>(y1, w2r, conv2_b, y2);
    pool_kernel<<<256, CCH>>>(y2, part);
    ca_kernel<<<1, CCH>>>(part, ca1_w, ca1_b, ca2_w, ca2_b, att);

    expand_bias<<<HEADS * NTOK * NTOK / 256, 256>>>(rpi, rpbt, biasb);
    gemm_bf16<0><<<dim3(LTOK / 128, 3), 256, SMEM_GEMM>>>(
        xn, qw, qkv_b, qkvb, 96, 288, nullptr, nullptr, nullptr);
    attn_kernel<<<NWIN * HEADS * 16, 256, SMEM_ATTN>>>(qkvb, biasb, ob);

    gemm_bf16<2><<<dim3(LTOK / 128, 1), 256, SMEM_GEMM>>>(
        ob, pw, proj_b, x1, 96, 96, x, y2, att);

    ln_kernel<<<LTOK / 8, 256>>>(x1, n2g, n2b, xn2);
    gemm_bf16<1><<<dim3(LTOK / 128, 4), 256, SMEM_GEMM>>>(
        xn2, f1w, fc1_b, hb, 96, 384, nullptr, nullptr, nullptr);
    gemm_bf16<3><<<dim3(LTOK / 128, 1), 256, SMEM_GEMM>>>(
        hb, f2w, fc2_b, out, 384, 96, x1, nullptr, nullptr);
}

// round 4
// speedup vs baseline: 4.5377x; 1.0589x over previous
#include <cuda_runtime.h>
#include <cuda_bf16.h>
#include <math.h>
#include <stdint.h>

#define DD 8
#define HH 64
#define WW 64
#define LTOK 32768
#define CCH 96
#define CMP 32
#define HID 384
#define HEADS 6
#define HDIM 16
#define NWIN 64
#define NTOK 512

// ---------------- scratch ----------------
__device__ __nv_bfloat16 g_xn  [LTOK * CCH];
__device__ __nv_bfloat16 g_y1  [LTOK * CMP];
__device__ float         g_y2  [LTOK * CCH];
__device__ float         g_part[256 * CCH];
__device__ float         g_att [CCH];
__device__ __nv_bfloat16 g_qkv [LTOK * 3 * CCH];
__device__ __nv_bfloat16 g_bias[HEADS * NTOK * NTOK];
__device__ __nv_bfloat16 g_o   [LTOK * CCH];
__device__ float         g_x1  [LTOK * CCH];
__device__ __nv_bfloat16 g_xn2 [LTOK * CCH];
__device__ __nv_bfloat16 g_h   [LTOK * HID];
__device__ __nv_bfloat16 g_w1r [27 * CMP * CCH];
__device__ __nv_bfloat16 g_w2r [27 * CCH * CMP];
__device__ __nv_bfloat16 g_qw  [288 * 96];
__device__ __nv_bfloat16 g_pw  [96 * 96];
__device__ __nv_bfloat16 g_f1w [384 * 96];
__device__ __nv_bfloat16 g_f2w [96 * 384];

__device__ __forceinline__ float gelu_exact(float v) {
    return 0.5f * v * (1.0f + erff(v * 0.70710678118654752f));
}
__device__ __forceinline__ unsigned pack2(float a, float b) {
    __nv_bfloat162 t = __floats2bfloat162_rn(a, b);
    return *reinterpret_cast<unsigned*>(&t);
}
__device__ __forceinline__ void ldsm4(unsigned* r, unsigned addr) {
    asm volatile("ldmatrix.sync.aligned.m8n8.x4.shared.b16 {%0,%1,%2,%3},[%4];"
                 : "=r"(r[0]), "=r"(r[1]), "=r"(r[2]), "=r"(r[3]) : "r"(addr));
}
// B-operand ldmatrix: covers TWO n8 tiles (rows nb..nb+15) for one k16 block.
// r[0],r[1] = b-frag of n-tile 0; r[2],r[3] = b-frag of n-tile 1.
__device__ __forceinline__ void ldsmB(unsigned* r, const __nv_bfloat16* base, int S, int lane) {
    int tq = lane & 7, sel = lane >> 3;
    const __nv_bfloat16* p = base + ((sel & 2) * 4 + tq) * S + (sel & 1) * 8;
    ldsm4(r, (unsigned)__cvta_generic_to_shared(p));
}
__device__ __forceinline__ void mma16(float* d, const unsigned* a, const unsigned* b) {
    asm volatile(
        "mma.sync.aligned.m16n8k16.row.col.f32.bf16.bf16.f32 "
        "{%0,%1,%2,%3},{%4,%5,%6,%7},{%8,%9},{%0,%1,%2,%3};"
        : "+f"(d[0]), "+f"(d[1]), "+f"(d[2]), "+f"(d[3])
        : "r"(a[0]), "r"(a[1]), "r"(a[2]), "r"(a[3]), "r"(b[0]), "r"(b[1]));
}

// ---------------- LayerNorm (fp32 in -> bf16 out) ----------------
__global__ void ln_kernel(const float* __restrict__ x, const float* __restrict__ g,
                          const float* __restrict__ b, __nv_bfloat16* __restrict__ out)
{
    int row  = blockIdx.x * 8 + (threadIdx.x >> 5);
    int lane = threadIdx.x & 31;
    const float* xr = x + (size_t)row * CCH;
    float v0 = xr[lane], v1 = xr[lane + 32], v2 = xr[lane + 64];
    float s = v0 + v1 + v2;
    #pragma unroll
    for (int o = 16; o; o >>= 1) s += __shfl_xor_sync(0xffffffffu, s, o);
    float mu = s * (1.0f / 96.0f);
    float d0 = v0 - mu, d1 = v1 - mu, d2 = v2 - mu;
    float q = d0 * d0 + d1 * d1 + d2 * d2;
    #pragma unroll
    for (int o = 16; o; o >>= 1) q += __shfl_xor_sync(0xffffffffu, q, o);
    float inv = rsqrtf(q * (1.0f / 96.0f) + 1e-5f);
    __nv_bfloat16* orow = out + (size_t)row * CCH;
    orow[lane]      = __float2bfloat16(d0 * inv * g[lane]      + b[lane]);
    orow[lane + 32] = __float2bfloat16(d1 * inv * g[lane + 32] + b[lane + 32]);
    orow[lane + 64] = __float2bfloat16(d2 * inv * g[lane + 64] + b[lane + 64]);
}

// ---------------- single fused setup kernel ----------------
// blocks: [0,108) qw | [108,144) pw | [144,288) f1w | [288,432) f2w
//         [432,756) w1r | [756,1080) w2r | [1080,7224) bias expand
__global__ void setup_kernel(
    const float* __restrict__ qkv_w, const float* __restrict__ proj_w,
    const float* __restrict__ fc1_w, const float* __restrict__ fc2_w,
    const float* __restrict__ conv1_w, const float* __restrict__ conv2_w,
    const int* __restrict__ rpi, const float* __restrict__ rpbt,
    __nv_bfloat16* __restrict__ qw, __nv_bfloat16* __restrict__ pw,
    __nv_bfloat16* __restrict__ f1w, __nv_bfloat16* __restrict__ f2w,
    __nv_bfloat16* __restrict__ w1r, __nv_bfloat16* __restrict__ w2r,
    __nv_bfloat16* __restrict__ biasb)
{
    int b = blockIdx.x, tx = threadIdx.x;
    if (b < 108) {
        int i = b * 256 + tx;
        if (i < 288 * 96) qw[i] = __float2bfloat16(qkv_w[i]);
    } else if (b < 144) {
        int i = (b - 108) * 256 + tx;
        if (i < 96 * 96) pw[i] = __float2bfloat16(proj_w[i]);
    } else if (b < 288) {
        int i = (b - 144) * 256 + tx;
        if (i < 384 * 96) f1w[i] = __float2bfloat16(fc1_w[i]);
    } else if (b < 432) {
        int i = (b - 288) * 256 + tx;
        if (i < 96 * 384) f2w[i] = __float2bfloat16(fc2_w[i]);
    } else if (b < 756) {
        int tid = (b - 432) * 256 + tx;
        if (tid < CMP * CCH * 27) {
            int o = tid / (CCH * 27);
            int rem = tid - o * (CCH * 27);
            int c = rem / 27;
            int tap = rem - c * 27;
            w1r[(tap * CMP + o) * CCH + c] = __float2bfloat16(conv1_w[tid]);
        }
    } else if (b < 1080) {
        int tid = (b - 756) * 256 + tx;
        if (tid < CCH * CMP * 27) {
            int o = tid / (CMP * 27);
            int rem = tid - o * (CMP * 27);
            int i = rem / 27;
            int tap = rem - i * 27;
            w2r[(tap * CCH + o) * CMP + i] = __float2bfloat16(conv2_w[tid]);
        }
    } else {
        int tid = (b - 1080) * 256 + tx;
        int h = tid >> 18;
        int r = tid & 262143;
        biasb[tid] = __float2bfloat16(rpbt[rpi[r] * HEADS + h]);
    }
}

// ---------------- conv1: 96->32 + GELU ----------------
__global__ __launch_bounds__(256) void conv1_kernel(
    const __nv_bfloat16* __restrict__ xn, const __nv_bfloat16* __restrict__ w1r,
    const float* __restrict__ b1, __nv_bfloat16* __restrict__ y1)
{
    extern __shared__ __nv_bfloat16 smb[];
    __nv_bfloat16* in_s = smb;              // 66 x 104
    __nv_bfloat16* w_s  = smb + 66 * 104;   // 96 x 104
    unsigned in_u = (unsigned)__cvta_generic_to_shared(in_s);
    int d = blockIdx.x >> 6, h = blockIdx.x & 63;
    int tx = threadIdx.x;
    int warp = tx >> 5, lane = tx & 31;
    int wm = warp >> 1, wn = warp & 1;
    int gid = lane >> 2, tig = lane & 3;
    float acc[2][4] = {};
    for (int kd = 0; kd < 3; kd++) {
        int dd = d + kd - 1;
        for (int kh = 0; kh < 3; kh++) {
            int hh = h + kh - 1;
            bool rv = ((unsigned)dd < (unsigned)DD) && ((unsigned)hh < (unsigned)HH);
            __syncthreads();
            const __nv_bfloat16* src_row = xn + ((size_t)(dd * HH + hh) * WW) * CCH;
            for (int idx = tx; idx < 792; idx += 256) {
                int r = idx / 12, c = idx - r * 12;
                int wv = r - 1;
                uint4 val = make_uint4(0u, 0u, 0u, 0u);
                if (rv && (unsigned)wv < 64u) val = *(const uint4*)(src_row + wv * CCH + c * 8);
                *(uint4*)(in_s + r * 104 + c * 8) = val;
            }
            const __nv_bfloat16* wsrc = w1r + (kd * 3 + kh) * 3 * (CMP * CCH);
            for (int idx = tx; idx < 1152; idx += 256) {
                int r = idx / 12, c = idx - r * 12;
                *(uint4*)(w_s + r * 104 + c * 8) = *(const uint4*)(wsrc + idx * 8);
            }
            __syncthreads();
            #pragma unroll
            for (int kw = 0; kw < 3; kw++) {
                #pragma unroll
                for (int ks = 0; ks < 6; ks++) {
                    unsigned af[4];
                    ldsm4(af, in_u + 2u * ((wm * 16 + (lane & 15) + kw) * 104 + ks * 16 + ((lane >> 4) << 3)));
                    unsigned bf[4];
                    ldsmB(bf, w_s + (kw * 32 + wn * 16) * 104 + ks * 16, 104, lane);
                    mma16(acc[0], af, bf);
                    mma16(acc[1], af, bf + 2);
                }
            }
        }
    }
    __nv_bfloat16* orow = y1 + (size_t)(d * HH + h) * WW * CMP;
    #pragma unroll
    for (int nt = 0; nt < 2; nt++) {
        int oc = wn * 16 + nt * 8 + tig * 2;
        float bb0 = b1[oc], bb1 = b1[oc + 1];
        #pragma unroll
        for (int half = 0; half < 2; half++) {
            int v = wm * 16 + gid + half * 8;
            *(unsigned*)(orow + v * CMP + oc) =
                pack2(gelu_exact(acc[nt][half * 2 + 0] + bb0),
                      gelu_exact(acc[nt][half * 2 + 1] + bb1));
        }
    }
}

// ---------------- conv2: 32->96 ----------------
__global__ __launch_bounds__(256) void conv2_kernel(
    const __nv_bfloat16* __restrict__ y1, const __nv_bfloat16* __restrict__ w2r,
    const float* __restrict__ b2, float* __restrict__ y2)
{
    extern __shared__ __nv_bfloat16 smb[];
    __nv_bfloat16* in_s = smb;              // 66 x 40
    __nv_bfloat16* w_s  = smb + 66 * 40;    // 288 x 40
    unsigned in_u = (unsigned)__cvta_generic_to_shared(in_s);
    int d = blockIdx.x >> 6, h = blockIdx.x & 63;
    int tx = threadIdx.x;
    int warp = tx >> 5, lane = tx & 31;
    int wm = warp >> 1, wn = warp & 1;
    int gid = lane >> 2, tig = lane & 3;
    float acc[6][4] = {};
    for (int kd = 0; kd < 3; kd++) {
        int dd = d + kd - 1;
        for (int kh = 0; kh < 3; kh++) {
            int hh = h + kh - 1;
            bool rv = ((unsigned)dd < (unsigned)DD) && ((unsigned)hh < (unsigned)HH);
            __syncthreads();
            const __nv_bfloat16* src_row = y1 + ((size_t)(dd * HH + hh) * WW) * CMP;
            for (int idx = tx; idx < 264; idx += 256) {
                int r = idx >> 2, c = idx & 3;
                int wv = r - 1;
                uint4 val = make_uint4(0u, 0u, 0u, 0u);
                if (rv && (unsigned)wv < 64u) val = *(const uint4*)(src_row + wv * CMP + c * 8);
                *(uint4*)(in_s + r * 40 + c * 8) = val;
            }
            const __nv_bfloat16* wsrc = w2r + (kd * 3 + kh) * 3 * (CCH * CMP);
            for (int idx = tx; idx < 1152; idx += 256) {
                int r = idx >> 2, c = idx & 3;
                *(uint4*)(w_s + r * 40 + c * 8) = *(const uint4*)(wsrc + idx * 8);
            }
            __syncthreads();
            #pragma unroll
            for (int kw = 0; kw < 3; kw++) {
                #pragma unroll
                for (int ks = 0; ks < 2; ks++) {
                    unsigned af[4];
                    ldsm4(af, in_u + 2u * ((wm * 16 + (lane & 15) + kw) * 40 + ks * 16 + ((lane >> 4) << 3)));
                    #pragma unroll
                    for (int np = 0; np < 3; np++) {
                        unsigned bf[4];
                        ldsmB(bf, w_s + (kw * 96 + wn * 48 + np * 16) * 40 + ks * 16, 40, lane);
                        mma16(acc[np * 2], af, bf);
                        mma16(acc[np * 2 + 1], af, bf + 2);
                    }
                }
            }
        }
    }
    float* orow = y2 + (size_t)(d * HH + h) * WW * CCH;
    #pragma unroll
    for (int nt = 0; nt < 6; nt++) {
        int oc = wn * 48 + nt * 8 + tig * 2;
        float bb0 = b2[oc], bb1 = b2[oc + 1];
        #pragma unroll
        for (int half = 0; half < 2; half++) {
            int v = wm * 16 + gid + half * 8;
            float2 o2;
            o2.x = acc[nt][half * 2 + 0] + bb0;
            o2.y = acc[nt][half * 2 + 1] + bb1;
            *(float2*)(orow + v * CCH + oc) = o2;
        }
    }
}

// ---------------- pooling + channel attention ----------------
__global__ void pool_kernel(const float* __restrict__ y2, float* __restrict__ part)
{
    int c = threadIdx.x;
    const float* base = y2 + (size_t)blockIdx.x * 128 * CCH;
    float s = 0.f;
    for (int v = 0; v < 128; v++) s += base[v * CCH + c];
    part[blockIdx.x * CCH + c] = s;
}
__global__ void ca_kernel(const float* __restrict__ part,
                          const float* __restrict__ ca1w, const float* __restrict__ ca1b,
                          const float* __restrict__ ca2w, const float* __restrict__ ca2b,
                          float* __restrict__ att)
{
    __shared__ float p[CCH], hs[3];
    int tx = threadIdx.x;
    float s = 0.f;
    for (int b = 0; b < 256; b++) s += part[b * CCH + tx];
    p[tx] = s * (1.0f / (float)LTOK);
    __syncthreads();
    if (tx < 3) {
        float a = ca1b[tx];
        for (int c = 0; c < CCH; c++) a += ca1w[tx * CCH + c] * p[c];
        hs[tx] = fmaxf(a, 0.f);
    }
    __syncthreads();
    float a = ca2b[tx];
    #pragma unroll
    for (int k = 0; k < 3; k++) a += ca2w[tx * 3 + k] * hs[k];
    att[tx] = 1.0f / (1.0f + expf(-a));
}

// ---------------- bf16 GEMM ----------------
template <int EPI>
__global__ __launch_bounds__(256) void gemm_bf16(
    const __nv_bfloat16* __restrict__ A, const __nv_bfloat16* __restrict__ Wt,
    const float* __restrict__ bias, void* __restrict__ Cout, int Ktot, int Nn,
    const float* __restrict__ res1, const float* __restrict__ res2,
    const float* __restrict__ att)
{
    extern __shared__ __nv_bfloat16 smb[];
    __nv_bfloat16* a_s = smb;               // 128 x 104
    __nv_bfloat16* w_s = smb + 128 * 104;   // 96 x 104
    unsigned a_u = (unsigned)__cvta_generic_to_shared(a_s);
    int m0 = blockIdx.x * 128, n0 = blockIdx.y * 96;
    int tx = threadIdx.x;
    int warp = tx >> 5, lane = tx & 31;
    int wm = warp >> 1, wn = warp & 1;
    int gid = lane >> 2, tig = lane & 3;
    float acc[2][6][4] = {};
    int nchunk = Ktot / 96;
    for (int kc = 0; kc < nchunk; kc++) {
        int k0 = kc * 96;
        __syncthreads();
        for (int idx = tx; idx < 1536; idx += 256) {
            int r = idx / 12, c = idx - r * 12;
            *(uint4*)(a_s + r * 104 + c * 8) = *(const uint4*)(A + (size_t)(m0 + r) * Ktot + k0 + c * 8);
        }
        for (int idx = tx; idx < 1152; idx += 256) {
            int r = idx / 12, c = idx - r * 12;
            *(uint4*)(w_s + r * 104 + c * 8) = *(const uint4*)(Wt + (size_t)(n0 + r) * Ktot + k0 + c * 8);
        }
        __syncthreads();
        #pragma unroll
        for (int ks = 0; ks < 6; ks++) {
            unsigned af[2][4];
            #pragma unroll
            for (int mt = 0; mt < 2; mt++)
                ldsm4(af[mt], a_u + 2u * ((wm * 32 + mt * 16 + (lane & 15)) * 104 + ks * 16 + ((lane >> 4) << 3)));
            #pragma unroll
            for (int np = 0; np < 3; np++) {
                unsigned bf[4];
                ldsmB(bf, w_s + (wn * 48 + np * 16) * 104 + ks * 16, 104, lane);
                #pragma unroll
                for (int mt = 0; mt < 2; mt++) {
                    mma16(acc[mt][np * 2], af[mt], bf);
                    mma16(acc[mt][np * 2 + 1], af[mt], bf + 2);
                }
            }
        }
    }
    #pragma unroll
    for (int mt = 0; mt < 2; mt++) {
        #pragma unroll
        for (int nt = 0; nt < 6; nt++) {
            int cc = n0 + wn * 48 + nt * 8 + tig * 2;
            float bb0 = bias[cc], bb1 = bias[cc + 1];
            #pragma unroll
            for (int half = 0; half < 2; half++) {
                int r = m0 + wm * 32 + mt * 16 + gid + half * 8;
                size_t idx = (size_t)r * Nn + cc;
                float v0 = acc[mt][nt][half * 2 + 0] + bb0;
                float v1 = acc[mt][nt][half * 2 + 1] + bb1;
                if (EPI == 0) {
                    *(unsigned*)((__nv_bfloat16*)Cout + idx) = pack2(v0, v1);
                } else if (EPI == 1) {
                    *(unsigned*)((__nv_bfloat16*)Cout + idx) = pack2(gelu_exact(v0), gelu_exact(v1));
                } else if (EPI == 2) {
                    float2 r1 = *(const float2*)(res1 + idx);
                    float2 r2 = *(const float2*)(res2 + idx);
                    float2 o2;
                    o2.x = r1.x + v0 + r2.x * att[cc] * 0.01f;
                    o2.y = r1.y + v1 + r2.y * att[cc + 1] * 0.01f;
                    *(float2*)((float*)Cout + idx) = o2;
                } else {
                    float2 r1 = *(const float2*)(res1 + idx);
                    float2 o2;
                    o2.x = r1.x + v0;
                    o2.y = r1.y + v1;
                    *(float2*)((float*)Cout + idx) = o2;
                }
            }
        }
    }
}

// ---------------- attention: 64-query blocks, register-fused PV ----------------
#define OFF_Q  0
#define OFF_K  3072
#define OFF_V  27648
#define OFF_R1 44288
#define OFF_R2 45312
#define OFF_OR 46336
#define SMEM_ATTN 62720

__device__ __forceinline__ int wtok(int j, int base) {
    return ((j >> 6) << 12) + base + (((j >> 3) & 7) << 6) + (j & 7);
}

__global__ __launch_bounds__(512) void attn_kernel(
    const __nv_bfloat16* __restrict__ qkv, const __nv_bfloat16* __restrict__ biasb,
    __nv_bfloat16* __restrict__ o)
{
    extern __shared__ char smc[];
    __nv_bfloat16* q_s = (__nv_bfloat16*)(smc + OFF_Q);   // 64 x 24
    __nv_bfloat16* k_s = (__nv_bfloat16*)(smc + OFF_K);   // 512 x 24
    __nv_bfloat16* v_t = (__nv_bfloat16*)(smc + OFF_V);   // 16 x 520
    float* red1 = (float*)(smc + OFF_R1);                  // 64 x 4
    float* red2 = (float*)(smc + OFF_R2);                  // 64 x 4
    float* o_red = (float*)(smc + OFF_OR);                 // 4 x 64 x 16
    unsigned q_u = (unsigned)__cvta_generic_to_shared(q_s);

    int blk = blockIdx.x;
    int qc = blk & 7;                 // 8 chunks of 64 queries
    int head = (blk >> 3) % 6;
    int win = blk / 48;
    int base = (win >> 3) * 512 + (win & 7) * 8;
    int m0 = qc * 64;
    int tx = threadIdx.x;
    int warp = tx >> 5, lane = tx & 31;
    int gid = lane >> 2, tig = lane & 3;
    int wm = warp >> 2, wn = warp & 3;     // wm: 4 m16 tiles; wn: 4 col groups of 128
    int r0 = wm * 16, j0 = wn * 128;

    // load K, V (V transposed)
    for (int idx = tx; idx < 1024; idx += 512) {
        int j = idx >> 1, half = idx & 1;
        int t = wtok(j, base);
        const __nv_bfloat16* p = qkv + (size_t)t * 288 + head * 16 + half * 8;
        *(uint4*)(k_s + j * 24 + half * 8) = *(const uint4*)(p + 96);
        uint4 v4 = *(const uint4*)(p + 192);
        const __nv_bfloat16* vp = (const __nv_bfloat16*)&v4;
        #pragma unroll
        for (int dd2 = 0; dd2 < 8; dd2++)
            v_t[(half * 8 + dd2) * 520 + j] = vp[dd2];
    }
    // load Q scaled by 0.25
    if (tx < 128) {
        int i = tx >> 1, half = tx & 1;
        int t = wtok(m0 + i, base);
        uint4 raw = *(const uint4*)(qkv + (size_t)t * 288 + head * 16 + half * 8);
        const __nv_bfloat16* rp = (const __nv_bfloat16*)&raw;
        unsigned pk[4];
        #pragma unroll
        for (int e = 0; e < 4; e++)
            pk[e] = pack2(__bfloat162float(rp[e * 2]) * 0.25f,
                          __bfloat162float(rp[e * 2 + 1]) * 0.25f);
        *(uint4*)(q_s + i * 24 + half * 8) = *(uint4*)pk;
    }
    __syncthreads();

    // QK: warp = 16 rows x 128 cols (acc[nt] -> cols j0+nt*8)
    float acc[16][4] = {};
    {
        unsigned aq[4];
        ldsm4(aq, q_u + 2u * ((r0 + (lane & 15)) * 24 + ((lane >> 4) << 3)));
        #pragma unroll
        for (int np = 0; np < 8; np++) {
            unsigned bf[4];
            ldsmB(bf, k_s + (j0 + np * 16) * 24, 24, lane);
            mma16(acc[np * 2], aq, bf);
            mma16(acc[np * 2 + 1], aq, bf + 2);
        }
        const __nv_bfloat16* bbA = biasb + ((size_t)head * 512 + (m0 + r0 + gid)) * 512 + j0 + tig * 2;
        const __nv_bfloat16* bbB = bbA + 8 * 512;
        #pragma unroll
        for (int nt = 0; nt < 16; nt++) {
            float2 fa = __bfloat1622float2(*(const __nv_bfloat162*)(bbA + nt * 8));
            float2 fb = __bfloat1622float2(*(const __nv_bfloat162*)(bbB + nt * 8));
            acc[nt][0] += fa.x; acc[nt][1] += fa.y;
            acc[nt][2] += fb.x; acc[nt][3] += fb.y;
        }
    }
    // softmax (rows r0+gid and r0+gid+8)
    {
        float mA = -1e30f, mB = -1e30f;
        #pragma unroll
        for (int nt = 0; nt < 16; nt++) {
            mA = fmaxf(mA, fmaxf(acc[nt][0], acc[nt][1]));
            mB = fmaxf(mB, fmaxf(acc[nt][2], acc[nt][3]));
        }
        mA = fmaxf(mA, __shfl_xor_sync(0xffffffffu, mA, 1));
        mA = fmaxf(mA, __shfl_xor_sync(0xffffffffu, mA, 2));
        mB = fmaxf(mB, __shfl_xor_sync(0xffffffffu, mB, 1));
        mB = fmaxf(mB, __shfl_xor_sync(0xffffffffu, mB, 2));
        if (tig == 0) {
            red1[(r0 + gid) * 4 + wn] = mA;
            red1[(r0 + gid + 8) * 4 + wn] = mB;
        }
        __syncthreads();
        mA = fmaxf(fmaxf(red1[(r0 + gid) * 4 + 0], red1[(r0 + gid) * 4 + 1]),
                   fmaxf(red1[(r0 + gid) * 4 + 2], red1[(r0 + gid) * 4 + 3]));
        mB = fmaxf(fmaxf(red1[(r0 + gid + 8) * 4 + 0], red1[(r0 + gid + 8) * 4 + 1]),
                   fmaxf(red1[(r0 + gid + 8) * 4 + 2], red1[(r0 + gid + 8) * 4 + 3]));
        float sA = 0.f, sB = 0.f;
        #pragma unroll
        for (int nt = 0; nt < 16; nt++) {
            acc[nt][0] = __expf(acc[nt][0] - mA);
            acc[nt][1] = __expf(acc[nt][1] - mA);
            acc[nt][2] = __expf(acc[nt][2] - mB);
            acc[nt][3] = __expf(acc[nt][3] - mB);
            sA += acc[nt][0] + acc[nt][1];
            sB += acc[nt][2] + acc[nt][3];
        }
        sA += __shfl_xor_sync(0xffffffffu, sA, 1);
        sA += __shfl_xor_sync(0xffffffffu, sA, 2);
        sB += __shfl_xor_sync(0xffffffffu, sB, 1);
        sB += __shfl_xor_sync(0xffffffffu, sB, 2);
        if (tig == 0) {
            red2[(r0 + gid) * 4 + wn] = sA;
            red2[(r0 + gid + 8) * 4 + wn] = sB;
        }
        __syncthreads();
        sA = red2[(r0 + gid) * 4 + 0] + red2[(r0 + gid) * 4 + 1]
           + red2[(r0 + gid) * 4 + 2] + red2[(r0 + gid) * 4 + 3];
        sB = red2[(r0 + gid + 8) * 4 + 0] + red2[(r0 + gid + 8) * 4 + 1]
           + red2[(r0 + gid + 8) * 4 + 2] + red2[(r0 + gid + 8) * 4 + 3];
        float iA = 1.0f / sA, iB = 1.0f / sB;
        #pragma unroll
        for (int nt = 0; nt < 16; nt++) {
            acc[nt][0] *= iA; acc[nt][1] *= iA;
            acc[nt][2] *= iB; acc[nt][3] *= iB;
        }
    }

    // PV: P-fragments formed IN REGISTERS from acc (c-frag == a-frag layout).
    // warp computes partial O[16 rows][16 d] over its 128-col k range.
    float oa[2][4] = {};
    #pragma unroll
    for (int kk = 0; kk < 8; kk++) {
        unsigned af[4];
        af[0] = pack2(acc[2 * kk][0],     acc[2 * kk][1]);
        af[1] = pack2(acc[2 * kk][2],     acc[2 * kk][3]);
        af[2] = pack2(acc[2 * kk + 1][0], acc[2 * kk + 1][1]);
        af[3] = pack2(acc[2 * kk + 1][2], acc[2 * kk + 1][3]);
        unsigned bf[4];
        ldsmB(bf, v_t + j0 + kk * 16, 520, lane);   // rows d0..15, k block
        mma16(oa[0], af, bf);
        mma16(oa[1], af, bf + 2);
    }
    {
        float* orp = o_red + (size_t)wn * 1024;
        #pragma unroll
        for (int dt = 0; dt < 2; dt++) {
            int dc = dt * 8 + tig * 2;
            *(float2*)(orp + (r0 + gid) * 16 + dc)     = make_float2(oa[dt][0], oa[dt][1]);
            *(float2*)(orp + (r0 + gid + 8) * 16 + dc) = make_float2(oa[dt][2], oa[dt][3]);
        }
    }
    __syncthreads();
    {
        int row = tx >> 3, d2 = tx & 7;
        int dim = d2 * 2;
        float v0 = 0.f, v1 = 0.f;
        #pragma unroll
        for (int p = 0; p < 4; p++) {
            v0 += o_red[p * 1024 + row * 16 + dim];
            v1 += o_red[p * 1024 + row * 16 + dim + 1];
        }
        int t = wtok(m0 + row, base);
        *(unsigned*)(o + (size_t)t * CCH + head * 16 + dim) = pack2(v0, v1);
    }
}

// ---------------- launch ----------------
extern "C" void kernel_launch(void* const* d_in, const int* in_sizes, int n_in,
                              void* d_out, int out_size)
{
    (void)in_sizes; (void)n_in; (void)out_size;
    const float* x       = (const float*)d_in[0];
    const float* n1g     = (const float*)d_in[1];
    const float* n1b     = (const float*)d_in[2];
    const float* qkv_w   = (const float*)d_in[3];
    const float* qkv_b   = (const float*)d_in[4];
    const float* rpbt    = (const float*)d_in[5];
    const float* proj_w  = (const float*)d_in[6];
    const float* proj_b  = (const float*)d_in[7];
    const float* conv1_w = (const float*)d_in[8];
    const float* conv1_b = (const float*)d_in[9];
    const float* conv2_w = (const float*)d_in[10];
    const float* conv2_b = (const float*)d_in[11];
    const float* ca1_w   = (const float*)d_in[12];
    const float* ca1_b   = (const float*)d_in[13];
    const float* ca2_w   = (const float*)d_in[14];
    const float* ca2_b   = (const float*)d_in[15];
    const float* n2g     = (const float*)d_in[16];
    const float* n2b     = (const float*)d_in[17];
    const float* fc1_w   = (const float*)d_in[18];
    const float* fc1_b   = (const float*)d_in[19];
    const float* fc2_w   = (const float*)d_in[20];
    const float* fc2_b   = (const float*)d_in[21];
    const int*   rpi     = (const int*)d_in[22];
    float* out = (float*)d_out;

    __nv_bfloat16 *xn, *y1, *qkvb, *biasb, *ob, *xn2, *hb, *w1r, *w2r, *qw, *pw, *f1w, *f2w;
    float *y2, *part, *att, *x1;
    cudaGetSymbolAddress((void**)&xn,    g_xn);
    cudaGetSymbolAddress((void**)&y1,    g_y1);
    cudaGetSymbolAddress((void**)&y2,    g_y2);
    cudaGetSymbolAddress((void**)&part,  g_part);
    cudaGetSymbolAddress((void**)&att,   g_att);
    cudaGetSymbolAddress((void**)&qkvb,  g_qkv);
    cudaGetSymbolAddress((void**)&biasb, g_bias);
    cudaGetSymbolAddress((void**)&ob,    g_o);
    cudaGetSymbolAddress((void**)&x1,    g_x1);
    cudaGetSymbolAddress((void**)&xn2,   g_xn2);
    cudaGetSymbolAddress((void**)&hb,    g_h);
    cudaGetSymbolAddress((void**)&w1r,   g_w1r);
    cudaGetSymbolAddress((void**)&w2r,   g_w2r);
    cudaGetSymbolAddress((void**)&qw,    g_qw);
    cudaGetSymbolAddress((void**)&pw,    g_pw);
    cudaGetSymbolAddress((void**)&f1w,   g_f1w);
    cudaGetSymbolAddress((void**)&f2w,   g_f2w);

    const int SMEM_CONV1 = (66 * 104 + 96 * 104) * 2;
    const int SMEM_CONV2 = (66 * 40 + 288 * 40) * 2;
    const int SMEM_GEMM  = (128 * 104 + 96 * 104) * 2;
    cudaFuncSetAttribute(conv1_kernel, cudaFuncAttributeMaxDynamicSharedMemorySize, SMEM_CONV1);
    cudaFuncSetAttribute(conv2_kernel, cudaFuncAttributeMaxDynamicSharedMemorySize, SMEM_CONV2);
    cudaFuncSetAttribute(gemm_bf16<0>, cudaFuncAttributeMaxDynamicSharedMemorySize, SMEM_GEMM);
    cudaFuncSetAttribute(gemm_bf16<1>, cudaFuncAttributeMaxDynamicSharedMemorySize, SMEM_GEMM);
    cudaFuncSetAttribute(gemm_bf16<2>, cudaFuncAttributeMaxDynamicSharedMemorySize, SMEM_GEMM);
    cudaFuncSetAttribute(gemm_bf16<3>, cudaFuncAttributeMaxDynamicSharedMemorySize, SMEM_GEMM);
    cudaFuncSetAttribute(attn_kernel, cudaFuncAttributeMaxDynamicSharedMemorySize, SMEM_ATTN);

    setup_kernel<<<7224, 256>>>(qkv_w, proj_w, fc1_w, fc2_w, conv1_w, conv2_w,
                                rpi, rpbt, qw, pw, f1w, f2w, w1r, w2r, biasb);

    ln_kernel<<<LTOK / 8, 256>>>(x, n1g, n1b, xn);

    conv1_kernel<<<DD * HH, 256, SMEM_CONV1>>>(xn, w1r, conv1_b, y1);
    conv2_kernel<<<DD * HH, 256, SMEM_CONV2>>>(y1, w2r, conv2_b, y2);
    pool_kernel<<<256, CCH>>>(y2, part);
    ca_kernel<<<1, CCH>>>(part, ca1_w, ca1_b, ca2_w, ca2_b, att);

    gemm_bf16<0><<<dim3(LTOK / 128, 3), 256, SMEM_GEMM>>>(
        xn, qw, qkv_b, qkvb, 96, 288, nullptr, nullptr, nullptr);
    attn_kernel<<<NWIN * HEADS * 8, 512, SMEM_ATTN>>>(qkvb, biasb, ob);

    gemm_bf16<2><<<dim3(LTOK / 128, 1), 256, SMEM_GEMM>>>(
        ob, pw, proj_b, x1, 96, 96, x, y2, att);

    ln_kernel<<<LTOK / 8, 256>>>(x1, n2g, n2b, xn2);
    gemm_bf16<1><<<dim3(LTOK / 128, 4), 256, SMEM_GEMM>>>(
        xn2, f1w, fc1_b, hb, 96, 384, nullptr, nullptr, nullptr);
    gemm_bf16<3><<<dim3(LTOK / 128, 1), 256, SMEM_GEMM>>>(
        hb, f2w, fc2_b, out, 384, 96, x1, nullptr, nullptr);
}

// round 5
// speedup vs baseline: 4.5660x; 1.0062x over previous
#include <cuda_runtime.h>
#include <cuda_bf16.h>
#include <math.h>
#include <stdint.h>

#define DD 8
#define HH 64
#define WW 64
#define LTOK 32768
#define CCH 96
#define CMP 32
#define HID 384
#define HEADS 6
#define HDIM 16
#define NWIN 64
#define NTOK 512

// ---------------- scratch ----------------
__device__ __nv_bfloat16 g_xn  [LTOK * CCH];
__device__ __nv_bfloat16 g_y1  [LTOK * CMP];
__device__ float         g_y2  [LTOK * CCH];
__device__ float         g_part[256 * CCH];
__device__ float         g_att [CCH];
__device__ __nv_bfloat16 g_qkv [LTOK * 3 * CCH];
__device__ __nv_bfloat16 g_bias[HEADS * NTOK * NTOK];
__device__ __nv_bfloat16 g_o   [LTOK * CCH];
__device__ float         g_x1  [LTOK * CCH];
__device__ __nv_bfloat16 g_xn2 [LTOK * CCH];
__device__ __nv_bfloat16 g_h   [LTOK * HID];
__device__ __nv_bfloat16 g_w1r [27 * CMP * CCH];
__device__ __nv_bfloat16 g_w2r [27 * CCH * CMP];
__device__ __nv_bfloat16 g_qw  [288 * 96];
__device__ __nv_bfloat16 g_pw  [96 * 96];
__device__ __nv_bfloat16 g_f1w [384 * 96];
__device__ __nv_bfloat16 g_f2w [96 * 384];

__device__ __forceinline__ float gelu_exact(float v) {
    return 0.5f * v * (1.0f + erff(v * 0.70710678118654752f));
}
__device__ __forceinline__ unsigned pack2(float a, float b) {
    __nv_bfloat162 t = __floats2bfloat162_rn(a, b);
    return *reinterpret_cast<unsigned*>(&t);
}
__device__ __forceinline__ void ldsm4(unsigned* r, unsigned addr) {
    asm volatile("ldmatrix.sync.aligned.m8n8.x4.shared.b16 {%0,%1,%2,%3},[%4];"
                 : "=r"(r[0]), "=r"(r[1]), "=r"(r[2]), "=r"(r[3]) : "r"(addr));
}
// B-operand ldmatrix: two n8 tiles for one k16 block.
__device__ __forceinline__ void ldsmB(unsigned* r, const __nv_bfloat16* base, int S, int lane) {
    int tq = lane & 7, sel = lane >> 3;
    const __nv_bfloat16* p = base + ((sel & 2) * 4 + tq) * S + (sel & 1) * 8;
    ldsm4(r, (unsigned)__cvta_generic_to_shared(p));
}
__device__ __forceinline__ void mma16(float* d, const unsigned* a, const unsigned* b) {
    asm volatile(
        "mma.sync.aligned.m16n8k16.row.col.f32.bf16.bf16.f32 "
        "{%0,%1,%2,%3},{%4,%5,%6,%7},{%8,%9},{%0,%1,%2,%3};"
        : "+f"(d[0]), "+f"(d[1]), "+f"(d[2]), "+f"(d[3])
        : "r"(a[0]), "r"(a[1]), "r"(a[2]), "r"(a[3]), "r"(b[0]), "r"(b[1]));
}

// ---------------- LayerNorm (fp32 in -> bf16 out) ----------------
__global__ void ln_kernel(const float* __restrict__ x, const float* __restrict__ g,
                          const float* __restrict__ b, __nv_bfloat16* __restrict__ out)
{
    int row  = blockIdx.x * 8 + (threadIdx.x >> 5);
    int lane = threadIdx.x & 31;
    const float* xr = x + (size_t)row * CCH;
    float v0 = xr[lane], v1 = xr[lane + 32], v2 = xr[lane + 64];
    float s = v0 + v1 + v2;
    #pragma unroll
    for (int o = 16; o; o >>= 1) s += __shfl_xor_sync(0xffffffffu, s, o);
    float mu = s * (1.0f / 96.0f);
    float d0 = v0 - mu, d1 = v1 - mu, d2 = v2 - mu;
    float q = d0 * d0 + d1 * d1 + d2 * d2;
    #pragma unroll
    for (int o = 16; o; o >>= 1) q += __shfl_xor_sync(0xffffffffu, q, o);
    float inv = rsqrtf(q * (1.0f / 96.0f) + 1e-5f);
    __nv_bfloat16* orow = out + (size_t)row * CCH;
    orow[lane]      = __float2bfloat16(d0 * inv * g[lane]      + b[lane]);
    orow[lane + 32] = __float2bfloat16(d1 * inv * g[lane + 32] + b[lane + 32]);
    orow[lane + 64] = __float2bfloat16(d2 * inv * g[lane + 64] + b[lane + 64]);
}

// ---------------- fused setup ----------------
__global__ void setup_kernel(
    const float* __restrict__ qkv_w, const float* __restrict__ proj_w,
    const float* __restrict__ fc1_w, const float* __restrict__ fc2_w,
    const float* __restrict__ conv1_w, const float* __restrict__ conv2_w,
    const int* __restrict__ rpi, const float* __restrict__ rpbt,
    __nv_bfloat16* __restrict__ qw, __nv_bfloat16* __restrict__ pw,
    __nv_bfloat16* __restrict__ f1w, __nv_bfloat16* __restrict__ f2w,
    __nv_bfloat16* __restrict__ w1r, __nv_bfloat16* __restrict__ w2r,
    __nv_bfloat16* __restrict__ biasb)
{
    int b = blockIdx.x, tx = threadIdx.x;
    if (b < 108) {
        int i = b * 256 + tx;
        if (i < 288 * 96) qw[i] = __float2bfloat16(qkv_w[i]);
    } else if (b < 144) {
        int i = (b - 108) * 256 + tx;
        if (i < 96 * 96) pw[i] = __float2bfloat16(proj_w[i]);
    } else if (b < 288) {
        int i = (b - 144) * 256 + tx;
        if (i < 384 * 96) f1w[i] = __float2bfloat16(fc1_w[i]);
    } else if (b < 432) {
        int i = (b - 288) * 256 + tx;
        if (i < 96 * 384) f2w[i] = __float2bfloat16(fc2_w[i]);
    } else if (b < 756) {
        int tid = (b - 432) * 256 + tx;
        if (tid < CMP * CCH * 27) {
            int o = tid / (CCH * 27);
            int rem = tid - o * (CCH * 27);
            int c = rem / 27;
            int tap = rem - c * 27;
            w1r[(tap * CMP + o) * CCH + c] = __float2bfloat16(conv1_w[tid]);
        }
    } else if (b < 1080) {
        int tid = (b - 756) * 256 + tx;
        if (tid < CCH * CMP * 27) {
            int o = tid / (CMP * 27);
            int rem = tid - o * (CMP * 27);
            int i = rem / 27;
            int tap = rem - i * 27;
            w2r[(tap * CCH + o) * CMP + i] = __float2bfloat16(conv2_w[tid]);
        }
    } else {
        int tid = (b - 1080) * 256 + tx;
        int h = tid >> 18;
        int r = tid & 262143;
        biasb[tid] = __float2bfloat16(rpbt[rpi[r] * HEADS + h]);
    }
}

// ---------------- conv1: 96->32 + GELU, 2 h-rows per block (M=128) ----------------
__global__ __launch_bounds__(256) void conv1_kernel(
    const __nv_bfloat16* __restrict__ xn, const __nv_bfloat16* __restrict__ w1r,
    const float* __restrict__ b1, __nv_bfloat16* __restrict__ y1)
{
    extern __shared__ __nv_bfloat16 smb[];
    __nv_bfloat16* in_s = smb;               // 2 x 66 x 104
    __nv_bfloat16* w_s  = smb + 132 * 104;   // 96 x 104
    unsigned in_u = (unsigned)__cvta_generic_to_shared(in_s);
    int d = blockIdx.x >> 5, h0 = (blockIdx.x & 31) * 2;
    int tx = threadIdx.x;
    int warp = tx >> 5, lane = tx & 31;
    int gid = lane >> 2, tig = lane & 3;
    int hrow = warp >> 2, w16 = warp & 3;
    float acc[4][4] = {};
    for (int kd = 0; kd < 3; kd++) {
        int dd = d + kd - 1;
        bool dv = (unsigned)dd < (unsigned)DD;
        for (int kh = 0; kh < 3; kh++) {
            int hh0 = h0 + kh - 1;
            __syncthreads();
            for (int idx = tx; idx < 1584; idx += 256) {
                int r = idx / 12, c = idx - r * 12;
                int row = (r >= 66) ? 1 : 0;
                int wv = r - row * 66 - 1;
                int hh = hh0 + row;
                uint4 val = make_uint4(0u, 0u, 0u, 0u);
                if (dv && (unsigned)hh < (unsigned)HH && (unsigned)wv < 64u)
                    val = *(const uint4*)(xn + ((size_t)((dd * HH + hh) * WW) + wv) * CCH + c * 8);
                *(uint4*)(in_s + r * 104 + c * 8) = val;
            }
            const __nv_bfloat16* wsrc = w1r + (kd * 3 + kh) * 3 * (CMP * CCH);
            for (int idx = tx; idx < 1152; idx += 256) {
                int r = idx / 12, c = idx - r * 12;
                *(uint4*)(w_s + r * 104 + c * 8) = *(const uint4*)(wsrc + idx * 8);
            }
            __syncthreads();
            #pragma unroll
            for (int kw = 0; kw < 3; kw++) {
                #pragma unroll
                for (int ks = 0; ks < 6; ks++) {
                    unsigned af[4];
                    ldsm4(af, in_u + 2u * ((hrow * 66 + w16 * 16 + kw + (lane & 15)) * 104
                                           + ks * 16 + ((lane >> 4) << 3)));
                    #pragma unroll
                    for (int np = 0; np < 2; np++) {
                        unsigned bf[4];
                        ldsmB(bf, w_s + (kw * 32 + np * 16) * 104 + ks * 16, 104, lane);
                        mma16(acc[np * 2], af, bf);
                        mma16(acc[np * 2 + 1], af, bf + 2);
                    }
                }
            }
        }
    }
    #pragma unroll
    for (int nt = 0; nt < 4; nt++) {
        int oc = nt * 8 + tig * 2;
        float bb0 = b1[oc], bb1 = b1[oc + 1];
        #pragma unroll
        for (int half = 0; half < 2; half++) {
            int m = warp * 16 + gid + half * 8;
            int hr = m >> 6, w = m & 63;
            size_t oidx = ((size_t)((d * HH + h0 + hr) * WW) + w) * CMP + oc;
            *(unsigned*)(y1 + oidx) =
                pack2(gelu_exact(acc[nt][half * 2 + 0] + bb0),
                      gelu_exact(acc[nt][half * 2 + 1] + bb1));
        }
    }
}

// ---------------- conv2: 32->96, 2 h-rows per block ----------------
__global__ __launch_bounds__(256) void conv2_kernel(
    const __nv_bfloat16* __restrict__ y1, const __nv_bfloat16* __restrict__ w2r,
    const float* __restrict__ b2, float* __restrict__ y2)
{
    extern __shared__ __nv_bfloat16 smb[];
    __nv_bfloat16* in_s = smb;               // 2 x 66 x 40
    __nv_bfloat16* w_s  = smb + 132 * 40;    // 288 x 40
    unsigned in_u = (unsigned)__cvta_generic_to_shared(in_s);
    int d = blockIdx.x >> 5, h0 = (blockIdx.x & 31) * 2;
    int tx = threadIdx.x;
    int warp = tx >> 5, lane = tx & 31;
    int gid = lane >> 2, tig = lane & 3;
    int hrow = warp >> 2, w16 = warp & 3;
    float acc[12][4] = {};
    for (int kd = 0; kd < 3; kd++) {
        int dd = d + kd - 1;
        bool dv = (unsigned)dd < (unsigned)DD;
        for (int kh = 0; kh < 3; kh++) {
            int hh0 = h0 + kh - 1;
            __syncthreads();
            for (int idx = tx; idx < 528; idx += 256) {
                int r = idx >> 2, c = idx & 3;
                int row = (r >= 66) ? 1 : 0;
                int wv = r - row * 66 - 1;
                int hh = hh0 + row;
                uint4 val = make_uint4(0u, 0u, 0u, 0u);
                if (dv && (unsigned)hh < (unsigned)HH && (unsigned)wv < 64u)
                    val = *(const uint4*)(y1 + ((size_t)((dd * HH + hh) * WW) + wv) * CMP + c * 8);
                *(uint4*)(in_s + r * 40 + c * 8) = val;
            }
            const __nv_bfloat16* wsrc = w2r + (kd * 3 + kh) * 3 * (CCH * CMP);
            for (int idx = tx; idx < 1152; idx += 256) {
                int r = idx >> 2, c = idx & 3;
                *(uint4*)(w_s + r * 40 + c * 8) = *(const uint4*)(wsrc + idx * 8);
            }
            __syncthreads();
            #pragma unroll
            for (int kw = 0; kw < 3; kw++) {
                #pragma unroll
                for (int ks = 0; ks < 2; ks++) {
                    unsigned af[4];
                    ldsm4(af, in_u + 2u * ((hrow * 66 + w16 * 16 + kw + (lane & 15)) * 40
                                           + ks * 16 + ((lane >> 4) << 3)));
                    #pragma unroll
                    for (int np = 0; np < 6; np++) {
                        unsigned bf[4];
                        ldsmB(bf, w_s + (kw * 96 + np * 16) * 40 + ks * 16, 40, lane);
                        mma16(acc[np * 2], af, bf);
                        mma16(acc[np * 2 + 1], af, bf + 2);
                    }
                }
            }
        }
    }
    #pragma unroll
    for (int nt = 0; nt < 12; nt++) {
        int oc = nt * 8 + tig * 2;
        float bb0 = b2[oc], bb1 = b2[oc + 1];
        #pragma unroll
        for (int half = 0; half < 2; half++) {
            int m = warp * 16 + gid + half * 8;
            int hr = m >> 6, w = m & 63;
            size_t oidx = ((size_t)((d * HH + h0 + hr) * WW) + w) * CCH + oc;
            float2 o2;
            o2.x = acc[nt][half * 2 + 0] + bb0;
            o2.y = acc[nt][half * 2 + 1] + bb1;
            *(float2*)(y2 + oidx) = o2;
        }
    }
}

// ---------------- pooling + channel attention ----------------
__global__ void pool_kernel(const float* __restrict__ y2, float* __restrict__ part)
{
    int c = threadIdx.x;
    const float* base = y2 + (size_t)blockIdx.x * 128 * CCH;
    float s = 0.f;
    for (int v = 0; v < 128; v++) s += base[v * CCH + c];
    part[blockIdx.x * CCH + c] = s;
}
__global__ void ca_kernel(const float* __restrict__ part,
                          const float* __restrict__ ca1w, const float* __restrict__ ca1b,
                          const float* __restrict__ ca2w, const float* __restrict__ ca2b,
                          float* __restrict__ att)
{
    __shared__ float p[CCH], hs[3];
    int tx = threadIdx.x;
    float s = 0.f;
    for (int b = 0; b < 256; b++) s += part[b * CCH + tx];
    p[tx] = s * (1.0f / (float)LTOK);
    __syncthreads();
    if (tx < 3) {
        float a = ca1b[tx];
        for (int c = 0; c < CCH; c++) a += ca1w[tx * CCH + c] * p[c];
        hs[tx] = fmaxf(a, 0.f);
    }
    __syncthreads();
    float a = ca2b[tx];
    #pragma unroll
    for (int k = 0; k < 3; k++) a += ca2w[tx * 3 + k] * hs[k];
    att[tx] = 1.0f / (1.0f + expf(-a));
}

// ---------------- bf16 GEMM (EPI: 0 bf16, 1 gelu->bf16, 3 fp32 res1+v) ----------------
// MTILES: 2 -> 128-row tile, 1 -> 64-row tile
template <int EPI, int MTILES>
__global__ __launch_bounds__(256) void gemm_bf16(
    const __nv_bfloat16* __restrict__ A, const __nv_bfloat16* __restrict__ Wt,
    const float* __restrict__ bias, void* __restrict__ Cout, int Ktot, int Nn,
    const float* __restrict__ res1)
{
    const int MROWS = MTILES * 64;
    extern __shared__ __nv_bfloat16 smb[];
    __nv_bfloat16* a_s = smb;
    __nv_bfloat16* w_s = smb + MROWS * 104;
    unsigned a_u = (unsigned)__cvta_generic_to_shared(a_s);
    int m0 = blockIdx.x * MROWS, n0 = blockIdx.y * 96;
    int tx = threadIdx.x;
    int warp = tx >> 5, lane = tx & 31;
    int wm = warp >> 1, wn = warp & 1;
    int gid = lane >> 2, tig = lane & 3;
    float acc[MTILES][6][4] = {};
    int nchunk = Ktot / 96;
    for (int kc = 0; kc < nchunk; kc++) {
        int k0 = kc * 96;
        __syncthreads();
        for (int idx = tx; idx < MROWS * 12; idx += 256) {
            int r = idx / 12, c = idx - r * 12;
            *(uint4*)(a_s + r * 104 + c * 8) = *(const uint4*)(A + (size_t)(m0 + r) * Ktot + k0 + c * 8);
        }
        for (int idx = tx; idx < 1152; idx += 256) {
            int r = idx / 12, c = idx - r * 12;
            *(uint4*)(w_s + r * 104 + c * 8) = *(const uint4*)(Wt + (size_t)(n0 + r) * Ktot + k0 + c * 8);
        }
        __syncthreads();
        #pragma unroll
        for (int ks = 0; ks < 6; ks++) {
            unsigned af[MTILES][4];
            #pragma unroll
            for (int mt = 0; mt < MTILES; mt++)
                ldsm4(af[mt], a_u + 2u * ((wm * (MTILES * 16) + mt * 16 + (lane & 15)) * 104
                                          + ks * 16 + ((lane >> 4) << 3)));
            #pragma unroll
            for (int np = 0; np < 3; np++) {
                unsigned bf[4];
                ldsmB(bf, w_s + (wn * 48 + np * 16) * 104 + ks * 16, 104, lane);
                #pragma unroll
                for (int mt = 0; mt < MTILES; mt++) {
                    mma16(acc[mt][np * 2], af[mt], bf);
                    mma16(acc[mt][np * 2 + 1], af[mt], bf + 2);
                }
            }
        }
    }
    #pragma unroll
    for (int mt = 0; mt < MTILES; mt++) {
        #pragma unroll
        for (int nt = 0; nt < 6; nt++) {
            int cc = n0 + wn * 48 + nt * 8 + tig * 2;
            float bb0 = bias[cc], bb1 = bias[cc + 1];
            #pragma unroll
            for (int half = 0; half < 2; half++) {
                int r = m0 + wm * (MTILES * 16) + mt * 16 + gid + half * 8;
                size_t idx = (size_t)r * Nn + cc;
                float v0 = acc[mt][nt][half * 2 + 0] + bb0;
                float v1 = acc[mt][nt][half * 2 + 1] + bb1;
                if (EPI == 0) {
                    *(unsigned*)((__nv_bfloat16*)Cout + idx) = pack2(v0, v1);
                } else if (EPI == 1) {
                    *(unsigned*)((__nv_bfloat16*)Cout + idx) = pack2(gelu_exact(v0), gelu_exact(v1));
                } else {
                    float2 r1 = *(const float2*)(res1 + idx);
                    float2 o2;
                    o2.x = r1.x + v0;
                    o2.y = r1.y + v1;
                    *(float2*)((float*)Cout + idx) = o2;
                }
            }
        }
    }
}

// ---------------- proj GEMM + residual merge + fused LayerNorm2 ----------------
// x1 = x + (o@W+b) + y2*att*0.01 ; xn2 = LN(x1)*g + b  (tile N=96 = full row)
__global__ __launch_bounds__(256) void gemm_proj_ln(
    const __nv_bfloat16* __restrict__ A, const __nv_bfloat16* __restrict__ Wt,
    const float* __restrict__ bias,
    const float* __restrict__ res1, const float* __restrict__ res2,
    const float* __restrict__ att,
    const float* __restrict__ n2g, const float* __restrict__ n2b,
    float* __restrict__ x1, __nv_bfloat16* __restrict__ xn2)
{
    extern __shared__ __nv_bfloat16 smb[];
    __nv_bfloat16* a_s = smb;               // 128 x 104
    __nv_bfloat16* w_s = smb + 128 * 104;   // 96 x 104
    float* red_s = (float*)smb;             // aliased after mainloop: 128 x 2
    float* red_q = red_s + 256;             // 128 x 2
    unsigned a_u = (unsigned)__cvta_generic_to_shared(a_s);
    int m0 = blockIdx.x * 128;
    int tx = threadIdx.x;
    int warp = tx >> 5, lane = tx & 31;
    int wm = warp >> 1, wn = warp & 1;
    int gid = lane >> 2, tig = lane & 3;
    float acc[2][6][4] = {};
    {
        for (int idx = tx; idx < 1536; idx += 256) {
            int r = idx / 12, c = idx - r * 12;
            *(uint4*)(a_s + r * 104 + c * 8) = *(const uint4*)(A + (size_t)(m0 + r) * 96 + c * 8);
        }
        for (int idx = tx; idx < 1152; idx += 256) {
            int r = idx / 12, c = idx - r * 12;
            *(uint4*)(w_s + r * 104 + c * 8) = *(const uint4*)(Wt + (size_t)r * 96 + c * 8);
        }
        __syncthreads();
        #pragma unroll
        for (int ks = 0; ks < 6; ks++) {
            unsigned af[2][4];
            #pragma unroll
            for (int mt = 0; mt < 2; mt++)
                ldsm4(af[mt], a_u + 2u * ((wm * 32 + mt * 16 + (lane & 15)) * 104
                                          + ks * 16 + ((lane >> 4) << 3)));
            #pragma unroll
            for (int np = 0; np < 3; np++) {
                unsigned bf[4];
                ldsmB(bf, w_s + (wn * 48 + np * 16) * 104 + ks * 16, 104, lane);
                #pragma unroll
                for (int mt = 0; mt < 2; mt++) {
                    mma16(acc[mt][np * 2], af[mt], bf);
                    mma16(acc[mt][np * 2 + 1], af[mt], bf + 2);
                }
            }
        }
    }
    __syncthreads();   // before smem reuse as reduction buffer

    // compute x1 values, accumulate row sums
    float rs[2][2] = {}, rq[2][2] = {};
    #pragma unroll
    for (int mt = 0; mt < 2; mt++) {
        #pragma unroll
        for (int nt = 0; nt < 6; nt++) {
            int cc = wn * 48 + nt * 8 + tig * 2;
            float bb0 = bias[cc], bb1 = bias[cc + 1];
            float a0 = att[cc] * 0.01f, a1 = att[cc + 1] * 0.01f;
            #pragma unroll
            for (int half = 0; half < 2; half++) {
                int r = m0 + wm * 32 + mt * 16 + gid + half * 8;
                size_t idx = (size_t)r * 96 + cc;
                float2 r1 = *(const float2*)(res1 + idx);
                float2 r2 = *(const float2*)(res2 + idx);
                float v0 = r1.x + acc[mt][nt][half * 2 + 0] + bb0 + r2.x * a0;
                float v1 = r1.y + acc[mt][nt][half * 2 + 1] + bb1 + r2.y * a1;
                acc[mt][nt][half * 2 + 0] = v0;
                acc[mt][nt][half * 2 + 1] = v1;
                *(float2*)(x1 + idx) = make_float2(v0, v1);
                rs[mt][half] += v0 + v1;
                rq[mt][half] += v0 * v0 + v1 * v1;
            }
        }
    }
    #pragma unroll
    for (int mt = 0; mt < 2; mt++)
        #pragma unroll
        for (int half = 0; half < 2; half++) {
            float s = rs[mt][half], q = rq[mt][half];
            s += __shfl_xor_sync(0xffffffffu, s, 1);
            s += __shfl_xor_sync(0xffffffffu, s, 2);
            q += __shfl_xor_sync(0xffffffffu, q, 1);
            q += __shfl_xor_sync(0xffffffffu, q, 2);
            if (tig == 0) {
                int lr = wm * 32 + mt * 16 + half * 8 + gid;
                red_s[lr * 2 + wn] = s;
                red_q[lr * 2 + wn] = q;
            }
        }
    __syncthreads();
    #pragma unroll
    for (int mt = 0; mt < 2; mt++) {
        #pragma unroll
        for (int half = 0; half < 2; half++) {
            int lr = wm * 32 + mt * 16 + half * 8 + gid;
            float sum = red_s[lr * 2] + red_s[lr * 2 + 1];
            float sq  = red_q[lr * 2] + red_q[lr * 2 + 1];
            float mean = sum * (1.0f / 96.0f);
            float var = sq * (1.0f / 96.0f) - mean * mean;
            float inv = rsqrtf(var + 1e-5f);
            int r = m0 + lr;
            #pragma unroll
            for (int nt = 0; nt < 6; nt++) {
                int cc = wn * 48 + nt * 8 + tig * 2;
                float g0 = n2g[cc], g1 = n2g[cc + 1];
                float b0 = n2b[cc], b1 = n2b[cc + 1];
                float v0 = (acc[mt][nt][half * 2 + 0] - mean) * inv * g0 + b0;
                float v1 = (acc[mt][nt][half * 2 + 1] - mean) * inv * g1 + b1;
                *(unsigned*)(xn2 + (size_t)r * 96 + cc) = pack2(v0, v1);
            }
        }
    }
}

// ---------------- attention: 64-query blocks, register-fused PV ----------------
#define OFF_Q  0
#define OFF_K  3072
#define OFF_V  27648
#define OFF_R1 44288
#define OFF_R2 45312
#define OFF_OR 46336
#define SMEM_ATTN 62720

__device__ __forceinline__ int wtok(int j, int base) {
    return ((j >> 6) << 12) + base + (((j >> 3) & 7) << 6) + (j & 7);
}

__global__ __launch_bounds__(512) void attn_kernel(
    const __nv_bfloat16* __restrict__ qkv, const __nv_bfloat16* __restrict__ biasb,
    __nv_bfloat16* __restrict__ o)
{
    extern __shared__ char smc[];
    __nv_bfloat16* q_s = (__nv_bfloat16*)(smc + OFF_Q);   // 64 x 24
    __nv_bfloat16* k_s = (__nv_bfloat16*)(smc + OFF_K);   // 512 x 24
    __nv_bfloat16* v_t = (__nv_bfloat16*)(smc + OFF_V);   // 16 x 520
    float* red1 = (float*)(smc + OFF_R1);
    float* red2 = (float*)(smc + OFF_R2);
    float* o_red = (float*)(smc + OFF_OR);                 // 4 x 64 x 16
    unsigned q_u = (unsigned)__cvta_generic_to_shared(q_s);

    int blk = blockIdx.x;
    int qc = blk & 7;
    int head = (blk >> 3) % 6;
    int win = blk / 48;
    int base = (win >> 3) * 512 + (win & 7) * 8;
    int m0 = qc * 64;
    int tx = threadIdx.x;
    int warp = tx >> 5, lane = tx & 31;
    int gid = lane >> 2, tig = lane & 3;
    int wm = warp >> 2, wn = warp & 3;
    int r0 = wm * 16, j0 = wn * 128;

    for (int idx = tx; idx < 1024; idx += 512) {
        int j = idx >> 1, half = idx & 1;
        int t = wtok(j, base);
        const __nv_bfloat16* p = qkv + (size_t)t * 288 + head * 16 + half * 8;
        *(uint4*)(k_s + j * 24 + half * 8) = *(const uint4*)(p + 96);
        uint4 v4 = *(const uint4*)(p + 192);
        const __nv_bfloat16* vp = (const __nv_bfloat16*)&v4;
        #pragma unroll
        for (int dd2 = 0; dd2 < 8; dd2++)
            v_t[(half * 8 + dd2) * 520 + j] = vp[dd2];
    }
    if (tx < 128) {
        int i = tx >> 1, half = tx & 1;
        int t = wtok(m0 + i, base);
        uint4 raw = *(const uint4*)(qkv + (size_t)t * 288 + head * 16 + half * 8);
        const __nv_bfloat16* rp = (const __nv_bfloat16*)&raw;
        unsigned pk[4];
        #pragma unroll
        for (int e = 0; e < 4; e++)
            pk[e] = pack2(__bfloat162float(rp[e * 2]) * 0.25f,
                          __bfloat162float(rp[e * 2 + 1]) * 0.25f);
        *(uint4*)(q_s + i * 24 + half * 8) = *(uint4*)pk;
    }
    __syncthreads();

    float acc[16][4] = {};
    {
        unsigned aq[4];
        ldsm4(aq, q_u + 2u * ((r0 + (lane & 15)) * 24 + ((lane >> 4) << 3)));
        #pragma unroll
        for (int np = 0; np < 8; np++) {
            unsigned bf[4];
            ldsmB(bf, k_s + (j0 + np * 16) * 24, 24, lane);
            mma16(acc[np * 2], aq, bf);
            mma16(acc[np * 2 + 1], aq, bf + 2);
        }
        const __nv_bfloat16* bbA = biasb + ((size_t)head * 512 + (m0 + r0 + gid)) * 512 + j0 + tig * 2;
        const __nv_bfloat16* bbB = bbA + 8 * 512;
        #pragma unroll
        for (int nt = 0; nt < 16; nt++) {
            float2 fa = __bfloat1622float2(*(const __nv_bfloat162*)(bbA + nt * 8));
            float2 fb = __bfloat1622float2(*(const __nv_bfloat162*)(bbB + nt * 8));
            acc[nt][0] += fa.x; acc[nt][1] += fa.y;
            acc[nt][2] += fb.x; acc[nt][3] += fb.y;
        }
    }
    {
        float mA = -1e30f, mB = -1e30f;
        #pragma unroll
        for (int nt = 0; nt < 16; nt++) {
            mA = fmaxf(mA, fmaxf(acc[nt][0], acc[nt][1]));
            mB = fmaxf(mB, fmaxf(acc[nt][2], acc[nt][3]));
        }
        mA = fmaxf(mA, __shfl_xor_sync(0xffffffffu, mA, 1));
        mA = fmaxf(mA, __shfl_xor_sync(0xffffffffu, mA, 2));
        mB = fmaxf(mB, __shfl_xor_sync(0xffffffffu, mB, 1));
        mB = fmaxf(mB, __shfl_xor_sync(0xffffffffu, mB, 2));
        if (tig == 0) {
            red1[(r0 + gid) * 4 + wn] = mA;
            red1[(r0 + gid + 8) * 4 + wn] = mB;
        }
        __syncthreads();
        mA = fmaxf(fmaxf(red1[(r0 + gid) * 4 + 0], red1[(r0 + gid) * 4 + 1]),
                   fmaxf(red1[(r0 + gid) * 4 + 2], red1[(r0 + gid) * 4 + 3]));
        mB = fmaxf(fmaxf(red1[(r0 + gid + 8) * 4 + 0], red1[(r0 + gid + 8) * 4 + 1]),
                   fmaxf(red1[(r0 + gid + 8) * 4 + 2], red1[(r0 + gid + 8) * 4 + 3]));
        float sA = 0.f, sB = 0.f;
        #pragma unroll
        for (int nt = 0; nt < 16; nt++) {
            acc[nt][0] = __expf(acc[nt][0] - mA);
            acc[nt][1] = __expf(acc[nt][1] - mA);
            acc[nt][2] = __expf(acc[nt][2] - mB);
            acc[nt][3] = __expf(acc[nt][3] - mB);
            sA += acc[nt][0] + acc[nt][1];
            sB += acc[nt][2] + acc[nt][3];
        }
        sA += __shfl_xor_sync(0xffffffffu, sA, 1);
        sA += __shfl_xor_sync(0xffffffffu, sA, 2);
        sB += __shfl_xor_sync(0xffffffffu, sB, 1);
        sB += __shfl_xor_sync(0xffffffffu, sB, 2);
        if (tig == 0) {
            red2[(r0 + gid) * 4 + wn] = sA;
            red2[(r0 + gid + 8) * 4 + wn] = sB;
        }
        __syncthreads();
        sA = red2[(r0 + gid) * 4 + 0] + red2[(r0 + gid) * 4 + 1]
           + red2[(r0 + gid) * 4 + 2] + red2[(r0 + gid) * 4 + 3];
        sB = red2[(r0 + gid + 8) * 4 + 0] + red2[(r0 + gid + 8) * 4 + 1]
           + red2[(r0 + gid + 8) * 4 + 2] + red2[(r0 + gid + 8) * 4 + 3];
        float iA = 1.0f / sA, iB = 1.0f / sB;
        #pragma unroll
        for (int nt = 0; nt < 16; nt++) {
            acc[nt][0] *= iA; acc[nt][1] *= iA;
            acc[nt][2] *= iB; acc[nt][3] *= iB;
        }
    }

    float oa[2][4] = {};
    #pragma unroll
    for (int kk = 0; kk < 8; kk++) {
        unsigned af[4];
        af[0] = pack2(acc[2 * kk][0],     acc[2 * kk][1]);
        af[1] = pack2(acc[2 * kk][2],     acc[2 * kk][3]);
        af[2] = pack2(acc[2 * kk + 1][0], acc[2 * kk + 1][1]);
        af[3] = pack2(acc[2 * kk + 1][2], acc[2 * kk + 1][3]);
        unsigned bf[4];
        ldsmB(bf, v_t + j0 + kk * 16, 520, lane);
        mma16(oa[0], af, bf);
        mma16(oa[1], af, bf + 2);
    }
    {
        float* orp = o_red + (size_t)wn * 1024;
        #pragma unroll
        for (int dt = 0; dt < 2; dt++) {
            int dc = dt * 8 + tig * 2;
            *(float2*)(orp + (r0 + gid) * 16 + dc)     = make_float2(oa[dt][0], oa[dt][1]);
            *(float2*)(orp + (r0 + gid + 8) * 16 + dc) = make_float2(oa[dt][2], oa[dt][3]);
        }
    }
    __syncthreads();
    {
        int row = tx >> 3, d2 = tx & 7;
        int dim = d2 * 2;
        float v0 = 0.f, v1 = 0.f;
        #pragma unroll
        for (int p = 0; p < 4; p++) {
            v0 += o_red[p * 1024 + row * 16 + dim];
            v1 += o_red[p * 1024 + row * 16 + dim + 1];
        }
        int t = wtok(m0 + row, base);
        *(unsigned*)(o + (size_t)t * CCH + head * 16 + dim) = pack2(v0, v1);
    }
}

// ---------------- launch ----------------
extern "C" void kernel_launch(void* const* d_in, const int* in_sizes, int n_in,
                              void* d_out, int out_size)
{
    (void)in_sizes; (void)n_in; (void)out_size;
    const float* x       = (const float*)d_in[0];
    const float* n1g     = (const float*)d_in[1];
    const float* n1b     = (const float*)d_in[2];
    const float* qkv_w   = (const float*)d_in[3];
    const float* qkv_b   = (const float*)d_in[4];
    const float* rpbt    = (const float*)d_in[5];
    const float* proj_w  = (const float*)d_in[6];
    const float* proj_b  = (const float*)d_in[7];
    const float* conv1_w = (const float*)d_in[8];
    const float* conv1_b = (const float*)d_in[9];
    const float* conv2_w = (const float*)d_in[10];
    const float* conv2_b = (const float*)d_in[11];
    const float* ca1_w   = (const float*)d_in[12];
    const float* ca1_b   = (const float*)d_in[13];
    const float* ca2_w   = (const float*)d_in[14];
    const float* ca2_b   = (const float*)d_in[15];
    const float* n2g     = (const float*)d_in[16];
    const float* n2b     = (const float*)d_in[17];
    const float* fc1_w   = (const float*)d_in[18];
    const float* fc1_b   = (const float*)d_in[19];
    const float* fc2_w   = (const float*)d_in[20];
    const float* fc2_b   = (const float*)d_in[21];
    const int*   rpi     = (const int*)d_in[22];
    float* out = (float*)d_out;

    __nv_bfloat16 *xn, *y1, *qkvb, *biasb, *ob, *xn2, *hb, *w1r, *w2r, *qw, *pw, *f1w, *f2w;
    float *y2, *part, *att, *x1;
    cudaGetSymbolAddress((void**)&xn,    g_xn);
    cudaGetSymbolAddress((void**)&y1,    g_y1);
    cudaGetSymbolAddress((void**)&y2,    g_y2);
    cudaGetSymbolAddress((void**)&part,  g_part);
    cudaGetSymbolAddress((void**)&att,   g_att);
    cudaGetSymbolAddress((void**)&qkvb,  g_qkv);
    cudaGetSymbolAddress((void**)&biasb, g_bias);
    cudaGetSymbolAddress((void**)&ob,    g_o);
    cudaGetSymbolAddress((void**)&x1,    g_x1);
    cudaGetSymbolAddress((void**)&xn2,   g_xn2);
    cudaGetSymbolAddress((void**)&hb,    g_h);
    cudaGetSymbolAddress((void**)&w1r,   g_w1r);
    cudaGetSymbolAddress((void**)&w2r,   g_w2r);
    cudaGetSymbolAddress((void**)&qw,    g_qw);
    cudaGetSymbolAddress((void**)&pw,    g_pw);
    cudaGetSymbolAddress((void**)&f1w,   g_f1w);
    cudaGetSymbolAddress((void**)&f2w,   g_f2w);

    const int SMEM_CONV1 = (132 * 104 + 96 * 104) * 2;   // 47424
    const int SMEM_CONV2 = (132 * 40 + 288 * 40) * 2;    // 33600
    const int SMEM_G128  = (128 * 104 + 96 * 104) * 2;   // 46592
    const int SMEM_G64   = (64 * 104 + 96 * 104) * 2;    // 33280
    cudaFuncSetAttribute(conv1_kernel, cudaFuncAttributeMaxDynamicSharedMemorySize, SMEM_CONV1);
    cudaFuncSetAttribute(conv2_kernel, cudaFuncAttributeMaxDynamicSharedMemorySize, SMEM_CONV2);
    cudaFuncSetAttribute(gemm_bf16<0, 2>, cudaFuncAttributeMaxDynamicSharedMemorySize, SMEM_G128);
    cudaFuncSetAttribute(gemm_bf16<1, 2>, cudaFuncAttributeMaxDynamicSharedMemorySize, SMEM_G128);
    cudaFuncSetAttribute(gemm_bf16<3, 1>, cudaFuncAttributeMaxDynamicSharedMemorySize, SMEM_G64);
    cudaFuncSetAttribute(gemm_proj_ln, cudaFuncAttributeMaxDynamicSharedMemorySize, SMEM_G128);
    cudaFuncSetAttribute(attn_kernel, cudaFuncAttributeMaxDynamicSharedMemorySize, SMEM_ATTN);

    setup_kernel<<<7224, 256>>>(qkv_w, proj_w, fc1_w, fc2_w, conv1_w, conv2_w,
                                rpi, rpbt, qw, pw, f1w, f2w, w1r, w2r, biasb);

    ln_kernel<<<LTOK / 8, 256>>>(x, n1g, n1b, xn);

    conv1_kernel<<<256, 256, SMEM_CONV1>>>(xn, w1r, conv1_b, y1);
    conv2_kernel<<<256, 256, SMEM_CONV2>>>(y1, w2r, conv2_b, y2);
    pool_kernel<<<256, CCH>>>(y2, part);
    ca_kernel<<<1, CCH>>>(part, ca1_w, ca1_b, ca2_w, ca2_b, att);

    gemm_bf16<0, 2><<<dim3(LTOK / 128, 3), 256, SMEM_G128>>>(
        xn, qw, qkv_b, qkvb, 96, 288, nullptr);
    attn_kernel<<<NWIN * HEADS * 8, 512, SMEM_ATTN>>>(qkvb, biasb, ob);

    gemm_proj_ln<<<LTOK / 128, 256, SMEM_G128>>>(
        ob, pw, proj_b, x, y2, att, n2g, n2b, x1, xn2);

    gemm_bf16<1, 2><<<dim3(LTOK / 128, 4), 256, SMEM_G128>>>(
        xn2, f1w, fc1_b, hb, 96, 384, nullptr);
    gemm_bf16<3, 1><<<dim3(LTOK / 64, 1), 256, SMEM_G64>>>(
        hb, f2w, fc2_b, out, 384, 96, x1);
}

// round 6
// speedup vs baseline: 4.6884x; 1.0268x over previous
#include <cuda_runtime.h>
#include <cuda_bf16.h>
#include <math.h>
#include <stdint.h>

#define DD 8
#define HH 64
#define WW 64
#define LTOK 32768
#define CCH 96
#define CMP 32
#define HID 384
#define HEADS 6
#define HDIM 16
#define NWIN 64
#define NTOK 512

// ---------------- scratch ----------------
__device__ __nv_bfloat16 g_xn  [LTOK * CCH];
__device__ __nv_bfloat16 g_y1  [LTOK * CMP];
__device__ float         g_y2  [LTOK * CCH];
__device__ float         g_part[512 * CCH];
__device__ float         g_att [CCH];
__device__ __nv_bfloat16 g_qkv [LTOK * 3 * CCH];
__device__ __nv_bfloat16 g_bias[HEADS * NTOK * NTOK];
__device__ __nv_bfloat16 g_o   [LTOK * CCH];
__device__ float         g_x1  [LTOK * CCH];
__device__ __nv_bfloat16 g_xn2 [LTOK * CCH];
__device__ __nv_bfloat16 g_h   [LTOK * HID];
__device__ __nv_bfloat16 g_w1r [27 * CMP * CCH];
__device__ __nv_bfloat16 g_w2r [27 * CCH * CMP];
__device__ __nv_bfloat16 g_qw  [288 * 96];
__device__ __nv_bfloat16 g_pw  [96 * 96];
__device__ __nv_bfloat16 g_f1w [384 * 96];
__device__ __nv_bfloat16 g_f2w [96 * 384];

__device__ __forceinline__ float gelu_exact(float v) {
    return 0.5f * v * (1.0f + erff(v * 0.70710678118654752f));
}
__device__ __forceinline__ unsigned pack2(float a, float b) {
    __nv_bfloat162 t = __floats2bfloat162_rn(a, b);
    return *reinterpret_cast<unsigned*>(&t);
}
__device__ __forceinline__ void ldsm4(unsigned* r, unsigned addr) {
    asm volatile("ldmatrix.sync.aligned.m8n8.x4.shared.b16 {%0,%1,%2,%3},[%4];"
                 : "=r"(r[0]), "=r"(r[1]), "=r"(r[2]), "=r"(r[3]) : "r"(addr));
}
__device__ __forceinline__ void ldsmB(unsigned* r, const __nv_bfloat16* base, int S, int lane) {
    int tq = lane & 7, sel = lane >> 3;
    const __nv_bfloat16* p = base + ((sel & 2) * 4 + tq) * S + (sel & 1) * 8;
    ldsm4(r, (unsigned)__cvta_generic_to_shared(p));
}
__device__ __forceinline__ void mma16(float* d, const unsigned* a, const unsigned* b) {
    asm volatile(
        "mma.sync.aligned.m16n8k16.row.col.f32.bf16.bf16.f32 "
        "{%0,%1,%2,%3},{%4,%5,%6,%7},{%8,%9},{%0,%1,%2,%3};"
        : "+f"(d[0]), "+f"(d[1]), "+f"(d[2]), "+f"(d[3])
        : "r"(a[0]), "r"(a[1]), "r"(a[2]), "r"(a[3]), "r"(b[0]), "r"(b[1]));
}
// cp.async 16B with zero-fill predicate
__device__ __forceinline__ void cpa16(__nv_bfloat16* s, const void* g, bool v) {
    unsigned sa = (unsigned)__cvta_generic_to_shared(s);
    int sz = v ? 16 : 0;
    asm volatile("cp.async.cg.shared.global [%0], [%1], 16, %2;" :: "r"(sa), "l"(g), "r"(sz));
}
__device__ __forceinline__ void cpa_commit() { asm volatile("cp.async.commit_group;"); }
template <int N> __device__ __forceinline__ void cpa_wait() {
    asm volatile("cp.async.wait_group %0;" :: "n"(N));
}

// ---------------- LayerNorm (fp32 in -> bf16 out) ----------------
__global__ void ln_kernel(const float* __restrict__ x, const float* __restrict__ g,
                          const float* __restrict__ b, __nv_bfloat16* __restrict__ out)
{
    int row  = blockIdx.x * 8 + (threadIdx.x >> 5);
    int lane = threadIdx.x & 31;
    const float* xr = x + (size_t)row * CCH;
    float v0 = xr[lane], v1 = xr[lane + 32], v2 = xr[lane + 64];
    float s = v0 + v1 + v2;
    #pragma unroll
    for (int o = 16; o; o >>= 1) s += __shfl_xor_sync(0xffffffffu, s, o);
    float mu = s * (1.0f / 96.0f);
    float d0 = v0 - mu, d1 = v1 - mu, d2 = v2 - mu;
    float q = d0 * d0 + d1 * d1 + d2 * d2;
    #pragma unroll
    for (int o = 16; o; o >>= 1) q += __shfl_xor_sync(0xffffffffu, q, o);
    float inv = rsqrtf(q * (1.0f / 96.0f) + 1e-5f);
    __nv_bfloat16* orow = out + (size_t)row * CCH;
    orow[lane]      = __float2bfloat16(d0 * inv * g[lane]      + b[lane]);
    orow[lane + 32] = __float2bfloat16(d1 * inv * g[lane + 32] + b[lane + 32]);
    orow[lane + 64] = __float2bfloat16(d2 * inv * g[lane + 64] + b[lane + 64]);
}

// ---------------- fused setup ----------------
__global__ void setup_kernel(
    const float* __restrict__ qkv_w, const float* __restrict__ proj_w,
    const float* __restrict__ fc1_w, const float* __restrict__ fc2_w,
    const float* __restrict__ conv1_w, const float* __restrict__ conv2_w,
    const int* __restrict__ rpi, const float* __restrict__ rpbt,
    __nv_bfloat16* __restrict__ qw, __nv_bfloat16* __restrict__ pw,
    __nv_bfloat16* __restrict__ f1w, __nv_bfloat16* __restrict__ f2w,
    __nv_bfloat16* __restrict__ w1r, __nv_bfloat16* __restrict__ w2r,
    __nv_bfloat16* __restrict__ biasb)
{
    int b = blockIdx.x, tx = threadIdx.x;
    if (b < 108) {
        int i = b * 256 + tx;
        if (i < 288 * 96) qw[i] = __float2bfloat16(qkv_w[i]);
    } else if (b < 144) {
        int i = (b - 108) * 256 + tx;
        if (i < 96 * 96) pw[i] = __float2bfloat16(proj_w[i]);
    } else if (b < 288) {
        int i = (b - 144) * 256 + tx;
        if (i < 384 * 96) f1w[i] = __float2bfloat16(fc1_w[i]);
    } else if (b < 432) {
        int i = (b - 288) * 256 + tx;
        if (i < 96 * 384) f2w[i] = __float2bfloat16(fc2_w[i]);
    } else if (b < 756) {
        int tid = (b - 432) * 256 + tx;
        if (tid < CMP * CCH * 27) {
            int o = tid / (CCH * 27);
            int rem = tid - o * (CCH * 27);
            int c = rem / 27;
            int tap = rem - c * 27;
            w1r[(tap * CMP + o) * CCH + c] = __float2bfloat16(conv1_w[tid]);
        }
    } else if (b < 1080) {
        int tid = (b - 756) * 256 + tx;
        if (tid < CCH * CMP * 27) {
            int o = tid / (CMP * 27);
            int rem = tid - o * (CMP * 27);
            int i = rem / 27;
            int tap = rem - i * 27;
            w2r[(tap * CCH + o) * CMP + i] = __float2bfloat16(conv2_w[tid]);
        }
    } else {
        int tid = (b - 1080) * 256 + tx;
        int h = tid >> 18;
        int r = tid & 262143;
        biasb[tid] = __float2bfloat16(rpbt[rpi[r] * HEADS + h]);
    }
}

// ---------------- conv1: 96->32 + GELU, cp.async 3-stage pipeline ----------------
#define C1_SE (162 * 104)      // elements per stage (66 in rows + 96 w rows)
__global__ __launch_bounds__(256) void conv1_kernel(
    const __nv_bfloat16* __restrict__ xn, const __nv_bfloat16* __restrict__ w1r,
    const float* __restrict__ b1, __nv_bfloat16* __restrict__ y1)
{
    extern __shared__ __nv_bfloat16 smb[];
    int d = blockIdx.x >> 6, h = blockIdx.x & 63;
    int tx = threadIdx.x;
    int warp = tx >> 5, lane = tx & 31;
    int gid = lane >> 2, tig = lane & 3;
    int wm = warp >> 1, wn = warp & 1;
    float acc[2][4] = {};

    auto load_phase = [&](int p, int buf) {
        int kd = p / 3, kh = p - kd * 3;
        int dd = d + kd - 1, hh = h + kh - 1;
        bool rowv = ((unsigned)dd < 8u) && ((unsigned)hh < 64u);
        __nv_bfloat16* in_s = smb + buf * C1_SE;
        __nv_bfloat16* w_s  = in_s + 66 * 104;
        const __nv_bfloat16* src_row = xn + ((size_t)(dd * HH + hh) * WW) * CCH;
        for (int idx = tx; idx < 792; idx += 256) {
            int r = idx / 12, c = idx - r * 12;
            int wv = r - 1;
            bool v = rowv && (unsigned)wv < 64u;
            const void* g = v ? (const void*)(src_row + wv * CCH + c * 8) : (const void*)xn;
            cpa16(in_s + r * 104 + c * 8, g, v);
        }
        const __nv_bfloat16* wsrc = w1r + (size_t)p * 3 * (CMP * CCH);
        for (int idx = tx; idx < 1152; idx += 256) {
            int r = idx / 12, c = idx - r * 12;
            cpa16(w_s + r * 104 + c * 8, wsrc + idx * 8, true);
        }
        cpa_commit();
    };

    load_phase(0, 0);
    for (int p = 0; p < 9; p++) {
        if (p < 8) { load_phase(p + 1, (p + 1) % 3); cpa_wait<1>(); }
        else cpa_wait<0>();
        __syncthreads();
        __nv_bfloat16* in_s = smb + (p % 3) * C1_SE;
        __nv_bfloat16* w_s  = in_s + 66 * 104;
        unsigned in_u = (unsigned)__cvta_generic_to_shared(in_s);
        #pragma unroll
        for (int kw = 0; kw < 3; kw++) {
            #pragma unroll
            for (int ks = 0; ks < 6; ks++) {
                unsigned af[4];
                ldsm4(af, in_u + 2u * ((wm * 16 + kw + (lane & 15)) * 104
                                       + ks * 16 + ((lane >> 4) << 3)));
                unsigned bf[4];
                ldsmB(bf, w_s + (kw * 32 + wn * 16) * 104 + ks * 16, 104, lane);
                mma16(acc[0], af, bf);
                mma16(acc[1], af, bf + 2);
            }
        }
    }
    __nv_bfloat16* orow = y1 + (size_t)(d * HH + h) * WW * CMP;
    #pragma unroll
    for (int nt = 0; nt < 2; nt++) {
        int oc = wn * 16 + nt * 8 + tig * 2;
        float bb0 = b1[oc], bb1 = b1[oc + 1];
        #pragma unroll
        for (int half = 0; half < 2; half++) {
            int v = wm * 16 + gid + half * 8;
            *(unsigned*)(orow + v * CMP + oc) =
                pack2(gelu_exact(acc[nt][half * 2 + 0] + bb0),
                      gelu_exact(acc[nt][half * 2 + 1] + bb1));
        }
    }
}

// ---------------- conv2: 32->96, cp.async 3-stage + fused pool partials ----------------
#define C2_SE (354 * 40)       // 66 in rows + 288 w rows
__global__ __launch_bounds__(256) void conv2_kernel(
    const __nv_bfloat16* __restrict__ y1, const __nv_bfloat16* __restrict__ w2r,
    const float* __restrict__ b2, float* __restrict__ y2, float* __restrict__ part)
{
    extern __shared__ __nv_bfloat16 smb[];
    int d = blockIdx.x >> 6, h = blockIdx.x & 63;
    int tx = threadIdx.x;
    int warp = tx >> 5, lane = tx & 31;
    int gid = lane >> 2, tig = lane & 3;
    int wm = warp >> 1, wn = warp & 1;
    float acc[6][4] = {};

    auto load_phase = [&](int p, int buf) {
        int kd = p / 3, kh = p - kd * 3;
        int dd = d + kd - 1, hh = h + kh - 1;
        bool rowv = ((unsigned)dd < 8u) && ((unsigned)hh < 64u);
        __nv_bfloat16* in_s = smb + buf * C2_SE;
        __nv_bfloat16* w_s  = in_s + 66 * 40;
        const __nv_bfloat16* src_row = y1 + ((size_t)(dd * HH + hh) * WW) * CMP;
        for (int idx = tx; idx < 264; idx += 256) {
            int r = idx >> 2, c = idx & 3;
            int wv = r - 1;
            bool v = rowv && (unsigned)wv < 64u;
            const void* g = v ? (const void*)(src_row + wv * CMP + c * 8) : (const void*)y1;
            cpa16(in_s + r * 40 + c * 8, g, v);
        }
        const __nv_bfloat16* wsrc = w2r + (size_t)p * 3 * (CCH * CMP);
        for (int idx = tx; idx < 1152; idx += 256) {
            int r = idx >> 2, c = idx & 3;
            cpa16(w_s + r * 40 + c * 8, wsrc + idx * 8, true);
        }
        cpa_commit();
    };

    load_phase(0, 0);
    for (int p = 0; p < 9; p++) {
        if (p < 8) { load_phase(p + 1, (p + 1) % 3); cpa_wait<1>(); }
        else cpa_wait<0>();
        __syncthreads();
        __nv_bfloat16* in_s = smb + (p % 3) * C2_SE;
        __nv_bfloat16* w_s  = in_s + 66 * 40;
        unsigned in_u = (unsigned)__cvta_generic_to_shared(in_s);
        #pragma unroll
        for (int kw = 0; kw < 3; kw++) {
            #pragma unroll
            for (int ks = 0; ks < 2; ks++) {
                unsigned af[4];
                ldsm4(af, in_u + 2u * ((wm * 16 + kw + (lane & 15)) * 40
                                       + ks * 16 + ((lane >> 4) << 3)));
                #pragma unroll
                for (int np = 0; np < 3; np++) {
                    unsigned bf[4];
                    ldsmB(bf, w_s + (kw * 96 + wn * 48 + np * 16) * 40 + ks * 16, 40, lane);
                    mma16(acc[np * 2], af, bf);
                    mma16(acc[np * 2 + 1], af, bf + 2);
                }
            }
        }
    }
    float* orow = y2 + (size_t)(d * HH + h) * WW * CCH;
    float ch0[6], ch1[6];
    #pragma unroll
    for (int nt = 0; nt < 6; nt++) {
        int oc = wn * 48 + nt * 8 + tig * 2;
        float bb0 = b2[oc], bb1 = b2[oc + 1];
        #pragma unroll
        for (int half = 0; half < 2; half++) {
            int v = wm * 16 + gid + half * 8;
            float2 o2;
            o2.x = acc[nt][half * 2 + 0] + bb0;
            o2.y = acc[nt][half * 2 + 1] + bb1;
            *(float2*)(orow + v * CCH + oc) = o2;
        }
        ch0[nt] = acc[nt][0] + acc[nt][2] + 2.0f * bb0;
        ch1[nt] = acc[nt][1] + acc[nt][3] + 2.0f * bb1;
    }
    // reduce over gid within warp (lanes sharing tig)
    #pragma unroll
    for (int nt = 0; nt < 6; nt++) {
        #pragma unroll
        for (int m = 4; m < 32; m <<= 1) {
            ch0[nt] += __shfl_xor_sync(0xffffffffu, ch0[nt], m);
            ch1[nt] += __shfl_xor_sync(0xffffffffu, ch1[nt], m);
        }
    }
    float* ws = (float*)smb;    // aliases stage 0 (free by now)
    if (gid == 0) {
        #pragma unroll
        for (int nt = 0; nt < 6; nt++) {
            int oc = wn * 48 + nt * 8 + tig * 2;
            ws[warp * 96 + oc] = ch0[nt];
            ws[warp * 96 + oc + 1] = ch1[nt];
        }
    }
    __syncthreads();
    if (tx < 96) {
        int wn2 = tx / 48;
        float s = ws[wn2 * 96 + tx] + ws[(wn2 + 2) * 96 + tx]
                + ws[(wn2 + 4) * 96 + tx] + ws[(wn2 + 6) * 96 + tx];
        part[blockIdx.x * 96 + tx] = s;
    }
}

// ---------------- channel attention (pool finalize) ----------------
__global__ void ca_kernel(const float* __restrict__ part,
                          const float* __restrict__ ca1w, const float* __restrict__ ca1b,
                          const float* __restrict__ ca2w, const float* __restrict__ ca2b,
                          float* __restrict__ att)
{
    __shared__ float p[CCH], hs[3];
    int tx = threadIdx.x;
    float s = 0.f;
    for (int b = 0; b < 512; b++) s += part[b * CCH + tx];
    p[tx] = s * (1.0f / (float)LTOK);
    __syncthreads();
    if (tx < 3) {
        float a = ca1b[tx];
        for (int c = 0; c < CCH; c++) a += ca1w[tx * CCH + c] * p[c];
        hs[tx] = fmaxf(a, 0.f);
    }
    __syncthreads();
    float a = ca2b[tx];
    #pragma unroll
    for (int k = 0; k < 3; k++) a += ca2w[tx * 3 + k] * hs[k];
    att[tx] = 1.0f / (1.0f + expf(-a));
}

// ---------------- bf16 GEMM (EPI: 0 bf16, 1 gelu->bf16, 3 fp32 res1+v) ----------------
// MTILES: rows/64 per block. KCH: compile-time K chunks (pipelined if >1).
template <int EPI, int MTILES, int KCH>
__global__ __launch_bounds__(256) void gemm_bf16(
    const __nv_bfloat16* __restrict__ A, const __nv_bfloat16* __restrict__ Wt,
    const float* __restrict__ bias, void* __restrict__ Cout, int Nn,
    const float* __restrict__ res1)
{
    const int MROWS = MTILES * 64;
    const int Ktot = KCH * 96;
    const int SE = (MROWS + 96) * 104;
    extern __shared__ __nv_bfloat16 smb[];
    int m0 = blockIdx.x * MROWS, n0 = blockIdx.y * 96;
    int tx = threadIdx.x;
    int warp = tx >> 5, lane = tx & 31;
    int wm = warp >> 1, wn = warp & 1;
    int gid = lane >> 2, tig = lane & 3;
    float acc[MTILES][6][4] = {};

    if (KCH == 1) {
        for (int idx = tx; idx < MROWS * 12; idx += 256) {
            int r = idx / 12, c = idx - r * 12;
            *(uint4*)(smb + r * 104 + c * 8) = *(const uint4*)(A + (size_t)(m0 + r) * Ktot + c * 8);
        }
        for (int idx = tx; idx < 1152; idx += 256) {
            int r = idx / 12, c = idx - r * 12;
            *(uint4*)(smb + (MROWS + r) * 104 + c * 8) = *(const uint4*)(Wt + (size_t)(n0 + r) * Ktot + c * 8);
        }
        __syncthreads();
    } else {
        // prologue chunk 0
        for (int idx = tx; idx < MROWS * 12; idx += 256) {
            int r = idx / 12, c = idx - r * 12;
            cpa16(smb + r * 104 + c * 8, A + (size_t)(m0 + r) * Ktot + c * 8, true);
        }
        for (int idx = tx; idx < 1152; idx += 256) {
            int r = idx / 12, c = idx - r * 12;
            cpa16(smb + (MROWS + r) * 104 + c * 8, Wt + (size_t)(n0 + r) * Ktot + c * 8, true);
        }
        cpa_commit();
    }

    for (int kc = 0; kc < KCH; kc++) {
        if (KCH > 1) {
            if (kc + 1 < KCH) {
                int k0 = (kc + 1) * 96;
                __nv_bfloat16* st = smb + ((kc + 1) % 3) * SE;
                for (int idx = tx; idx < MROWS * 12; idx += 256) {
                    int r = idx / 12, c = idx - r * 12;
                    cpa16(st + r * 104 + c * 8, A + (size_t)(m0 + r) * Ktot + k0 + c * 8, true);
                }
                for (int idx = tx; idx < 1152; idx += 256) {
                    int r = idx / 12, c = idx - r * 12;
                    cpa16(st + (MROWS + r) * 104 + c * 8, Wt + (size_t)(n0 + r) * Ktot + k0 + c * 8, true);
                }
                cpa_commit();
                cpa_wait<1>();
            } else {
                cpa_wait<0>();
            }
            __syncthreads();
        }
        __nv_bfloat16* a_s = smb + (KCH > 1 ? (kc % 3) * SE : 0);
        __nv_bfloat16* w_s = a_s + MROWS * 104;
        unsigned a_u = (unsigned)__cvta_generic_to_shared(a_s);
        #pragma unroll
        for (int ks = 0; ks < 6; ks++) {
            unsigned af[MTILES][4];
            #pragma unroll
            for (int mt = 0; mt < MTILES; mt++)
                ldsm4(af[mt], a_u + 2u * ((wm * (MTILES * 16) + mt * 16 + (lane & 15)) * 104
                                          + ks * 16 + ((lane >> 4) << 3)));
            #pragma unroll
            for (int np = 0; np < 3; np++) {
                unsigned bf[4];
                ldsmB(bf, w_s + (wn * 48 + np * 16) * 104 + ks * 16, 104, lane);
                #pragma unroll
                for (int mt = 0; mt < MTILES; mt++) {
                    mma16(acc[mt][np * 2], af[mt], bf);
                    mma16(acc[mt][np * 2 + 1], af[mt], bf + 2);
                }
            }
        }
    }
    #pragma unroll
    for (int mt = 0; mt < MTILES; mt++) {
        #pragma unroll
        for (int nt = 0; nt < 6; nt++) {
            int cc = n0 + wn * 48 + nt * 8 + tig * 2;
            float bb0 = bias[cc], bb1 = bias[cc + 1];
            #pragma unroll
            for (int half = 0; half < 2; half++) {
                int r = m0 + wm * (MTILES * 16) + mt * 16 + gid + half * 8;
                size_t idx = (size_t)r * Nn + cc;
                float v0 = acc[mt][nt][half * 2 + 0] + bb0;
                float v1 = acc[mt][nt][half * 2 + 1] + bb1;
                if (EPI == 0) {
                    *(unsigned*)((__nv_bfloat16*)Cout + idx) = pack2(v0, v1);
                } else if (EPI == 1) {
                    *(unsigned*)((__nv_bfloat16*)Cout + idx) = pack2(gelu_exact(v0), gelu_exact(v1));
                } else {
                    float2 r1 = *(const float2*)(res1 + idx);
                    float2 o2;
                    o2.x = r1.x + v0;
                    o2.y = r1.y + v1;
                    *(float2*)((float*)Cout + idx) = o2;
                }
            }
        }
    }
}

// ---------------- proj GEMM + residual merge + fused LayerNorm2 ----------------
__global__ __launch_bounds__(256) void gemm_proj_ln(
    const __nv_bfloat16* __restrict__ A, const __nv_bfloat16* __restrict__ Wt,
    const float* __restrict__ bias,
    const float* __restrict__ res1, const float* __restrict__ res2,
    const float* __restrict__ att,
    const float* __restrict__ n2g, const float* __restrict__ n2b,
    float* __restrict__ x1, __nv_bfloat16* __restrict__ xn2)
{
    extern __shared__ __nv_bfloat16 smb[];
    __nv_bfloat16* a_s = smb;
    __nv_bfloat16* w_s = smb + 128 * 104;
    float* red_s = (float*)smb;
    float* red_q = red_s + 256;
    unsigned a_u = (unsigned)__cvta_generic_to_shared(a_s);
    int m0 = blockIdx.x * 128;
    int tx = threadIdx.x;
    int warp = tx >> 5, lane = tx & 31;
    int wm = warp >> 1, wn = warp & 1;
    int gid = lane >> 2, tig = lane & 3;
    float acc[2][6][4] = {};
    {
        for (int idx = tx; idx < 1536; idx += 256) {
            int r = idx / 12, c = idx - r * 12;
            *(uint4*)(a_s + r * 104 + c * 8) = *(const uint4*)(A + (size_t)(m0 + r) * 96 + c * 8);
        }
        for (int idx = tx; idx < 1152; idx += 256) {
            int r = idx / 12, c = idx - r * 12;
            *(uint4*)(w_s + r * 104 + c * 8) = *(const uint4*)(Wt + (size_t)r * 96 + c * 8);
        }
        __syncthreads();
        #pragma unroll
        for (int ks = 0; ks < 6; ks++) {
            unsigned af[2][4];
            #pragma unroll
            for (int mt = 0; mt < 2; mt++)
                ldsm4(af[mt], a_u + 2u * ((wm * 32 + mt * 16 + (lane & 15)) * 104
                                          + ks * 16 + ((lane >> 4) << 3)));
            #pragma unroll
            for (int np = 0; np < 3; np++) {
                unsigned bf[4];
                ldsmB(bf, w_s + (wn * 48 + np * 16) * 104 + ks * 16, 104, lane);
                #pragma unroll
                for (int mt = 0; mt < 2; mt++) {
                    mma16(acc[mt][np * 2], af[mt], bf);
                    mma16(acc[mt][np * 2 + 1], af[mt], bf + 2);
                }
            }
        }
    }
    __syncthreads();

    float rs[2][2] = {}, rq[2][2] = {};
    #pragma unroll
    for (int mt = 0; mt < 2; mt++) {
        #pragma unroll
        for (int nt = 0; nt < 6; nt++) {
            int cc = wn * 48 + nt * 8 + tig * 2;
            float bb0 = bias[cc], bb1 = bias[cc + 1];
            float a0 = att[cc] * 0.01f, a1 = att[cc + 1] * 0.01f;
            #pragma unroll
            for (int half = 0; half < 2; half++) {
                int r = m0 + wm * 32 + mt * 16 + gid + half * 8;
                size_t idx = (size_t)r * 96 + cc;
                float2 r1 = *(const float2*)(res1 + idx);
                float2 r2 = *(const float2*)(res2 + idx);
                float v0 = r1.x + acc[mt][nt][half * 2 + 0] + bb0 + r2.x * a0;
                float v1 = r1.y + acc[mt][nt][half * 2 + 1] + bb1 + r2.y * a1;
                acc[mt][nt][half * 2 + 0] = v0;
                acc[mt][nt][half * 2 + 1] = v1;
                *(float2*)(x1 + idx) = make_float2(v0, v1);
                rs[mt][half] += v0 + v1;
                rq[mt][half] += v0 * v0 + v1 * v1;
            }
        }
    }
    #pragma unroll
    for (int mt = 0; mt < 2; mt++)
        #pragma unroll
        for (int half = 0; half < 2; half++) {
            float s = rs[mt][half], q = rq[mt][half];
            s += __shfl_xor_sync(0xffffffffu, s, 1);
            s += __shfl_xor_sync(0xffffffffu, s, 2);
            q += __shfl_xor_sync(0xffffffffu, q, 1);
            q += __shfl_xor_sync(0xffffffffu, q, 2);
            if (tig == 0) {
                int lr = wm * 32 + mt * 16 + half * 8 + gid;
                red_s[lr * 2 + wn] = s;
                red_q[lr * 2 + wn] = q;
            }
        }
    __syncthreads();
    #pragma unroll
    for (int mt = 0; mt < 2; mt++) {
        #pragma unroll
        for (int half = 0; half < 2; half++) {
            int lr = wm * 32 + mt * 16 + half * 8 + gid;
            float sum = red_s[lr * 2] + red_s[lr * 2 + 1];
            float sq  = red_q[lr * 2] + red_q[lr * 2 + 1];
            float mean = sum * (1.0f / 96.0f);
            float var = sq * (1.0f / 96.0f) - mean * mean;
            float inv = rsqrtf(var + 1e-5f);
            int r = m0 + lr;
            #pragma unroll
            for (int nt = 0; nt < 6; nt++) {
                int cc = wn * 48 + nt * 8 + tig * 2;
                float g0 = n2g[cc], g1 = n2g[cc + 1];
                float b0 = n2b[cc], b1 = n2b[cc + 1];
                float v0 = (acc[mt][nt][half * 2 + 0] - mean) * inv * g0 + b0;
                float v1 = (acc[mt][nt][half * 2 + 1] - mean) * inv * g1 + b1;
                *(unsigned*)(xn2 + (size_t)r * 96 + cc) = pack2(v0, v1);
            }
        }
    }
}

// ---------------- attention ----------------
#define OFF_Q  0
#define OFF_K  3072
#define OFF_V  27648
#define OFF_R1 44288
#define OFF_R2 45312
#define OFF_OR 46336
#define SMEM_ATTN 62720

__device__ __forceinline__ int wtok(int j, int base) {
    return ((j >> 6) << 12) + base + (((j >> 3) & 7) << 6) + (j & 7);
}

__global__ __launch_bounds__(512) void attn_kernel(
    const __nv_bfloat16* __restrict__ qkv, const __nv_bfloat16* __restrict__ biasb,
    __nv_bfloat16* __restrict__ o)
{
    extern __shared__ char smc[];
    __nv_bfloat16* q_s = (__nv_bfloat16*)(smc + OFF_Q);
    __nv_bfloat16* k_s = (__nv_bfloat16*)(smc + OFF_K);
    __nv_bfloat16* v_t = (__nv_bfloat16*)(smc + OFF_V);
    float* red1 = (float*)(smc + OFF_R1);
    float* red2 = (float*)(smc + OFF_R2);
    float* o_red = (float*)(smc + OFF_OR);
    unsigned q_u = (unsigned)__cvta_generic_to_shared(q_s);

    int blk = blockIdx.x;
    int qc = blk & 7;
    int head = (blk >> 3) % 6;
    int win = blk / 48;
    int base = (win >> 3) * 512 + (win & 7) * 8;
    int m0 = qc * 64;
    int tx = threadIdx.x;
    int warp = tx >> 5, lane = tx & 31;
    int gid = lane >> 2, tig = lane & 3;
    int wm = warp >> 2, wn = warp & 3;
    int r0 = wm * 16, j0 = wn * 128;

    for (int idx = tx; idx < 1024; idx += 512) {
        int j = idx >> 1, half = idx & 1;
        int t = wtok(j, base);
        const __nv_bfloat16* p = qkv + (size_t)t * 288 + head * 16 + half * 8;
        *(uint4*)(k_s + j * 24 + half * 8) = *(const uint4*)(p + 96);
        uint4 v4 = *(const uint4*)(p + 192);
        const __nv_bfloat16* vp = (const __nv_bfloat16*)&v4;
        #pragma unroll
        for (int dd2 = 0; dd2 < 8; dd2++)
            v_t[(half * 8 + dd2) * 520 + j] = vp[dd2];
    }
    if (tx < 128) {
        int i = tx >> 1, half = tx & 1;
        int t = wtok(m0 + i, base);
        uint4 raw = *(const uint4*)(qkv + (size_t)t * 288 + head * 16 + half * 8);
        const __nv_bfloat16* rp = (const __nv_bfloat16*)&raw;
        unsigned pk[4];
        #pragma unroll
        for (int e = 0; e < 4; e++)
            pk[e] = pack2(__bfloat162float(rp[e * 2]) * 0.25f,
                          __bfloat162float(rp[e * 2 + 1]) * 0.25f);
        *(uint4*)(q_s + i * 24 + half * 8) = *(uint4*)pk;
    }
    __syncthreads();

    float acc[16][4] = {};
    {
        unsigned aq[4];
        ldsm4(aq, q_u + 2u * ((r0 + (lane & 15)) * 24 + ((lane >> 4) << 3)));
        #pragma unroll
        for (int np = 0; np < 8; np++) {
            unsigned bf[4];
            ldsmB(bf, k_s + (j0 + np * 16) * 24, 24, lane);
            mma16(acc[np * 2], aq, bf);
            mma16(acc[np * 2 + 1], aq, bf + 2);
        }
        const __nv_bfloat16* bbA = biasb + ((size_t)head * 512 + (m0 + r0 + gid)) * 512 + j0 + tig * 2;
        const __nv_bfloat16* bbB = bbA + 8 * 512;
        #pragma unroll
        for (int nt = 0; nt < 16; nt++) {
            float2 fa = __bfloat1622float2(*(const __nv_bfloat162*)(bbA + nt * 8));
            float2 fb = __bfloat1622float2(*(const __nv_bfloat162*)(bbB + nt * 8));
            acc[nt][0] += fa.x; acc[nt][1] += fa.y;
            acc[nt][2] += fb.x; acc[nt][3] += fb.y;
        }
    }
    {
        float mA = -1e30f, mB = -1e30f;
        #pragma unroll
        for (int nt = 0; nt < 16; nt++) {
            mA = fmaxf(mA, fmaxf(acc[nt][0], acc[nt][1]));
            mB = fmaxf(mB, fmaxf(acc[nt][2], acc[nt][3]));
        }
        mA = fmaxf(mA, __shfl_xor_sync(0xffffffffu, mA, 1));
        mA = fmaxf(mA, __shfl_xor_sync(0xffffffffu, mA, 2));
        mB = fmaxf(mB, __shfl_xor_sync(0xffffffffu, mB, 1));
        mB = fmaxf(mB, __shfl_xor_sync(0xffffffffu, mB, 2));
        if (tig == 0) {
            red1[(r0 + gid) * 4 + wn] = mA;
            red1[(r0 + gid + 8) * 4 + wn] = mB;
        }
        __syncthreads();
        mA = fmaxf(fmaxf(red1[(r0 + gid) * 4 + 0], red1[(r0 + gid) * 4 + 1]),
                   fmaxf(red1[(r0 + gid) * 4 + 2], red1[(r0 + gid) * 4 + 3]));
        mB = fmaxf(fmaxf(red1[(r0 + gid + 8) * 4 + 0], red1[(r0 + gid + 8) * 4 + 1]),
                   fmaxf(red1[(r0 + gid + 8) * 4 + 2], red1[(r0 + gid + 8) * 4 + 3]));
        float sA = 0.f, sB = 0.f;
        #pragma unroll
        for (int nt = 0; nt < 16; nt++) {
            acc[nt][0] = __expf(acc[nt][0] - mA);
            acc[nt][1] = __expf(acc[nt][1] - mA);
            acc[nt][2] = __expf(acc[nt][2] - mB);
            acc[nt][3] = __expf(acc[nt][3] - mB);
            sA += acc[nt][0] + acc[nt][1];
            sB += acc[nt][2] + acc[nt][3];
        }
        sA += __shfl_xor_sync(0xffffffffu, sA, 1);
        sA += __shfl_xor_sync(0xffffffffu, sA, 2);
        sB += __shfl_xor_sync(0xffffffffu, sB, 1);
        sB += __shfl_xor_sync(0xffffffffu, sB, 2);
        if (tig == 0) {
            red2[(r0 + gid) * 4 + wn] = sA;
            red2[(r0 + gid + 8) * 4 + wn] = sB;
        }
        __syncthreads();
        sA = red2[(r0 + gid) * 4 + 0] + red2[(r0 + gid) * 4 + 1]
           + red2[(r0 + gid) * 4 + 2] + red2[(r0 + gid) * 4 + 3];
        sB = red2[(r0 + gid + 8) * 4 + 0] + red2[(r0 + gid + 8) * 4 + 1]
           + red2[(r0 + gid + 8) * 4 + 2] + red2[(r0 + gid + 8) * 4 + 3];
        float iA = 1.0f / sA, iB = 1.0f / sB;
        #pragma unroll
        for (int nt = 0; nt < 16; nt++) {
            acc[nt][0] *= iA; acc[nt][1] *= iA;
            acc[nt][2] *= iB; acc[nt][3] *= iB;
        }
    }

    float oa[2][4] = {};
    #pragma unroll
    for (int kk = 0; kk < 8; kk++) {
        unsigned af[4];
        af[0] = pack2(acc[2 * kk][0],     acc[2 * kk][1]);
        af[1] = pack2(acc[2 * kk][2],     acc[2 * kk][3]);
        af[2] = pack2(acc[2 * kk + 1][0], acc[2 * kk + 1][1]);
        af[3] = pack2(acc[2 * kk + 1][2], acc[2 * kk + 1][3]);
        unsigned bf[4];
        ldsmB(bf, v_t + j0 + kk * 16, 520, lane);
        mma16(oa[0], af, bf);
        mma16(oa[1], af, bf + 2);
    }
    {
        float* orp = o_red + (size_t)wn * 1024;
        #pragma unroll
        for (int dt = 0; dt < 2; dt++) {
            int dc = dt * 8 + tig * 2;
            *(float2*)(orp + (r0 + gid) * 16 + dc)     = make_float2(oa[dt][0], oa[dt][1]);
            *(float2*)(orp + (r0 + gid + 8) * 16 + dc) = make_float2(oa[dt][2], oa[dt][3]);
        }
    }
    __syncthreads();
    {
        int row = tx >> 3, d2 = tx & 7;
        int dim = d2 * 2;
        float v0 = 0.f, v1 = 0.f;
        #pragma unroll
        for (int p = 0; p < 4; p++) {
            v0 += o_red[p * 1024 + row * 16 + dim];
            v1 += o_red[p * 1024 + row * 16 + dim + 1];
        }
        int t = wtok(m0 + row, base);
        *(unsigned*)(o + (size_t)t * CCH + head * 16 + dim) = pack2(v0, v1);
    }
}

// ---------------- launch ----------------
extern "C" void kernel_launch(void* const* d_in, const int* in_sizes, int n_in,
                              void* d_out, int out_size)
{
    (void)in_sizes; (void)n_in; (void)out_size;
    const float* x       = (const float*)d_in[0];
    const float* n1g     = (const float*)d_in[1];
    const float* n1b     = (const float*)d_in[2];
    const float* qkv_w   = (const float*)d_in[3];
    const float* qkv_b   = (const float*)d_in[4];
    const float* rpbt    = (const float*)d_in[5];
    const float* proj_w  = (const float*)d_in[6];
    const float* proj_b  = (const float*)d_in[7];
    const float* conv1_w = (const float*)d_in[8];
    const float* conv1_b = (const float*)d_in[9];
    const float* conv2_w = (const float*)d_in[10];
    const float* conv2_b = (const float*)d_in[11];
    const float* ca1_w   = (const float*)d_in[12];
    const float* ca1_b   = (const float*)d_in[13];
    const float* ca2_w   = (const float*)d_in[14];
    const float* ca2_b   = (const float*)d_in[15];
    const float* n2g     = (const float*)d_in[16];
    const float* n2b     = (const float*)d_in[17];
    const float* fc1_w   = (const float*)d_in[18];
    const float* fc1_b   = (const float*)d_in[19];
    const float* fc2_w   = (const float*)d_in[20];
    const float* fc2_b   = (const float*)d_in[21];
    const int*   rpi     = (const int*)d_in[22];
    float* out = (float*)d_out;

    __nv_bfloat16 *xn, *y1, *qkvb, *biasb, *ob, *xn2, *hb, *w1r, *w2r, *qw, *pw, *f1w, *f2w;
    float *y2, *part, *att, *x1;
    cudaGetSymbolAddress((void**)&xn,    g_xn);
    cudaGetSymbolAddress((void**)&y1,    g_y1);
    cudaGetSymbolAddress((void**)&y2,    g_y2);
    cudaGetSymbolAddress((void**)&part,  g_part);
    cudaGetSymbolAddress((void**)&att,   g_att);
    cudaGetSymbolAddress((void**)&qkvb,  g_qkv);
    cudaGetSymbolAddress((void**)&biasb, g_bias);
    cudaGetSymbolAddress((void**)&ob,    g_o);
    cudaGetSymbolAddress((void**)&x1,    g_x1);
    cudaGetSymbolAddress((void**)&xn2,   g_xn2);
    cudaGetSymbolAddress((void**)&hb,    g_h);
    cudaGetSymbolAddress((void**)&w1r,   g_w1r);
    cudaGetSymbolAddress((void**)&w2r,   g_w2r);
    cudaGetSymbolAddress((void**)&qw,    g_qw);
    cudaGetSymbolAddress((void**)&pw,    g_pw);
    cudaGetSymbolAddress((void**)&f1w,   g_f1w);
    cudaGetSymbolAddress((void**)&f2w,   g_f2w);

    const int SMEM_CONV1 = 3 * C1_SE * 2;                 // 101088
    const int SMEM_CONV2 = 3 * C2_SE * 2;                 // 84960
    const int SMEM_G128  = (128 + 96) * 104 * 2;          // 46592
    const int SMEM_G64P  = 3 * (64 + 96) * 104 * 2;       // 99840
    cudaFuncSetAttribute(conv1_kernel, cudaFuncAttributeMaxDynamicSharedMemorySize, SMEM_CONV1);
    cudaFuncSetAttribute(conv2_kernel, cudaFuncAttributeMaxDynamicSharedMemorySize, SMEM_CONV2);
    cudaFuncSetAttribute(gemm_bf16<0, 2, 1>, cudaFuncAttributeMaxDynamicSharedMemorySize, SMEM_G128);
    cudaFuncSetAttribute(gemm_bf16<1, 2, 1>, cudaFuncAttributeMaxDynamicSharedMemorySize, SMEM_G128);
    cudaFuncSetAttribute(gemm_bf16<3, 1, 4>, cudaFuncAttributeMaxDynamicSharedMemorySize, SMEM_G64P);
    cudaFuncSetAttribute(gemm_proj_ln, cudaFuncAttributeMaxDynamicSharedMemorySize, SMEM_G128);
    cudaFuncSetAttribute(attn_kernel, cudaFuncAttributeMaxDynamicSharedMemorySize, SMEM_ATTN);

    setup_kernel<<<7224, 256>>>(qkv_w, proj_w, fc1_w, fc2_w, conv1_w, conv2_w,
                                rpi, rpbt, qw, pw, f1w, f2w, w1r, w2r, biasb);

    ln_kernel<<<LTOK / 8, 256>>>(x, n1g, n1b, xn);

    conv1_kernel<<<512, 256, SMEM_CONV1>>>(xn, w1r, conv1_b, y1);
    conv2_kernel<<<512, 256, SMEM_CONV2>>>(y1, w2r, conv2_b, y2, part);
    ca_kernel<<<1, CCH>>>(part, ca1_w, ca1_b, ca2_w, ca2_b, att);

    gemm_bf16<0, 2, 1><<<dim3(LTOK / 128, 3), 256, SMEM_G128>>>(
        xn, qw, qkv_b, qkvb, 288, nullptr);
    attn_kernel<<<NWIN * HEADS * 8, 512, SMEM_ATTN>>>(qkvb, biasb, ob);

    gemm_proj_ln<<<LTOK / 128, 256, SMEM_G128>>>(
        ob, pw, proj_b, x, y2, att, n2g, n2b, x1, xn2);

    gemm_bf16<1, 2, 1><<<dim3(LTOK / 128, 4), 256, SMEM_G128>>>(
        xn2, f1w, fc1_b, hb, 384, nullptr);
    gemm_bf16<3, 1, 4><<<dim3(LTOK / 64, 1), 256, SMEM_G64P>>>(
        hb, f2w, fc2_b, out, 96, x1);
}

// round 7
// speedup vs baseline: 4.8977x; 1.0446x over previous
#include <cuda_runtime.h>
#include <cuda_bf16.h>
#include <math.h>
#include <stdint.h>

#define DD 8
#define HH 64
#define WW 64
#define LTOK 32768
#define CCH 96
#define CMP 32
#define HID 384
#define HEADS 6
#define HDIM 16
#define NWIN 64
#define NTOK 512

// ---------------- scratch ----------------
__device__ __nv_bfloat16 g_xn  [LTOK * CCH];
__device__ __nv_bfloat16 g_y1  [LTOK * CMP];
__device__ float         g_y2  [LTOK * CCH];
__device__ float         g_part[512 * CCH];
__device__ float         g_att [CCH];
__device__ __nv_bfloat16 g_qkv [LTOK * 3 * CCH];
__device__ __nv_bfloat16 g_bias[HEADS * NTOK * NTOK];
__device__ __nv_bfloat16 g_o   [LTOK * CCH];
__device__ float         g_x1  [LTOK * CCH];
__device__ __nv_bfloat16 g_xn2 [LTOK * CCH];
__device__ __nv_bfloat16 g_h   [LTOK * HID];
__device__ __nv_bfloat16 g_w1r [27 * CMP * CCH];
__device__ __nv_bfloat16 g_w2r [27 * CCH * CMP];
__device__ __nv_bfloat16 g_qw  [288 * 96];
__device__ __nv_bfloat16 g_pw  [96 * 96];
__device__ __nv_bfloat16 g_f1w [384 * 96];
__device__ __nv_bfloat16 g_f2w [96 * 384];

__device__ __forceinline__ float gelu_exact(float v) {
    return 0.5f * v * (1.0f + erff(v * 0.70710678118654752f));
}
__device__ __forceinline__ unsigned pack2(float a, float b) {
    __nv_bfloat162 t = __floats2bfloat162_rn(a, b);
    return *reinterpret_cast<unsigned*>(&t);
}
__device__ __forceinline__ void ldsm4(unsigned* r, unsigned addr) {
    asm volatile("ldmatrix.sync.aligned.m8n8.x4.shared.b16 {%0,%1,%2,%3},[%4];"
                 : "=r"(r[0]), "=r"(r[1]), "=r"(r[2]), "=r"(r[3]) : "r"(addr));
}
__device__ __forceinline__ void ldsmB(unsigned* r, const __nv_bfloat16* base, int S, int lane) {
    int tq = lane & 7, sel = lane >> 3;
    const __nv_bfloat16* p = base + ((sel & 2) * 4 + tq) * S + (sel & 1) * 8;
    ldsm4(r, (unsigned)__cvta_generic_to_shared(p));
}
__device__ __forceinline__ void mma16(float* d, const unsigned* a, const unsigned* b) {
    asm volatile(
        "mma.sync.aligned.m16n8k16.row.col.f32.bf16.bf16.f32 "
        "{%0,%1,%2,%3},{%4,%5,%6,%7},{%8,%9},{%0,%1,%2,%3};"
        : "+f"(d[0]), "+f"(d[1]), "+f"(d[2]), "+f"(d[3])
        : "r"(a[0]), "r"(a[1]), "r"(a[2]), "r"(a[3]), "r"(b[0]), "r"(b[1]));
}
__device__ __forceinline__ void cpa16(__nv_bfloat16* s, const void* g, bool v) {
    unsigned sa = (unsigned)__cvta_generic_to_shared(s);
    int sz = v ? 16 : 0;
    asm volatile("cp.async.cg.shared.global [%0], [%1], 16, %2;" :: "r"(sa), "l"(g), "r"(sz));
}
__device__ __forceinline__ void cpa_commit() { asm volatile("cp.async.commit_group;"); }
template <int N> __device__ __forceinline__ void cpa_wait() {
    asm volatile("cp.async.wait_group %0;" :: "n"(N));
}

// ---------------- LayerNorm ----------------
__global__ void ln_kernel(const float* __restrict__ x, const float* __restrict__ g,
                          const float* __restrict__ b, __nv_bfloat16* __restrict__ out)
{
    int row  = blockIdx.x * 8 + (threadIdx.x >> 5);
    int lane = threadIdx.x & 31;
    const float* xr = x + (size_t)row * CCH;
    float v0 = xr[lane], v1 = xr[lane + 32], v2 = xr[lane + 64];
    float s = v0 + v1 + v2;
    #pragma unroll
    for (int o = 16; o; o >>= 1) s += __shfl_xor_sync(0xffffffffu, s, o);
    float mu = s * (1.0f / 96.0f);
    float d0 = v0 - mu, d1 = v1 - mu, d2 = v2 - mu;
    float q = d0 * d0 + d1 * d1 + d2 * d2;
    #pragma unroll
    for (int o = 16; o; o >>= 1) q += __shfl_xor_sync(0xffffffffu, q, o);
    float inv = rsqrtf(q * (1.0f / 96.0f) + 1e-5f);
    __nv_bfloat16* orow = out + (size_t)row * CCH;
    orow[lane]      = __float2bfloat16(d0 * inv * g[lane]      + b[lane]);
    orow[lane + 32] = __float2bfloat16(d1 * inv * g[lane + 32] + b[lane + 32]);
    orow[lane + 64] = __float2bfloat16(d2 * inv * g[lane + 64] + b[lane + 64]);
}

// ---------------- fused setup ----------------
__global__ void setup_kernel(
    const float* __restrict__ qkv_w, const float* __restrict__ proj_w,
    const float* __restrict__ fc1_w, const float* __restrict__ fc2_w,
    const float* __restrict__ conv1_w, const float* __restrict__ conv2_w,
    const int* __restrict__ rpi, const float* __restrict__ rpbt,
    __nv_bfloat16* __restrict__ qw, __nv_bfloat16* __restrict__ pw,
    __nv_bfloat16* __restrict__ f1w, __nv_bfloat16* __restrict__ f2w,
    __nv_bfloat16* __restrict__ w1r, __nv_bfloat16* __restrict__ w2r,
    __nv_bfloat16* __restrict__ biasb)
{
    int b = blockIdx.x, tx = threadIdx.x;
    if (b < 108) {
        int i = b * 256 + tx;
        if (i < 288 * 96) qw[i] = __float2bfloat16(qkv_w[i]);
    } else if (b < 144) {
        int i = (b - 108) * 256 + tx;
        if (i < 96 * 96) pw[i] = __float2bfloat16(proj_w[i]);
    } else if (b < 288) {
        int i = (b - 144) * 256 + tx;
        if (i < 384 * 96) f1w[i] = __float2bfloat16(fc1_w[i]);
    } else if (b < 432) {
        int i = (b - 288) * 256 + tx;
        if (i < 96 * 384) f2w[i] = __float2bfloat16(fc2_w[i]);
    } else if (b < 756) {
        int tid = (b - 432) * 256 + tx;
        if (tid < CMP * CCH * 27) {
            int o = tid / (CCH * 27);
            int rem = tid - o * (CCH * 27);
            int c = rem / 27;
            int tap = rem - c * 27;
            w1r[(tap * CMP + o) * CCH + c] = __float2bfloat16(conv1_w[tid]);
        }
    } else if (b < 1080) {
        int tid = (b - 756) * 256 + tx;
        if (tid < CCH * CMP * 27) {
            int o = tid / (CMP * 27);
            int rem = tid - o * (CMP * 27);
            int i = rem / 27;
            int tap = rem - i * 27;
            w2r[(tap * CCH + o) * CMP + i] = __float2bfloat16(conv2_w[tid]);
        }
    } else {
        int tid = (b - 1080) * 256 + tx;
        int h = tid >> 18;
        int r = tid & 262143;
        biasb[tid] = __float2bfloat16(rpbt[rpi[r] * HEADS + h]);
    }
}

// ---------------- conv1: 96->32 + GELU, cp.async 3-stage pipeline ----------------
#define C1_SE (162 * 104)
__global__ __launch_bounds__(256) void conv1_kernel(
    const __nv_bfloat16* __restrict__ xn, const __nv_bfloat16* __restrict__ w1r,
    const float* __restrict__ b1, __nv_bfloat16* __restrict__ y1)
{
    extern __shared__ __nv_bfloat16 smb[];
    int d = blockIdx.x >> 6, h = blockIdx.x & 63;
    int tx = threadIdx.x;
    int warp = tx >> 5, lane = tx & 31;
    int gid = lane >> 2, tig = lane & 3;
    int wm = warp >> 1, wn = warp & 1;
    float acc[2][4] = {};

    auto load_phase = [&](int p, int buf) {
        int kd = p / 3, kh = p - kd * 3;
        int dd = d + kd - 1, hh = h + kh - 1;
        bool rowv = ((unsigned)dd < 8u) && ((unsigned)hh < 64u);
        __nv_bfloat16* in_s = smb + buf * C1_SE;
        __nv_bfloat16* w_s  = in_s + 66 * 104;
        const __nv_bfloat16* src_row = xn + ((size_t)(dd * HH + hh) * WW) * CCH;
        for (int idx = tx; idx < 792; idx += 256) {
            int r = idx / 12, c = idx - r * 12;
            int wv = r - 1;
            bool v = rowv && (unsigned)wv < 64u;
            const void* g = v ? (const void*)(src_row + wv * CCH + c * 8) : (const void*)xn;
            cpa16(in_s + r * 104 + c * 8, g, v);
        }
        const __nv_bfloat16* wsrc = w1r + (size_t)p * 3 * (CMP * CCH);
        for (int idx = tx; idx < 1152; idx += 256) {
            int r = idx / 12, c = idx - r * 12;
            cpa16(w_s + r * 104 + c * 8, wsrc + idx * 8, true);
        }
        cpa_commit();
    };

    load_phase(0, 0);
    for (int p = 0; p < 9; p++) {
        if (p < 8) { load_phase(p + 1, (p + 1) % 3); cpa_wait<1>(); }
        else cpa_wait<0>();
        __syncthreads();
        __nv_bfloat16* in_s = smb + (p % 3) * C1_SE;
        __nv_bfloat16* w_s  = in_s + 66 * 104;
        unsigned in_u = (unsigned)__cvta_generic_to_shared(in_s);
        #pragma unroll
        for (int kw = 0; kw < 3; kw++) {
            #pragma unroll
            for (int ks = 0; ks < 6; ks++) {
                unsigned af[4];
                ldsm4(af, in_u + 2u * ((wm * 16 + kw + (lane & 15)) * 104
                                       + ks * 16 + ((lane >> 4) << 3)));
                unsigned bf[4];
                ldsmB(bf, w_s + (kw * 32 + wn * 16) * 104 + ks * 16, 104, lane);
                mma16(acc[0], af, bf);
                mma16(acc[1], af, bf + 2);
            }
        }
    }
    __nv_bfloat16* orow = y1 + (size_t)(d * HH + h) * WW * CMP;
    #pragma unroll
    for (int nt = 0; nt < 2; nt++) {
        int oc = wn * 16 + nt * 8 + tig * 2;
        float bb0 = b1[oc], bb1 = b1[oc + 1];
        #pragma unroll
        for (int half = 0; half < 2; half++) {
            int v = wm * 16 + gid + half * 8;
            *(unsigned*)(orow + v * CMP + oc) =
                pack2(gelu_exact(acc[nt][half * 2 + 0] + bb0),
                      gelu_exact(acc[nt][half * 2 + 1] + bb1));
        }
    }
}

// ---------------- conv2: 32->96, cp.async 3-stage + fused pool partials ----------------
#define C2_SE (354 * 40)
__global__ __launch_bounds__(256) void conv2_kernel(
    const __nv_bfloat16* __restrict__ y1, const __nv_bfloat16* __restrict__ w2r,
    const float* __restrict__ b2, float* __restrict__ y2, float* __restrict__ part)
{
    extern __shared__ __nv_bfloat16 smb[];
    int d = blockIdx.x >> 6, h = blockIdx.x & 63;
    int tx = threadIdx.x;
    int warp = tx >> 5, lane = tx & 31;
    int gid = lane >> 2, tig = lane & 3;
    int wm = warp >> 1, wn = warp & 1;
    float acc[6][4] = {};

    auto load_phase = [&](int p, int buf) {
        int kd = p / 3, kh = p - kd * 3;
        int dd = d + kd - 1, hh = h + kh - 1;
        bool rowv = ((unsigned)dd < 8u) && ((unsigned)hh < 64u);
        __nv_bfloat16* in_s = smb + buf * C2_SE;
        __nv_bfloat16* w_s  = in_s + 66 * 40;
        const __nv_bfloat16* src_row = y1 + ((size_t)(dd * HH + hh) * WW) * CMP;
        for (int idx = tx; idx < 264; idx += 256) {
            int r = idx >> 2, c = idx & 3;
            int wv = r - 1;
            bool v = rowv && (unsigned)wv < 64u;
            const void* g = v ? (const void*)(src_row + wv * CMP + c * 8) : (const void*)y1;
            cpa16(in_s + r * 40 + c * 8, g, v);
        }
        const __nv_bfloat16* wsrc = w2r + (size_t)p * 3 * (CCH * CMP);
        for (int idx = tx; idx < 1152; idx += 256) {
            int r = idx >> 2, c = idx & 3;
            cpa16(w_s + r * 40 + c * 8, wsrc + idx * 8, true);
        }
        cpa_commit();
    };

    load_phase(0, 0);
    for (int p = 0; p < 9; p++) {
        if (p < 8) { load_phase(p + 1, (p + 1) % 3); cpa_wait<1>(); }
        else cpa_wait<0>();
        __syncthreads();
        __nv_bfloat16* in_s = smb + (p % 3) * C2_SE;
        __nv_bfloat16* w_s  = in_s + 66 * 40;
        unsigned in_u = (unsigned)__cvta_generic_to_shared(in_s);
        #pragma unroll
        for (int kw = 0; kw < 3; kw++) {
            #pragma unroll
            for (int ks = 0; ks < 2; ks++) {
                unsigned af[4];
                ldsm4(af, in_u + 2u * ((wm * 16 + kw + (lane & 15)) * 40
                                       + ks * 16 + ((lane >> 4) << 3)));
                #pragma unroll
                for (int np = 0; np < 3; np++) {
                    unsigned bf[4];
                    ldsmB(bf, w_s + (kw * 96 + wn * 48 + np * 16) * 40 + ks * 16, 40, lane);
                    mma16(acc[np * 2], af, bf);
                    mma16(acc[np * 2 + 1], af, bf + 2);
                }
            }
        }
    }
    float* orow = y2 + (size_t)(d * HH + h) * WW * CCH;
    float ch0[6], ch1[6];
    #pragma unroll
    for (int nt = 0; nt < 6; nt++) {
        int oc = wn * 48 + nt * 8 + tig * 2;
        float bb0 = b2[oc], bb1 = b2[oc + 1];
        #pragma unroll
        for (int half = 0; half < 2; half++) {
            int v = wm * 16 + gid + half * 8;
            float2 o2;
            o2.x = acc[nt][half * 2 + 0] + bb0;
            o2.y = acc[nt][half * 2 + 1] + bb1;
            *(float2*)(orow + v * CCH + oc) = o2;
        }
        ch0[nt] = acc[nt][0] + acc[nt][2] + 2.0f * bb0;
        ch1[nt] = acc[nt][1] + acc[nt][3] + 2.0f * bb1;
    }
    #pragma unroll
    for (int nt = 0; nt < 6; nt++) {
        #pragma unroll
        for (int m = 4; m < 32; m <<= 1) {
            ch0[nt] += __shfl_xor_sync(0xffffffffu, ch0[nt], m);
            ch1[nt] += __shfl_xor_sync(0xffffffffu, ch1[nt], m);
        }
    }
    float* ws = (float*)smb;
    if (gid == 0) {
        #pragma unroll
        for (int nt = 0; nt < 6; nt++) {
            int oc = wn * 48 + nt * 8 + tig * 2;
            ws[warp * 96 + oc] = ch0[nt];
            ws[warp * 96 + oc + 1] = ch1[nt];
        }
    }
    __syncthreads();
    if (tx < 96) {
        int wn2 = tx / 48;
        float s = ws[wn2 * 96 + tx] + ws[(wn2 + 2) * 96 + tx]
                + ws[(wn2 + 4) * 96 + tx] + ws[(wn2 + 6) * 96 + tx];
        part[blockIdx.x * 96 + tx] = s;
    }
}

// ---------------- channel attention ----------------
__global__ void ca_kernel(const float* __restrict__ part,
                          const float* __restrict__ ca1w, const float* __restrict__ ca1b,
                          const float* __restrict__ ca2w, const float* __restrict__ ca2b,
                          float* __restrict__ att)
{
    __shared__ float p[CCH], hs[3];
    int tx = threadIdx.x;
    float s = 0.f;
    for (int b = 0; b < 512; b++) s += part[b * CCH + tx];
    p[tx] = s * (1.0f / (float)LTOK);
    __syncthreads();
    if (tx < 3) {
        float a = ca1b[tx];
        for (int c = 0; c < CCH; c++) a += ca1w[tx * CCH + c] * p[c];
        hs[tx] = fmaxf(a, 0.f);
    }
    __syncthreads();
    float a = ca2b[tx];
    #pragma unroll
    for (int k = 0; k < 3; k++) a += ca2w[tx * 3 + k] * hs[k];
    att[tx] = 1.0f / (1.0f + expf(-a));
}

// ---------------- bf16 GEMM ----------------
template <int EPI, int MTILES, int KCH>
__global__ __launch_bounds__(256) void gemm_bf16(
    const __nv_bfloat16* __restrict__ A, const __nv_bfloat16* __restrict__ Wt,
    const float* __restrict__ bias, void* __restrict__ Cout, int Nn,
    const float* __restrict__ res1)
{
    const int MROWS = MTILES * 64;
    const int Ktot = KCH * 96;
    const int SE = (MROWS + 96) * 104;
    extern __shared__ __nv_bfloat16 smb[];
    int m0 = blockIdx.x * MROWS, n0 = blockIdx.y * 96;
    int tx = threadIdx.x;
    int warp = tx >> 5, lane = tx & 31;
    int wm = warp >> 1, wn = warp & 1;
    int gid = lane >> 2, tig = lane & 3;
    float acc[MTILES][6][4] = {};

    if (KCH == 1) {
        for (int idx = tx; idx < MROWS * 12; idx += 256) {
            int r = idx / 12, c = idx - r * 12;
            *(uint4*)(smb + r * 104 + c * 8) = *(const uint4*)(A + (size_t)(m0 + r) * Ktot + c * 8);
        }
        for (int idx = tx; idx < 1152; idx += 256) {
            int r = idx / 12, c = idx - r * 12;
            *(uint4*)(smb + (MROWS + r) * 104 + c * 8) = *(const uint4*)(Wt + (size_t)(n0 + r) * Ktot + c * 8);
        }
        __syncthreads();
    } else {
        for (int idx = tx; idx < MROWS * 12; idx += 256) {
            int r = idx / 12, c = idx - r * 12;
            cpa16(smb + r * 104 + c * 8, A + (size_t)(m0 + r) * Ktot + c * 8, true);
        }
        for (int idx = tx; idx < 1152; idx += 256) {
            int r = idx / 12, c = idx - r * 12;
            cpa16(smb + (MROWS + r) * 104 + c * 8, Wt + (size_t)(n0 + r) * Ktot + c * 8, true);
        }
        cpa_commit();
    }

    for (int kc = 0; kc < KCH; kc++) {
        if (KCH > 1) {
            if (kc + 1 < KCH) {
                int k0 = (kc + 1) * 96;
                __nv_bfloat16* st = smb + ((kc + 1) % 3) * SE;
                for (int idx = tx; idx < MROWS * 12; idx += 256) {
                    int r = idx / 12, c = idx - r * 12;
                    cpa16(st + r * 104 + c * 8, A + (size_t)(m0 + r) * Ktot + k0 + c * 8, true);
                }
                for (int idx = tx; idx < 1152; idx += 256) {
                    int r = idx / 12, c = idx - r * 12;
                    cpa16(st + (MROWS + r) * 104 + c * 8, Wt + (size_t)(n0 + r) * Ktot + k0 + c * 8, true);
                }
                cpa_commit();
                cpa_wait<1>();
            } else {
                cpa_wait<0>();
            }
            __syncthreads();
        }
        __nv_bfloat16* a_s = smb + (KCH > 1 ? (kc % 3) * SE : 0);
        __nv_bfloat16* w_s = a_s + MROWS * 104;
        unsigned a_u = (unsigned)__cvta_generic_to_shared(a_s);
        #pragma unroll
        for (int ks = 0; ks < 6; ks++) {
            unsigned af[MTILES][4];
            #pragma unroll
            for (int mt = 0; mt < MTILES; mt++)
                ldsm4(af[mt], a_u + 2u * ((wm * (MTILES * 16) + mt * 16 + (lane & 15)) * 104
                                          + ks * 16 + ((lane >> 4) << 3)));
            #pragma unroll
            for (int np = 0; np < 3; np++) {
                unsigned bf[4];
                ldsmB(bf, w_s + (wn * 48 + np * 16) * 104 + ks * 16, 104, lane);
                #pragma unroll
                for (int mt = 0; mt < MTILES; mt++) {
                    mma16(acc[mt][np * 2], af[mt], bf);
                    mma16(acc[mt][np * 2 + 1], af[mt], bf + 2);
                }
            }
        }
    }
    #pragma unroll
    for (int mt = 0; mt < MTILES; mt++) {
        #pragma unroll
        for (int nt = 0; nt < 6; nt++) {
            int cc = n0 + wn * 48 + nt * 8 + tig * 2;
            float bb0 = bias[cc], bb1 = bias[cc + 1];
            #pragma unroll
            for (int half = 0; half < 2; half++) {
                int r = m0 + wm * (MTILES * 16) + mt * 16 + gid + half * 8;
                size_t idx = (size_t)r * Nn + cc;
                float v0 = acc[mt][nt][half * 2 + 0] + bb0;
                float v1 = acc[mt][nt][half * 2 + 1] + bb1;
                if (EPI == 0) {
                    *(unsigned*)((__nv_bfloat16*)Cout + idx) = pack2(v0, v1);
                } else if (EPI == 1) {
                    *(unsigned*)((__nv_bfloat16*)Cout + idx) = pack2(gelu_exact(v0), gelu_exact(v1));
                } else {
                    float2 r1 = *(const float2*)(res1 + idx);
                    float2 o2;
                    o2.x = r1.x + v0;
                    o2.y = r1.y + v1;
                    *(float2*)((float*)Cout + idx) = o2;
                }
            }
        }
    }
}

// ---------------- proj GEMM + residual merge + fused LayerNorm2 ----------------
__global__ __launch_bounds__(256) void gemm_proj_ln(
    const __nv_bfloat16* __restrict__ A, const __nv_bfloat16* __restrict__ Wt,
    const float* __restrict__ bias,
    const float* __restrict__ res1, const float* __restrict__ res2,
    const float* __restrict__ att,
    const float* __restrict__ n2g, const float* __restrict__ n2b,
    float* __restrict__ x1, __nv_bfloat16* __restrict__ xn2)
{
    extern __shared__ __nv_bfloat16 smb[];
    __nv_bfloat16* a_s = smb;
    __nv_bfloat16* w_s = smb + 128 * 104;
    float* red_s = (float*)smb;
    float* red_q = red_s + 256;
    unsigned a_u = (unsigned)__cvta_generic_to_shared(a_s);
    int m0 = blockIdx.x * 128;
    int tx = threadIdx.x;
    int warp = tx >> 5, lane = tx & 31;
    int wm = warp >> 1, wn = warp & 1;
    int gid = lane >> 2, tig = lane & 3;
    float acc[2][6][4] = {};
    {
        for (int idx = tx; idx < 1536; idx += 256) {
            int r = idx / 12, c = idx - r * 12;
            *(uint4*)(a_s + r * 104 + c * 8) = *(const uint4*)(A + (size_t)(m0 + r) * 96 + c * 8);
        }
        for (int idx = tx; idx < 1152; idx += 256) {
            int r = idx / 12, c = idx - r * 12;
            *(uint4*)(w_s + r * 104 + c * 8) = *(const uint4*)(Wt + (size_t)r * 96 + c * 8);
        }
        __syncthreads();
        #pragma unroll
        for (int ks = 0; ks < 6; ks++) {
            unsigned af[2][4];
            #pragma unroll
            for (int mt = 0; mt < 2; mt++)
                ldsm4(af[mt], a_u + 2u * ((wm * 32 + mt * 16 + (lane & 15)) * 104
                                          + ks * 16 + ((lane >> 4) << 3)));
            #pragma unroll
            for (int np = 0; np < 3; np++) {
                unsigned bf[4];
                ldsmB(bf, w_s + (wn * 48 + np * 16) * 104 + ks * 16, 104, lane);
                #pragma unroll
                for (int mt = 0; mt < 2; mt++) {
                    mma16(acc[mt][np * 2], af[mt], bf);
                    mma16(acc[mt][np * 2 + 1], af[mt], bf + 2);
                }
            }
        }
    }
    __syncthreads();

    float rs[2][2] = {}, rq[2][2] = {};
    #pragma unroll
    for (int mt = 0; mt < 2; mt++) {
        #pragma unroll
        for (int nt = 0; nt < 6; nt++) {
            int cc = wn * 48 + nt * 8 + tig * 2;
            float bb0 = bias[cc], bb1 = bias[cc + 1];
            float a0 = att[cc] * 0.01f, a1 = att[cc + 1] * 0.01f;
            #pragma unroll
            for (int half = 0; half < 2; half++) {
                int r = m0 + wm * 32 + mt * 16 + gid + half * 8;
                size_t idx = (size_t)r * 96 + cc;
                float2 r1 = *(const float2*)(res1 + idx);
                float2 r2 = *(const float2*)(res2 + idx);
                float v0 = r1.x + acc[mt][nt][half * 2 + 0] + bb0 + r2.x * a0;
                float v1 = r1.y + acc[mt][nt][half * 2 + 1] + bb1 + r2.y * a1;
                acc[mt][nt][half * 2 + 0] = v0;
                acc[mt][nt][half * 2 + 1] = v1;
                *(float2*)(x1 + idx) = make_float2(v0, v1);
                rs[mt][half] += v0 + v1;
                rq[mt][half] += v0 * v0 + v1 * v1;
            }
        }
    }
    #pragma unroll
    for (int mt = 0; mt < 2; mt++)
        #pragma unroll
        for (int half = 0; half < 2; half++) {
            float s = rs[mt][half], q = rq[mt][half];
            s += __shfl_xor_sync(0xffffffffu, s, 1);
            s += __shfl_xor_sync(0xffffffffu, s, 2);
            q += __shfl_xor_sync(0xffffffffu, q, 1);
            q += __shfl_xor_sync(0xffffffffu, q, 2);
            if (tig == 0) {
                int lr = wm * 32 + mt * 16 + half * 8 + gid;
                red_s[lr * 2 + wn] = s;
                red_q[lr * 2 + wn] = q;
            }
        }
    __syncthreads();
    #pragma unroll
    for (int mt = 0; mt < 2; mt++) {
        #pragma unroll
        for (int half = 0; half < 2; half++) {
            int lr = wm * 32 + mt * 16 + half * 8 + gid;
            float sum = red_s[lr * 2] + red_s[lr * 2 + 1];
            float sq  = red_q[lr * 2] + red_q[lr * 2 + 1];
            float mean = sum * (1.0f / 96.0f);
            float var = sq * (1.0f / 96.0f) - mean * mean;
            float inv = rsqrtf(var + 1e-5f);
            int r = m0 + lr;
            #pragma unroll
            for (int nt = 0; nt < 6; nt++) {
                int cc = wn * 48 + nt * 8 + tig * 2;
                float g0 = n2g[cc], g1 = n2g[cc + 1];
                float b0 = n2b[cc], b1 = n2b[cc + 1];
                float v0 = (acc[mt][nt][half * 2 + 0] - mean) * inv * g0 + b0;
                float v1 = (acc[mt][nt][half * 2 + 1] - mean) * inv * g1 + b1;
                *(unsigned*)(xn2 + (size_t)r * 96 + cc) = pack2(v0, v1);
            }
        }
    }
}

// ---------------- attention ----------------
#define OFF_Q  0
#define OFF_K  3072
#define OFF_V  27648
#define OFF_R1 44288
#define OFF_R2 45312
#define OFF_OR 46336
#define SMEM_ATTN 62720

__device__ __forceinline__ int wtok(int j, int base) {
    return ((j >> 6) << 12) + base + (((j >> 3) & 7) << 6) + (j & 7);
}

__global__ __launch_bounds__(512) void attn_kernel(
    const __nv_bfloat16* __restrict__ qkv, const __nv_bfloat16* __restrict__ biasb,
    __nv_bfloat16* __restrict__ o)
{
    extern __shared__ char smc[];
    __nv_bfloat16* q_s = (__nv_bfloat16*)(smc + OFF_Q);
    __nv_bfloat16* k_s = (__nv_bfloat16*)(smc + OFF_K);
    __nv_bfloat16* v_t = (__nv_bfloat16*)(smc + OFF_V);
    float* red1 = (float*)(smc + OFF_R1);
    float* red2 = (float*)(smc + OFF_R2);
    float* o_red = (float*)(smc + OFF_OR);
    unsigned q_u = (unsigned)__cvta_generic_to_shared(q_s);

    int blk = blockIdx.x;
    int qc = blk & 7;
    int head = (blk >> 3) % 6;
    int win = blk / 48;
    int base = (win >> 3) * 512 + (win & 7) * 8;
    int m0 = qc * 64;
    int tx = threadIdx.x;
    int warp = tx >> 5, lane = tx & 31;
    int gid = lane >> 2, tig = lane & 3;
    int wm = warp >> 2, wn = warp & 3;
    int r0 = wm * 16, j0 = wn * 128;

    for (int idx = tx; idx < 1024; idx += 512) {
        int j = idx >> 1, half = idx & 1;
        int t = wtok(j, base);
        const __nv_bfloat16* p = qkv + (size_t)t * 288 + head * 16 + half * 8;
        *(uint4*)(k_s + j * 24 + half * 8) = *(const uint4*)(p + 96);
        uint4 v4 = *(const uint4*)(p + 192);
        const __nv_bfloat16* vp = (const __nv_bfloat16*)&v4;
        #pragma unroll
        for (int dd2 = 0; dd2 < 8; dd2++)
            v_t[(half * 8 + dd2) * 520 + j] = vp[dd2];
    }
    if (tx < 128) {
        int i = tx >> 1, half = tx & 1;
        int t = wtok(m0 + i, base);
        uint4 raw = *(const uint4*)(qkv + (size_t)t * 288 + head * 16 + half * 8);
        const __nv_bfloat16* rp = (const __nv_bfloat16*)&raw;
        unsigned pk[4];
        #pragma unroll
        for (int e = 0; e < 4; e++)
            pk[e] = pack2(__bfloat162float(rp[e * 2]) * 0.25f,
                          __bfloat162float(rp[e * 2 + 1]) * 0.25f);
        *(uint4*)(q_s + i * 24 + half * 8) = *(uint4*)pk;
    }
    __syncthreads();

    float acc[16][4] = {};
    {
        unsigned aq[4];
        ldsm4(aq, q_u + 2u * ((r0 + (lane & 15)) * 24 + ((lane >> 4) << 3)));
        #pragma unroll
        for (int np = 0; np < 8; np++) {
            unsigned bf[4];
            ldsmB(bf, k_s + (j0 + np * 16) * 24, 24, lane);
            mma16(acc[np * 2], aq, bf);
            mma16(acc[np * 2 + 1], aq, bf + 2);
        }
        const __nv_bfloat16* bbA = biasb + ((size_t)head * 512 + (m0 + r0 + gid)) * 512 + j0 + tig * 2;
        const __nv_bfloat16* bbB = bbA + 8 * 512;
        #pragma unroll
        for (int nt = 0; nt < 16; nt++) {
            float2 fa = __bfloat1622float2(*(const __nv_bfloat162*)(bbA + nt * 8));
            float2 fb = __bfloat1622float2(*(const __nv_bfloat162*)(bbB + nt * 8));
            acc[nt][0] += fa.x; acc[nt][1] += fa.y;
            acc[nt][2] += fb.x; acc[nt][3] += fb.y;
        }
    }
    {
        float mA = -1e30f, mB = -1e30f;
        #pragma unroll
        for (int nt = 0; nt < 16; nt++) {
            mA = fmaxf(mA, fmaxf(acc[nt][0], acc[nt][1]));
            mB = fmaxf(mB, fmaxf(acc[nt][2], acc[nt][3]));
        }
        mA = fmaxf(mA, __shfl_xor_sync(0xffffffffu, mA, 1));
        mA = fmaxf(mA, __shfl_xor_sync(0xffffffffu, mA, 2));
        mB = fmaxf(mB, __shfl_xor_sync(0xffffffffu, mB, 1));
        mB = fmaxf(mB, __shfl_xor_sync(0xffffffffu, mB, 2));
        if (tig == 0) {
            red1[(r0 + gid) * 4 + wn] = mA;
            red1[(r0 + gid + 8) * 4 + wn] = mB;
        }
        __syncthreads();
        mA = fmaxf(fmaxf(red1[(r0 + gid) * 4 + 0], red1[(r0 + gid) * 4 + 1]),
                   fmaxf(red1[(r0 + gid) * 4 + 2], red1[(r0 + gid) * 4 + 3]));
        mB = fmaxf(fmaxf(red1[(r0 + gid + 8) * 4 + 0], red1[(r0 + gid + 8) * 4 + 1]),
                   fmaxf(red1[(r0 + gid + 8) * 4 + 2], red1[(r0 + gid + 8) * 4 + 3]));
        float sA = 0.f, sB = 0.f;
        #pragma unroll
        for (int nt = 0; nt < 16; nt++) {
            acc[nt][0] = __expf(acc[nt][0] - mA);
            acc[nt][1] = __expf(acc[nt][1] - mA);
            acc[nt][2] = __expf(acc[nt][2] - mB);
            acc[nt][3] = __expf(acc[nt][3] - mB);
            sA += acc[nt][0] + acc[nt][1];
            sB += acc[nt][2] + acc[nt][3];
        }
        sA += __shfl_xor_sync(0xffffffffu, sA, 1);
        sA += __shfl_xor_sync(0xffffffffu, sA, 2);
        sB += __shfl_xor_sync(0xffffffffu, sB, 1);
        sB += __shfl_xor_sync(0xffffffffu, sB, 2);
        if (tig == 0) {
            red2[(r0 + gid) * 4 + wn] = sA;
            red2[(r0 + gid + 8) * 4 + wn] = sB;
        }
        __syncthreads();
        sA = red2[(r0 + gid) * 4 + 0] + red2[(r0 + gid) * 4 + 1]
           + red2[(r0 + gid) * 4 + 2] + red2[(r0 + gid) * 4 + 3];
        sB = red2[(r0 + gid + 8) * 4 + 0] + red2[(r0 + gid + 8) * 4 + 1]
           + red2[(r0 + gid + 8) * 4 + 2] + red2[(r0 + gid + 8) * 4 + 3];
        float iA = 1.0f / sA, iB = 1.0f / sB;
        #pragma unroll
        for (int nt = 0; nt < 16; nt++) {
            acc[nt][0] *= iA; acc[nt][1] *= iA;
            acc[nt][2] *= iB; acc[nt][3] *= iB;
        }
    }

    float oa[2][4] = {};
    #pragma unroll
    for (int kk = 0; kk < 8; kk++) {
        unsigned af[4];
        af[0] = pack2(acc[2 * kk][0],     acc[2 * kk][1]);
        af[1] = pack2(acc[2 * kk][2],     acc[2 * kk][3]);
        af[2] = pack2(acc[2 * kk + 1][0], acc[2 * kk + 1][1]);
        af[3] = pack2(acc[2 * kk + 1][2], acc[2 * kk + 1][3]);
        unsigned bf[4];
        ldsmB(bf, v_t + j0 + kk * 16, 520, lane);
        mma16(oa[0], af, bf);
        mma16(oa[1], af, bf + 2);
    }
    {
        float* orp = o_red + (size_t)wn * 1024;
        #pragma unroll
        for (int dt = 0; dt < 2; dt++) {
            int dc = dt * 8 + tig * 2;
            *(float2*)(orp + (r0 + gid) * 16 + dc)     = make_float2(oa[dt][0], oa[dt][1]);
            *(float2*)(orp + (r0 + gid + 8) * 16 + dc) = make_float2(oa[dt][2], oa[dt][3]);
        }
    }
    __syncthreads();
    {
        int row = tx >> 3, d2 = tx & 7;
        int dim = d2 * 2;
        float v0 = 0.f, v1 = 0.f;
        #pragma unroll
        for (int p = 0; p < 4; p++) {
            v0 += o_red[p * 1024 + row * 16 + dim];
            v1 += o_red[p * 1024 + row * 16 + dim + 1];
        }
        int t = wtok(m0 + row, base);
        *(unsigned*)(o + (size_t)t * CCH + head * 16 + dim) = pack2(v0, v1);
    }
}

// ---------------- launch: forked-stream DAG (conv branch || attention branch) ----------------
extern "C" void kernel_launch(void* const* d_in, const int* in_sizes, int n_in,
                              void* d_out, int out_size)
{
    (void)in_sizes; (void)n_in; (void)out_size;
    const float* x       = (const float*)d_in[0];
    const float* n1g     = (const float*)d_in[1];
    const float* n1b     = (const float*)d_in[2];
    const float* qkv_w   = (const float*)d_in[3];
    const float* qkv_b   = (const float*)d_in[4];
    const float* rpbt    = (const float*)d_in[5];
    const float* proj_w  = (const float*)d_in[6];
    const float* proj_b  = (const float*)d_in[7];
    const float* conv1_w = (const float*)d_in[8];
    const float* conv1_b = (const float*)d_in[9];
    const float* conv2_w = (const float*)d_in[10];
    const float* conv2_b = (const float*)d_in[11];
    const float* ca1_w   = (const float*)d_in[12];
    const float* ca1_b   = (const float*)d_in[13];
    const float* ca2_w   = (const float*)d_in[14];
    const float* ca2_b   = (const float*)d_in[15];
    const float* n2g     = (const float*)d_in[16];
    const float* n2b     = (const float*)d_in[17];
    const float* fc1_w   = (const float*)d_in[18];
    const float* fc1_b   = (const float*)d_in[19];
    const float* fc2_w   = (const float*)d_in[20];
    const float* fc2_b   = (const float*)d_in[21];
    const int*   rpi     = (const int*)d_in[22];
    float* out = (float*)d_out;

    __nv_bfloat16 *xn, *y1, *qkvb, *biasb, *ob, *xn2, *hb, *w1r, *w2r, *qw, *pw, *f1w, *f2w;
    float *y2, *part, *att, *x1;
    cudaGetSymbolAddress((void**)&xn,    g_xn);
    cudaGetSymbolAddress((void**)&y1,    g_y1);
    cudaGetSymbolAddress((void**)&y2,    g_y2);
    cudaGetSymbolAddress((void**)&part,  g_part);
    cudaGetSymbolAddress((void**)&att,   g_att);
    cudaGetSymbolAddress((void**)&qkvb,  g_qkv);
    cudaGetSymbolAddress((void**)&biasb, g_bias);
    cudaGetSymbolAddress((void**)&ob,    g_o);
    cudaGetSymbolAddress((void**)&x1,    g_x1);
    cudaGetSymbolAddress((void**)&xn2,   g_xn2);
    cudaGetSymbolAddress((void**)&hb,    g_h);
    cudaGetSymbolAddress((void**)&w1r,   g_w1r);
    cudaGetSymbolAddress((void**)&w2r,   g_w2r);
    cudaGetSymbolAddress((void**)&qw,    g_qw);
    cudaGetSymbolAddress((void**)&pw,    g_pw);
    cudaGetSymbolAddress((void**)&f1w,   g_f1w);
    cudaGetSymbolAddress((void**)&f2w,   g_f2w);

    const int SMEM_CONV1 = 3 * C1_SE * 2;
    const int SMEM_CONV2 = 3 * C2_SE * 2;
    const int SMEM_G128  = (128 + 96) * 104 * 2;
    const int SMEM_G64P  = 3 * (64 + 96) * 104 * 2;
    cudaFuncSetAttribute(conv1_kernel, cudaFuncAttributeMaxDynamicSharedMemorySize, SMEM_CONV1);
    cudaFuncSetAttribute(conv2_kernel, cudaFuncAttributeMaxDynamicSharedMemorySize, SMEM_CONV2);
    cudaFuncSetAttribute(gemm_bf16<0, 2, 1>, cudaFuncAttributeMaxDynamicSharedMemorySize, SMEM_G128);
    cudaFuncSetAttribute(gemm_bf16<1, 2, 1>, cudaFuncAttributeMaxDynamicSharedMemorySize, SMEM_G128);
    cudaFuncSetAttribute(gemm_bf16<3, 1, 4>, cudaFuncAttributeMaxDynamicSharedMemorySize, SMEM_G64P);
    cudaFuncSetAttribute(gemm_proj_ln, cudaFuncAttributeMaxDynamicSharedMemorySize, SMEM_G128);
    cudaFuncSetAttribute(attn_kernel, cudaFuncAttributeMaxDynamicSharedMemorySize, SMEM_ATTN);

    // fork/join stream setup (host-side objects only; created fresh each call)
    cudaStream_t s2;
    cudaStreamCreateWithFlags(&s2, cudaStreamNonBlocking);
    cudaEvent_t eFork, eJoin;
    cudaEventCreateWithFlags(&eFork, cudaEventDisableTiming);
    cudaEventCreateWithFlags(&eJoin, cudaEventDisableTiming);

    // origin stream: setup + LN1 (both branches depend on these)
    setup_kernel<<<7224, 256>>>(qkv_w, proj_w, fc1_w, fc2_w, conv1_w, conv2_w,
                                rpi, rpbt, qw, pw, f1w, f2w, w1r, w2r, biasb);
    ln_kernel<<<LTOK / 8, 256>>>(x, n1g, n1b, xn);
    cudaEventRecord(eFork, 0);

    // side stream: conv branch
    cudaStreamWaitEvent(s2, eFork, 0);
    conv1_kernel<<<512, 256, SMEM_CONV1, s2>>>(xn, w1r, conv1_b, y1);
    conv2_kernel<<<512, 256, SMEM_CONV2, s2>>>(y1, w2r, conv2_b, y2, part);
    ca_kernel<<<1, CCH, 0, s2>>>(part, ca1_w, ca1_b, ca2_w, ca2_b, att);
    cudaEventRecord(eJoin, s2);

    // origin stream: attention branch (runs concurrently with conv branch)
    gemm_bf16<0, 2, 1><<<dim3(LTOK / 128, 3), 256, SMEM_G128>>>(
        xn, qw, qkv_b, qkvb, 288, nullptr);
    attn_kernel<<<NWIN * HEADS * 8, 512, SMEM_ATTN>>>(qkvb, biasb, ob);

    // join: proj needs attn output + y2 + att
    cudaStreamWaitEvent(0, eJoin, 0);
    gemm_proj_ln<<<LTOK / 128, 256, SMEM_G128>>>(
        ob, pw, proj_b, x, y2, att, n2g, n2b, x1, xn2);

    gemm_bf16<1, 2, 1><<<dim3(LTOK / 128, 4), 256, SMEM_G128>>>(
        xn2, f1w, fc1_b, hb, 384, nullptr);
    gemm_bf16<3, 1, 4><<<dim3(LTOK / 64, 1), 256, SMEM_G64P>>>(
        hb, f2w, fc2_b, out, 96, x1);
}

// round 10
// speedup vs baseline: 5.0203x; 1.0250x over previous
#include <cuda_runtime.h>
#include <cuda_bf16.h>
#include <math.h>
#include <stdint.h>

#define DD 8
#define HH 64
#define WW 64
#define LTOK 32768
#define CCH 96
#define CMP 32
#define HID 384
#define HEADS 6
#define HDIM 16
#define NWIN 64
#define NTOK 512

// ---------------- scratch ----------------
__device__ __nv_bfloat16 g_xn  [LTOK * CCH];
__device__ __nv_bfloat16 g_y1  [LTOK * CMP];
__device__ __nv_bfloat16 g_y2  [LTOK * CCH];
__device__ float         g_part[512 * CCH];
__device__ float         g_att [CCH];
__device__ __nv_bfloat16 g_qkv [LTOK * 3 * CCH];
__device__ __nv_bfloat16 g_bias[HEADS * NTOK * NTOK];
__device__ __nv_bfloat16 g_o   [LTOK * CCH];
__device__ float         g_x1  [LTOK * CCH];
__device__ __nv_bfloat16 g_xn2 [LTOK * CCH];
__device__ __nv_bfloat16 g_h   [LTOK * HID];
__device__ __nv_bfloat16 g_w1r [27 * CMP * CCH];
__device__ __nv_bfloat16 g_w2r [27 * CCH * CMP];
__device__ __nv_bfloat16 g_qw  [288 * 96];
__device__ __nv_bfloat16 g_pw  [96 * 96];
__device__ __nv_bfloat16 g_f1w [384 * 96];
__device__ __nv_bfloat16 g_f2w [96 * 384];

__device__ __forceinline__ float gelu_exact(float v) {
    return 0.5f * v * (1.0f + erff(v * 0.70710678118654752f));
}
__device__ __forceinline__ unsigned pack2(float a, float b) {
    __nv_bfloat162 t = __floats2bfloat162_rn(a, b);
    return *reinterpret_cast<unsigned*>(&t);
}
__device__ __forceinline__ void ldsm4(unsigned* r, unsigned addr) {
    asm volatile("ldmatrix.sync.aligned.m8n8.x4.shared.b16 {%0,%1,%2,%3},[%4];"
                 : "=r"(r[0]), "=r"(r[1]), "=r"(r[2]), "=r"(r[3]) : "r"(addr));
}
__device__ __forceinline__ void ldsmB(unsigned* r, const __nv_bfloat16* base, int S, int lane) {
    int tq = lane & 7, sel = lane >> 3;
    const __nv_bfloat16* p = base + ((sel & 2) * 4 + tq) * S + (sel & 1) * 8;
    ldsm4(r, (unsigned)__cvta_generic_to_shared(p));
}
__device__ __forceinline__ void mma16(float* d, const unsigned* a, const unsigned* b) {
    asm volatile(
        "mma.sync.aligned.m16n8k16.row.col.f32.bf16.bf16.f32 "
        "{%0,%1,%2,%3},{%4,%5,%6,%7},{%8,%9},{%0,%1,%2,%3};"
        : "+f"(d[0]), "+f"(d[1]), "+f"(d[2]), "+f"(d[3])
        : "r"(a[0]), "r"(a[1]), "r"(a[2]), "r"(a[3]), "r"(b[0]), "r"(b[1]));
}
__device__ __forceinline__ void cpa16(__nv_bfloat16* s, const void* g, bool v) {
    unsigned sa = (unsigned)__cvta_generic_to_shared(s);
    int sz = v ? 16 : 0;
    asm volatile("cp.async.cg.shared.global [%0], [%1], 16, %2;" :: "r"(sa), "l"(g), "r"(sz));
}
__device__ __forceinline__ void cpa_commit() { asm volatile("cp.async.commit_group;"); }
template <int N> __device__ __forceinline__ void cpa_wait() {
    asm volatile("cp.async.wait_group %0;" :: "n"(N));
}

// ---------------- LayerNorm ----------------
__global__ void ln_kernel(const float* __restrict__ x, const float* __restrict__ g,
                          const float* __restrict__ b, __nv_bfloat16* __restrict__ out)
{
    int row  = blockIdx.x * 8 + (threadIdx.x >> 5);
    int lane = threadIdx.x & 31;
    const float* xr = x + (size_t)row * CCH;
    float v0 = xr[lane], v1 = xr[lane + 32], v2 = xr[lane + 64];
    float s = v0 + v1 + v2;
    #pragma unroll
    for (int o = 16; o; o >>= 1) s += __shfl_xor_sync(0xffffffffu, s, o);
    float mu = s * (1.0f / 96.0f);
    float d0 = v0 - mu, d1 = v1 - mu, d2 = v2 - mu;
    float q = d0 * d0 + d1 * d1 + d2 * d2;
    #pragma unroll
    for (int o = 16; o; o >>= 1) q += __shfl_xor_sync(0xffffffffu, q, o);
    float inv = rsqrtf(q * (1.0f / 96.0f) + 1e-5f);
    __nv_bfloat16* orow = out + (size_t)row * CCH;
    orow[lane]      = __float2bfloat16(d0 * inv * g[lane]      + b[lane]);
    orow[lane + 32] = __float2bfloat16(d1 * inv * g[lane + 32] + b[lane + 32]);
    orow[lane + 64] = __float2bfloat16(d2 * inv * g[lane + 64] + b[lane + 64]);
}

// ---------------- setup: weights only (1080 blocks) ----------------
__global__ void setup_w_kernel(
    const float* __restrict__ qkv_w, const float* __restrict__ proj_w,
    const float* __restrict__ fc1_w, const float* __restrict__ fc2_w,
    const float* __restrict__ conv1_w, const float* __restrict__ conv2_w,
    __nv_bfloat16* __restrict__ qw, __nv_bfloat16* __restrict__ pw,
    __nv_bfloat16* __restrict__ f1w, __nv_bfloat16* __restrict__ f2w,
    __nv_bfloat16* __restrict__ w1r, __nv_bfloat16* __restrict__ w2r)
{
    int b = blockIdx.x, tx = threadIdx.x;
    if (b < 108) {
        int i = b * 256 + tx;
        if (i < 288 * 96) qw[i] = __float2bfloat16(qkv_w[i]);
    } else if (b < 144) {
        int i = (b - 108) * 256 + tx;
        if (i < 96 * 96) pw[i] = __float2bfloat16(proj_w[i]);
    } else if (b < 288) {
        int i = (b - 144) * 256 + tx;
        if (i < 384 * 96) f1w[i] = __float2bfloat16(fc1_w[i]);
    } else if (b < 432) {
        int i = (b - 288) * 256 + tx;
        if (i < 96 * 384) f2w[i] = __float2bfloat16(fc2_w[i]);
    } else if (b < 756) {
        int tid = (b - 432) * 256 + tx;
        if (tid < CMP * CCH * 27) {
            int o = tid / (CCH * 27);
            int rem = tid - o * (CCH * 27);
            int c = rem / 27;
            int tap = rem - c * 27;
            w1r[(tap * CMP + o) * CCH + c] = __float2bfloat16(conv1_w[tid]);
        }
    } else {
        int tid = (b - 756) * 256 + tx;
        if (tid < CCH * CMP * 27) {
            int o = tid / (CMP * 27);
            int rem = tid - o * (CMP * 27);
            int i = rem / 27;
            int tap = rem - i * 27;
            w2r[(tap * CCH + o) * CMP + i] = __float2bfloat16(conv2_w[tid]);
        }
    }
}

// ---------------- setup: bias expansion (6144 blocks) ----------------
__global__ void setup_bias_kernel(const int* __restrict__ rpi, const float* __restrict__ rpbt,
                                  __nv_bfloat16* __restrict__ biasb)
{
    int tid = blockIdx.x * 256 + threadIdx.x;
    int h = tid >> 18;
    int r = tid & 262143;
    biasb[tid] = __float2bfloat16(rpbt[rpi[r] * HEADS + h]);
}

// ---------------- conv1: 96->32 + GELU, cp.async 3-stage pipeline ----------------
#define C1_SE (162 * 104)
__global__ __launch_bounds__(256) void conv1_kernel(
    const __nv_bfloat16* __restrict__ xn, const __nv_bfloat16* __restrict__ w1r,
    const float* __restrict__ b1, __nv_bfloat16* __restrict__ y1)
{
    extern __shared__ __nv_bfloat16 smb[];
    int d = blockIdx.x >> 6, h = blockIdx.x & 63;
    int tx = threadIdx.x;
    int warp = tx >> 5, lane = tx & 31;
    int gid = lane >> 2, tig = lane & 3;
    int wm = warp >> 1, wn = warp & 1;
    float acc[2][4] = {};

    auto load_phase = [&](int p, int buf) {
        int kd = p / 3, kh = p - kd * 3;
        int dd = d + kd - 1, hh = h + kh - 1;
        bool rowv = ((unsigned)dd < 8u) && ((unsigned)hh < 64u);
        __nv_bfloat16* in_s = smb + buf * C1_SE;
        __nv_bfloat16* w_s  = in_s + 66 * 104;
        const __nv_bfloat16* src_row = xn + ((size_t)(dd * HH + hh) * WW) * CCH;
        for (int idx = tx; idx < 792; idx += 256) {
            int r = idx / 12, c = idx - r * 12;
            int wv = r - 1;
            bool v = rowv && (unsigned)wv < 64u;
            const void* g = v ? (const void*)(src_row + wv * CCH + c * 8) : (const void*)xn;
            cpa16(in_s + r * 104 + c * 8, g, v);
        }
        const __nv_bfloat16* wsrc = w1r + (size_t)p * 3 * (CMP * CCH);
        for (int idx = tx; idx < 1152; idx += 256) {
            int r = idx / 12, c = idx - r * 12;
            cpa16(w_s + r * 104 + c * 8, wsrc + idx * 8, true);
        }
        cpa_commit();
    };

    load_phase(0, 0);
    for (int p = 0; p < 9; p++) {
        if (p < 8) { load_phase(p + 1, (p + 1) % 3); cpa_wait<1>(); }
        else cpa_wait<0>();
        __syncthreads();
        __nv_bfloat16* in_s = smb + (p % 3) * C1_SE;
        __nv_bfloat16* w_s  = in_s + 66 * 104;
        unsigned in_u = (unsigned)__cvta_generic_to_shared(in_s);
        #pragma unroll
        for (int kw = 0; kw < 3; kw++) {
            #pragma unroll
            for (int ks = 0; ks < 6; ks++) {
                unsigned af[4];
                ldsm4(af, in_u + 2u * ((wm * 16 + kw + (lane & 15)) * 104
                                       + ks * 16 + ((lane >> 4) << 3)));
                unsigned bf[4];
                ldsmB(bf, w_s + (kw * 32 + wn * 16) * 104 + ks * 16, 104, lane);
                mma16(acc[0], af, bf);
                mma16(acc[1], af, bf + 2);
            }
        }
    }
    __nv_bfloat16* orow = y1 + (size_t)(d * HH + h) * WW * CMP;
    #pragma unroll
    for (int nt = 0; nt < 2; nt++) {
        int oc = wn * 16 + nt * 8 + tig * 2;
        float bb0 = b1[oc], bb1 = b1[oc + 1];
        #pragma unroll
        for (int half = 0; half < 2; half++) {
            int v = wm * 16 + gid + half * 8;
            *(unsigned*)(orow + v * CMP + oc) =
                pack2(gelu_exact(acc[nt][half * 2 + 0] + bb0),
                      gelu_exact(acc[nt][half * 2 + 1] + bb1));
        }
    }
}

// ---------------- conv2: 32->96, cp.async 3-stage + fused pool partials (bf16 out) ----------------
#define C2_SE (354 * 40)
__global__ __launch_bounds__(256) void conv2_kernel(
    const __nv_bfloat16* __restrict__ y1, const __nv_bfloat16* __restrict__ w2r,
    const float* __restrict__ b2, __nv_bfloat16* __restrict__ y2, float* __restrict__ part)
{
    extern __shared__ __nv_bfloat16 smb[];
    int d = blockIdx.x >> 6, h = blockIdx.x & 63;
    int tx = threadIdx.x;
    int warp = tx >> 5, lane = tx & 31;
    int gid = lane >> 2, tig = lane & 3;
    int wm = warp >> 1, wn = warp & 1;
    float acc[6][4] = {};

    auto load_phase = [&](int p, int buf) {
        int kd = p / 3, kh = p - kd * 3;
        int dd = d + kd - 1, hh = h + kh - 1;
        bool rowv = ((unsigned)dd < 8u) && ((unsigned)hh < 64u);
        __nv_bfloat16* in_s = smb + buf * C2_SE;
        __nv_bfloat16* w_s  = in_s + 66 * 40;
        const __nv_bfloat16* src_row = y1 + ((size_t)(dd * HH + hh) * WW) * CMP;
        for (int idx = tx; idx < 264; idx += 256) {
            int r = idx >> 2, c = idx & 3;
            int wv = r - 1;
            bool v = rowv && (unsigned)wv < 64u;
            const void* g = v ? (const void*)(src_row + wv * CMP + c * 8) : (const void*)y1;
            cpa16(in_s + r * 40 + c * 8, g, v);
        }
        const __nv_bfloat16* wsrc = w2r + (size_t)p * 3 * (CCH * CMP);
        for (int idx = tx; idx < 1152; idx += 256) {
            int r = idx >> 2, c = idx & 3;
            cpa16(w_s + r * 40 + c * 8, wsrc + idx * 8, true);
        }
        cpa_commit();
    };

    load_phase(0, 0);
    for (int p = 0; p < 9; p++) {
        if (p < 8) { load_phase(p + 1, (p + 1) % 3); cpa_wait<1>(); }
        else cpa_wait<0>();
        __syncthreads();
        __nv_bfloat16* in_s = smb + (p % 3) * C2_SE;
        __nv_bfloat16* w_s  = in_s + 66 * 40;
        unsigned in_u = (unsigned)__cvta_generic_to_shared(in_s);
        #pragma unroll
        for (int kw = 0; kw < 3; kw++) {
            #pragma unroll
            for (int ks = 0; ks < 2; ks++) {
                unsigned af[4];
                ldsm4(af, in_u + 2u * ((wm * 16 + kw + (lane & 15)) * 40
                                       + ks * 16 + ((lane >> 4) << 3)));
                #pragma unroll
                for (int np = 0; np < 3; np++) {
                    unsigned bf[4];
                    ldsmB(bf, w_s + (kw * 96 + wn * 48 + np * 16) * 40 + ks * 16, 40, lane);
                    mma16(acc[np * 2], af, bf);
                    mma16(acc[np * 2 + 1], af, bf + 2);
                }
            }
        }
    }
    __nv_bfloat16* orow = y2 + (size_t)(d * HH + h) * WW * CCH;
    float ch0[6], ch1[6];
    #pragma unroll
    for (int nt = 0; nt < 6; nt++) {
        int oc = wn * 48 + nt * 8 + tig * 2;
        float bb0 = b2[oc], bb1 = b2[oc + 1];
        #pragma unroll
        for (int half = 0; half < 2; half++) {
            int v = wm * 16 + gid + half * 8;
            *(unsigned*)(orow + v * CCH + oc) =
                pack2(acc[nt][half * 2 + 0] + bb0, acc[nt][half * 2 + 1] + bb1);
        }
        ch0[nt] = acc[nt][0] + acc[nt][2] + 2.0f * bb0;
        ch1[nt] = acc[nt][1] + acc[nt][3] + 2.0f * bb1;
    }
    #pragma unroll
    for (int nt = 0; nt < 6; nt++) {
        #pragma unroll
        for (int m = 4; m < 32; m <<= 1) {
            ch0[nt] += __shfl_xor_sync(0xffffffffu, ch0[nt], m);
            ch1[nt] += __shfl_xor_sync(0xffffffffu, ch1[nt], m);
        }
    }
    float* ws = (float*)smb;
    if (gid == 0) {
        #pragma unroll
        for (int nt = 0; nt < 6; nt++) {
            int oc = wn * 48 + nt * 8 + tig * 2;
            ws[warp * 96 + oc] = ch0[nt];
            ws[warp * 96 + oc + 1] = ch1[nt];
        }
    }
    __syncthreads();
    if (tx < 96) {
        int wn2 = tx / 48;
        float s = ws[wn2 * 96 + tx] + ws[(wn2 + 2) * 96 + tx]
                + ws[(wn2 + 4) * 96 + tx] + ws[(wn2 + 6) * 96 + tx];
        part[blockIdx.x * 96 + tx] = s;
    }
}

// ---------------- channel attention ----------------
__global__ void ca_kernel(const float* __restrict__ part,
                          const float* __restrict__ ca1w, const float* __restrict__ ca1b,
                          const float* __restrict__ ca2w, const float* __restrict__ ca2b,
                          float* __restrict__ att)
{
    __shared__ float p[CCH], hs[3];
    int tx = threadIdx.x;
    float s = 0.f;
    for (int b = 0; b < 512; b++) s += part[b * CCH + tx];
    p[tx] = s * (1.0f / (float)LTOK);
    __syncthreads();
    if (tx < 3) {
        float a = ca1b[tx];
        for (int c = 0; c < CCH; c++) a += ca1w[tx * CCH + c] * p[c];
        hs[tx] = fmaxf(a, 0.f);
    }
    __syncthreads();
    float a = ca2b[tx];
    #pragma unroll
    for (int k = 0; k < 3; k++) a += ca2w[tx * 3 + k] * hs[k];
    att[tx] = 1.0f / (1.0f + expf(-a));
}

// ---------------- bf16 GEMM ----------------
template <int EPI, int MTILES, int KCH>
__global__ __launch_bounds__(256) void gemm_bf16(
    const __nv_bfloat16* __restrict__ A, const __nv_bfloat16* __restrict__ Wt,
    const float* __restrict__ bias, void* __restrict__ Cout, int Nn,
    const float* __restrict__ res1)
{
    const int MROWS = MTILES * 64;
    const int Ktot = KCH * 96;
    const int SE = (MROWS + 96) * 104;
    extern __shared__ __nv_bfloat16 smb[];
    int m0 = blockIdx.x * MROWS, n0 = blockIdx.y * 96;
    int tx = threadIdx.x;
    int warp = tx >> 5, lane = tx & 31;
    int wm = warp >> 1, wn = warp & 1;
    int gid = lane >> 2, tig = lane & 3;
    float acc[MTILES][6][4] = {};

    if (KCH == 1) {
        for (int idx = tx; idx < MROWS * 12; idx += 256) {
            int r = idx / 12, c = idx - r * 12;
            *(uint4*)(smb + r * 104 + c * 8) = *(const uint4*)(A + (size_t)(m0 + r) * Ktot + c * 8);
        }
        for (int idx = tx; idx < 1152; idx += 256) {
            int r = idx / 12, c = idx - r * 12;
            *(uint4*)(smb + (MROWS + r) * 104 + c * 8) = *(const uint4*)(Wt + (size_t)(n0 + r) * Ktot + c * 8);
        }
        __syncthreads();
    } else {
        for (int idx = tx; idx < MROWS * 12; idx += 256) {
            int r = idx / 12, c = idx - r * 12;
            cpa16(smb + r * 104 + c * 8, A + (size_t)(m0 + r) * Ktot + c * 8, true);
        }
        for (int idx = tx; idx < 1152; idx += 256) {
            int r = idx / 12, c = idx - r * 12;
            cpa16(smb + (MROWS + r) * 104 + c * 8, Wt + (size_t)(n0 + r) * Ktot + c * 8, true);
        }
        cpa_commit();
    }

    for (int kc = 0; kc < KCH; kc++) {
        if (KCH > 1) {
            if (kc + 1 < KCH) {
                int k0 = (kc + 1) * 96;
                __nv_bfloat16* st = smb + ((kc + 1) % 3) * SE;
                for (int idx = tx; idx < MROWS * 12; idx += 256) {
                    int r = idx / 12, c = idx - r * 12;
                    cpa16(st + r * 104 + c * 8, A + (size_t)(m0 + r) * Ktot + k0 + c * 8, true);
                }
                for (int idx = tx; idx < 1152; idx += 256) {
                    int r = idx / 12, c = idx - r * 12;
                    cpa16(st + (MROWS + r) * 104 + c * 8, Wt + (size_t)(n0 + r) * Ktot + k0 + c * 8, true);
                }
                cpa_commit();
                cpa_wait<1>();
            } else {
                cpa_wait<0>();
            }
            __syncthreads();
        }
        __nv_bfloat16* a_s = smb + (KCH > 1 ? (kc % 3) * SE : 0);
        __nv_bfloat16* w_s = a_s + MROWS * 104;
        unsigned a_u = (unsigned)__cvta_generic_to_shared(a_s);
        #pragma unroll
        for (int ks = 0; ks < 6; ks++) {
            unsigned af[MTILES][4];
            #pragma unroll
            for (int mt = 0; mt < MTILES; mt++)
                ldsm4(af[mt], a_u + 2u * ((wm * (MTILES * 16) + mt * 16 + (lane & 15)) * 104
                                          + ks * 16 + ((lane >> 4) << 3)));
            #pragma unroll
            for (int np = 0; np < 3; np++) {
                unsigned bf[4];
                ldsmB(bf, w_s + (wn * 48 + np * 16) * 104 + ks * 16, 104, lane);
                #pragma unroll
                for (int mt = 0; mt < MTILES; mt++) {
                    mma16(acc[mt][np * 2], af[mt], bf);
                    mma16(acc[mt][np * 2 + 1], af[mt], bf + 2);
                }
            }
        }
    }
    #pragma unroll
    for (int mt = 0; mt < MTILES; mt++) {
        #pragma unroll
        for (int nt = 0; nt < 6; nt++) {
            int cc = n0 + wn * 48 + nt * 8 + tig * 2;
            float bb0 = bias[cc], bb1 = bias[cc + 1];
            #pragma unroll
            for (int half = 0; half < 2; half++) {
                int r = m0 + wm * (MTILES * 16) + mt * 16 + gid + half * 8;
                size_t idx = (size_t)r * Nn + cc;
                float v0 = acc[mt][nt][half * 2 + 0] + bb0;
                float v1 = acc[mt][nt][half * 2 + 1] + bb1;
                if (EPI == 0) {
                    *(unsigned*)((__nv_bfloat16*)Cout + idx) = pack2(v0, v1);
                } else if (EPI == 1) {
                    *(unsigned*)((__nv_bfloat16*)Cout + idx) = pack2(gelu_exact(v0), gelu_exact(v1));
                } else {
                    float2 r1 = *(const float2*)(res1 + idx);
                    float2 o2;
                    o2.x = r1.x + v0;
                    o2.y = r1.y + v1;
                    *(float2*)((float*)Cout + idx) = o2;
                }
            }
        }
    }
}

// ---------------- proj GEMM + residual merge + fused LayerNorm2 ----------------
__global__ __launch_bounds__(256) void gemm_proj_ln(
    const __nv_bfloat16* __restrict__ A, const __nv_bfloat16* __restrict__ Wt,
    const float* __restrict__ bias,
    const float* __restrict__ res1, const __nv_bfloat16* __restrict__ res2,
    const float* __restrict__ att,
    const float* __restrict__ n2g, const float* __restrict__ n2b,
    float* __restrict__ x1, __nv_bfloat16* __restrict__ xn2)
{
    extern __shared__ __nv_bfloat16 smb[];
    __nv_bfloat16* a_s = smb;
    __nv_bfloat16* w_s = smb + 128 * 104;
    float* red_s = (float*)smb;
    float* red_q = red_s + 256;
    unsigned a_u = (unsigned)__cvta_generic_to_shared(a_s);
    int m0 = blockIdx.x * 128;
    int tx = threadIdx.x;
    int warp = tx >> 5, lane = tx & 31;
    int wm = warp >> 1, wn = warp & 1;
    int gid = lane >> 2, tig = lane & 3;
    float acc[2][6][4] = {};
    {
        for (int idx = tx; idx < 1536; idx += 256) {
            int r = idx / 12, c = idx - r * 12;
            *(uint4*)(a_s + r * 104 + c * 8) = *(const uint4*)(A + (size_t)(m0 + r) * 96 + c * 8);
        }
        for (int idx = tx; idx < 1152; idx += 256) {
            int r = idx / 12, c = idx - r * 12;
            *(uint4*)(w_s + r * 104 + c * 8) = *(const uint4*)(Wt + (size_t)r * 96 + c * 8);
        }
        __syncthreads();
        #pragma unroll
        for (int ks = 0; ks < 6; ks++) {
            unsigned af[2][4];
            #pragma unroll
            for (int mt = 0; mt < 2; mt++)
                ldsm4(af[mt], a_u + 2u * ((wm * 32 + mt * 16 + (lane & 15)) * 104
                                          + ks * 16 + ((lane >> 4) << 3)));
            #pragma unroll
            for (int np = 0; np < 3; np++) {
                unsigned bf[4];
                ldsmB(bf, w_s + (wn * 48 + np * 16) * 104 + ks * 16, 104, lane);
                #pragma unroll
                for (int mt = 0; mt < 2; mt++) {
                    mma16(acc[mt][np * 2], af[mt], bf);
                    mma16(acc[mt][np * 2 + 1], af[mt], bf + 2);
                }
            }
        }
    }
    __syncthreads();

    float rs[2][2] = {}, rq[2][2] = {};
    #pragma unroll
    for (int mt = 0; mt < 2; mt++) {
        #pragma unroll
        for (int nt = 0; nt < 6; nt++) {
            int cc = wn * 48 + nt * 8 + tig * 2;
            float bb0 = bias[cc], bb1 = bias[cc + 1];
            float a0 = att[cc] * 0.01f, a1 = att[cc + 1] * 0.01f;
            #pragma unroll
            for (int half = 0; half < 2; half++) {
                int r = m0 + wm * 32 + mt * 16 + gid + half * 8;
                size_t idx = (size_t)r * 96 + cc;
                float2 r1 = *(const float2*)(res1 + idx);
                float2 r2 = __bfloat1622float2(*(const __nv_bfloat162*)(res2 + idx));
                float v0 = r1.x + acc[mt][nt][half * 2 + 0] + bb0 + r2.x * a0;
                float v1 = r1.y + acc[mt][nt][half * 2 + 1] + bb1 + r2.y * a1;
                acc[mt][nt][half * 2 + 0] = v0;
                acc[mt][nt][half * 2 + 1] = v1;
                *(float2*)(x1 + idx) = make_float2(v0, v1);
                rs[mt][half] += v0 + v1;
                rq[mt][half] += v0 * v0 + v1 * v1;
            }
        }
    }
    #pragma unroll
    for (int mt = 0; mt < 2; mt++)
        #pragma unroll
        for (int half = 0; half < 2; half++) {
            float s = rs[mt][half], q = rq[mt][half];
            s += __shfl_xor_sync(0xffffffffu, s, 1);
            s += __shfl_xor_sync(0xffffffffu, s, 2);
            q += __shfl_xor_sync(0xffffffffu, q, 1);
            q += __shfl_xor_sync(0xffffffffu, q, 2);
            if (tig == 0) {
                int lr = wm * 32 + mt * 16 + half * 8 + gid;
                red_s[lr * 2 + wn] = s;
                red_q[lr * 2 + wn] = q;
            }
        }
    __syncthreads();
    #pragma unroll
    for (int mt = 0; mt < 2; mt++) {
        #pragma unroll
        for (int half = 0; half < 2; half++) {
            int lr = wm * 32 + mt * 16 + half * 8 + gid;
            float sum = red_s[lr * 2] + red_s[lr * 2 + 1];
            float sq  = red_q[lr * 2] + red_q[lr * 2 + 1];
            float mean = sum * (1.0f / 96.0f);
            float var = sq * (1.0f / 96.0f) - mean * mean;
            float inv = rsqrtf(var + 1e-5f);
            int r = m0 + lr;
            #pragma unroll
            for (int nt = 0; nt < 6; nt++) {
                int cc = wn * 48 + nt * 8 + tig * 2;
                float g0 = n2g[cc], g1 = n2g[cc + 1];
                float b0 = n2b[cc], b1 = n2b[cc + 1];
                float v0 = (acc[mt][nt][half * 2 + 0] - mean) * inv * g0 + b0;
                float v1 = (acc[mt][nt][half * 2 + 1] - mean) * inv * g1 + b1;
                *(unsigned*)(xn2 + (size_t)r * 96 + cc) = pack2(v0, v1);
            }
        }
    }
}

// ---------------- attention ----------------
#define OFF_Q  0
#define OFF_K  3072
#define OFF_V  27648
#define OFF_R1 44288
#define OFF_R2 45312
#define OFF_OR 46336
#define SMEM_ATTN 62720

__device__ __forceinline__ int wtok(int j, int base) {
    return ((j >> 6) << 12) + base + (((j >> 3) & 7) << 6) + (j & 7);
}

__global__ __launch_bounds__(512) void attn_kernel(
    const __nv_bfloat16* __restrict__ qkv, const __nv_bfloat16* __restrict__ biasb,
    __nv_bfloat16* __restrict__ o)
{
    extern __shared__ char smc[];
    __nv_bfloat16* q_s = (__nv_bfloat16*)(smc + OFF_Q);
    __nv_bfloat16* k_s = (__nv_bfloat16*)(smc + OFF_K);
    __nv_bfloat16* v_t = (__nv_bfloat16*)(smc + OFF_V);
    float* red1 = (float*)(smc + OFF_R1);
    float* red2 = (float*)(smc + OFF_R2);
    float* o_red = (float*)(smc + OFF_OR);
    unsigned q_u = (unsigned)__cvta_generic_to_shared(q_s);

    int blk = blockIdx.x;
    int qc = blk & 7;
    int head = (blk >> 3) % 6;
    int win = blk / 48;
    int base = (win >> 3) * 512 + (win & 7) * 8;
    int m0 = qc * 64;
    int tx = threadIdx.x;
    int warp = tx >> 5, lane = tx & 31;
    int gid = lane >> 2, tig = lane & 3;
    int wm = warp >> 2, wn = warp & 3;
    int r0 = wm * 16, j0 = wn * 128;

    for (int idx = tx; idx < 1024; idx += 512) {
        int j = idx >> 1, half = idx & 1;
        int t = wtok(j, base);
        const __nv_bfloat16* p = qkv + (size_t)t * 288 + head * 16 + half * 8;
        *(uint4*)(k_s + j * 24 + half * 8) = *(const uint4*)(p + 96);
        uint4 v4 = *(const uint4*)(p + 192);
        const __nv_bfloat16* vp = (const __nv_bfloat16*)&v4;
        #pragma unroll
        for (int dd2 = 0; dd2 < 8; dd2++)
            v_t[(half * 8 + dd2) * 520 + j] = vp[dd2];
    }
    if (tx < 128) {
        int i = tx >> 1, half = tx & 1;
        int t = wtok(m0 + i, base);
        uint4 raw = *(const uint4*)(qkv + (size_t)t * 288 + head * 16 + half * 8);
        const __nv_bfloat16* rp = (const __nv_bfloat16*)&raw;
        unsigned pk[4];
        #pragma unroll
        for (int e = 0; e < 4; e++)
            pk[e] = pack2(__bfloat162float(rp[e * 2]) * 0.25f,
                          __bfloat162float(rp[e * 2 + 1]) * 0.25f);
        *(uint4*)(q_s + i * 24 + half * 8) = *(uint4*)pk;
    }
    __syncthreads();

    float acc[16][4] = {};
    {
        unsigned aq[4];
        ldsm4(aq, q_u + 2u * ((r0 + (lane & 15)) * 24 + ((lane >> 4) << 3)));
        #pragma unroll
        for (int np = 0; np < 8; np++) {
            unsigned bf[4];
            ldsmB(bf, k_s + (j0 + np * 16) * 24, 24, lane);
            mma16(acc[np * 2], aq, bf);
            mma16(acc[np * 2 + 1], aq, bf + 2);
        }
        const __nv_bfloat16* bbA = biasb + ((size_t)head * 512 + (m0 + r0 + gid)) * 512 + j0 + tig * 2;
        const __nv_bfloat16* bbB = bbA + 8 * 512;
        #pragma unroll
        for (int nt = 0; nt < 16; nt++) {
            float2 fa = __bfloat1622float2(*(const __nv_bfloat162*)(bbA + nt * 8));
            float2 fb = __bfloat1622float2(*(const __nv_bfloat162*)(bbB + nt * 8));
            acc[nt][0] += fa.x; acc[nt][1] += fa.y;
            acc[nt][2] += fb.x; acc[nt][3] += fb.y;
        }
    }
    {
        float mA = -1e30f, mB = -1e30f;
        #pragma unroll
        for (int nt = 0; nt < 16; nt++) {
            mA = fmaxf(mA, fmaxf(acc[nt][0], acc[nt][1]));
            mB = fmaxf(mB, fmaxf(acc[nt][2], acc[nt][3]));
        }
        mA = fmaxf(mA, __shfl_xor_sync(0xffffffffu, mA, 1));
        mA = fmaxf(mA, __shfl_xor_sync(0xffffffffu, mA, 2));
        mB = fmaxf(mB, __shfl_xor_sync(0xffffffffu, mB, 1));
        mB = fmaxf(mB, __shfl_xor_sync(0xffffffffu, mB, 2));
        if (tig == 0) {
            red1[(r0 + gid) * 4 + wn] = mA;
            red1[(r0 + gid + 8) * 4 + wn] = mB;
        }
        __syncthreads();
        mA = fmaxf(fmaxf(red1[(r0 + gid) * 4 + 0], red1[(r0 + gid) * 4 + 1]),
                   fmaxf(red1[(r0 + gid) * 4 + 2], red1[(r0 + gid) * 4 + 3]));
        mB = fmaxf(fmaxf(red1[(r0 + gid + 8) * 4 + 0], red1[(r0 + gid + 8) * 4 + 1]),
                   fmaxf(red1[(r0 + gid + 8) * 4 + 2], red1[(r0 + gid + 8) * 4 + 3]));
        float sA = 0.f, sB = 0.f;
        #pragma unroll
        for (int nt = 0; nt < 16; nt++) {
            acc[nt][0] = __expf(acc[nt][0] - mA);
            acc[nt][1] = __expf(acc[nt][1] - mA);
            acc[nt][2] = __expf(acc[nt][2] - mB);
            acc[nt][3] = __expf(acc[nt][3] - mB);
            sA += acc[nt][0] + acc[nt][1];
            sB += acc[nt][2] + acc[nt][3];
        }
        sA += __shfl_xor_sync(0xffffffffu, sA, 1);
        sA += __shfl_xor_sync(0xffffffffu, sA, 2);
        sB += __shfl_xor_sync(0xffffffffu, sB, 1);
        sB += __shfl_xor_sync(0xffffffffu, sB, 2);
        if (tig == 0) {
            red2[(r0 + gid) * 4 + wn] = sA;
            red2[(r0 + gid + 8) * 4 + wn] = sB;
        }
        __syncthreads();
        sA = red2[(r0 + gid) * 4 + 0] + red2[(r0 + gid) * 4 + 1]
           + red2[(r0 + gid) * 4 + 2] + red2[(r0 + gid) * 4 + 3];
        sB = red2[(r0 + gid + 8) * 4 + 0] + red2[(r0 + gid + 8) * 4 + 1]
           + red2[(r0 + gid + 8) * 4 + 2] + red2[(r0 + gid + 8) * 4 + 3];
        float iA = 1.0f / sA, iB = 1.0f / sB;
        #pragma unroll
        for (int nt = 0; nt < 16; nt++) {
            acc[nt][0] *= iA; acc[nt][1] *= iA;
            acc[nt][2] *= iB; acc[nt][3] *= iB;
        }
    }

    float oa[2][4] = {};
    #pragma unroll
    for (int kk = 0; kk < 8; kk++) {
        unsigned af[4];
        af[0] = pack2(acc[2 * kk][0],     acc[2 * kk][1]);
        af[1] = pack2(acc[2 * kk][2],     acc[2 * kk][3]);
        af[2] = pack2(acc[2 * kk + 1][0], acc[2 * kk + 1][1]);
        af[3] = pack2(acc[2 * kk + 1][2], acc[2 * kk + 1][3]);
        unsigned bf[4];
        ldsmB(bf, v_t + j0 + kk * 16, 520, lane);
        mma16(oa[0], af, bf);
        mma16(oa[1], af, bf + 2);
    }
    {
        float* orp = o_red + (size_t)wn * 1024;
        #pragma unroll
        for (int dt = 0; dt < 2; dt++) {
            int dc = dt * 8 + tig * 2;
            *(float2*)(orp + (r0 + gid) * 16 + dc)     = make_float2(oa[dt][0], oa[dt][1]);
            *(float2*)(orp + (r0 + gid + 8) * 16 + dc) = make_float2(oa[dt][2], oa[dt][3]);
        }
    }
    __syncthreads();
    {
        int row = tx >> 3, d2 = tx & 7;
        int dim = d2 * 2;
        float v0 = 0.f, v1 = 0.f;
        #pragma unroll
        for (int p = 0; p < 4; p++) {
            v0 += o_red[p * 1024 + row * 16 + dim];
            v1 += o_red[p * 1024 + row * 16 + dim + 1];
        }
        int t = wtok(m0 + row, base);
        *(unsigned*)(o + (size_t)t * CCH + head * 16 + dim) = pack2(v0, v1);
    }
}

// ---------------- launch: fork/join DAG with PERSISTENT streams/events ----------------
extern "C" void kernel_launch(void* const* d_in, const int* in_sizes, int n_in,
                              void* d_out, int out_size)
{
    (void)in_sizes; (void)n_in; (void)out_size;
    const float* x       = (const float*)d_in[0];
    const float* n1g     = (const float*)d_in[1];
    const float* n1b     = (const float*)d_in[2];
    const float* qkv_w   = (const float*)d_in[3];
    const float* qkv_b   = (const float*)d_in[4];
    const float* rpbt    = (const float*)d_in[5];
    const float* proj_w  = (const float*)d_in[6];
    const float* proj_b  = (const float*)d_in[7];
    const float* conv1_w = (const float*)d_in[8];
    const float* conv1_b = (const float*)d_in[9];
    const float* conv2_w = (const float*)d_in[10];
    const float* conv2_b = (const float*)d_in[11];
    const float* ca1_w   = (const float*)d_in[12];
    const float* ca1_b   = (const float*)d_in[13];
    const float* ca2_w   = (const float*)d_in[14];
    const float* ca2_b   = (const float*)d_in[15];
    const float* n2g     = (const float*)d_in[16];
    const float* n2b     = (const float*)d_in[17];
    const float* fc1_w   = (const float*)d_in[18];
    const float* fc1_b   = (const float*)d_in[19];
    const float* fc2_w   = (const float*)d_in[20];
    const float* fc2_b   = (const float*)d_in[21];
    const int*   rpi     = (const int*)d_in[22];
    float* out = (float*)d_out;

    __nv_bfloat16 *xn, *y1, *y2, *qkvb, *biasb, *ob, *xn2, *hb, *w1r, *w2r, *qw, *pw, *f1w, *f2w;
    float *part, *att, *x1;
    cudaGetSymbolAddress((void**)&xn,    g_xn);
    cudaGetSymbolAddress((void**)&y1,    g_y1);
    cudaGetSymbolAddress((void**)&y2,    g_y2);
    cudaGetSymbolAddress((void**)&part,  g_part);
    cudaGetSymbolAddress((void**)&att,   g_att);
    cudaGetSymbolAddress((void**)&qkvb,  g_qkv);
    cudaGetSymbolAddress((void**)&biasb, g_bias);
    cudaGetSymbolAddress((void**)&ob,    g_o);
    cudaGetSymbolAddress((void**)&x1,    g_x1);
    cudaGetSymbolAddress((void**)&xn2,   g_xn2);
    cudaGetSymbolAddress((void**)&hb,    g_h);
    cudaGetSymbolAddress((void**)&w1r,   g_w1r);
    cudaGetSymbolAddress((void**)&w2r,   g_w2r);
    cudaGetSymbolAddress((void**)&qw,    g_qw);
    cudaGetSymbolAddress((void**)&pw,    g_pw);
    cudaGetSymbolAddress((void**)&f1w,   g_f1w);
    cudaGetSymbolAddress((void**)&f2w,   g_f2w);

    const int SMEM_CONV1 = 3 * C1_SE * 2;
    const int SMEM_CONV2 = 3 * C2_SE * 2;
    const int SMEM_G128  = (128 + 96) * 104 * 2;
    const int SMEM_G64P  = 3 * (64 + 96) * 104 * 2;

    // Persistent host objects: created ONCE (first call = eager correctness run,
    // before the harness's pre-capture memory baseline), reused afterwards so
    // device memory stays flat across capture/replay/teardown.
    static bool s_init = false;
    static cudaStream_t sW, sC;
    static cudaEvent_t eFork, eLn, eW, eConv;
    if (!s_init) {
        cudaStreamCreateWithFlags(&sW, cudaStreamNonBlocking);
        cudaStreamCreateWithFlags(&sC, cudaStreamNonBlocking);
        cudaEventCreateWithFlags(&eFork, cudaEventDisableTiming);
        cudaEventCreateWithFlags(&eLn,   cudaEventDisableTiming);
        cudaEventCreateWithFlags(&eW,    cudaEventDisableTiming);
        cudaEventCreateWithFlags(&eConv, cudaEventDisableTiming);
        cudaFuncSetAttribute(conv1_kernel, cudaFuncAttributeMaxDynamicSharedMemorySize, SMEM_CONV1);
        cudaFuncSetAttribute(conv2_kernel, cudaFuncAttributeMaxDynamicSharedMemorySize, SMEM_CONV2);
        cudaFuncSetAttribute(gemm_bf16<0, 2, 1>, cudaFuncAttributeMaxDynamicSharedMemorySize, SMEM_G128);
        cudaFuncSetAttribute(gemm_bf16<1, 2, 1>, cudaFuncAttributeMaxDynamicSharedMemorySize, SMEM_G128);
        cudaFuncSetAttribute(gemm_bf16<3, 1, 4>, cudaFuncAttributeMaxDynamicSharedMemorySize, SMEM_G64P);
        cudaFuncSetAttribute(gemm_proj_ln, cudaFuncAttributeMaxDynamicSharedMemorySize, SMEM_G128);
        cudaFuncSetAttribute(attn_kernel, cudaFuncAttributeMaxDynamicSharedMemorySize, SMEM_ATTN);
        s_init = true;
    }

    // ORIGIN records the fork first (legal capture topology).
    cudaEventRecord(eFork, 0);

    // stream W (forked from origin): weight conversions
    cudaStreamWaitEvent(sW, eFork, 0);
    setup_w_kernel<<<1080, 256, 0, sW>>>(qkv_w, proj_w, fc1_w, fc2_w, conv1_w, conv2_w,
                                         qw, pw, f1w, f2w, w1r, w2r);
    cudaEventRecord(eW, sW);

    // origin: LN1
    ln_kernel<<<LTOK / 8, 256>>>(x, n1g, n1b, xn);
    cudaEventRecord(eLn, 0);

    // stream C (forked after ln): conv branch — needs ln output + conv weights
    cudaStreamWaitEvent(sC, eLn, 0);
    cudaStreamWaitEvent(sC, eW, 0);
    conv1_kernel<<<512, 256, SMEM_CONV1, sC>>>(xn, w1r, conv1_b, y1);
    conv2_kernel<<<512, 256, SMEM_CONV2, sC>>>(y1, w2r, conv2_b, y2, part);
    ca_kernel<<<1, CCH, 0, sC>>>(part, ca1_w, ca1_b, ca2_w, ca2_b, att);
    cudaEventRecord(eConv, sC);

    // origin: bias expansion (overlaps conv branch), then attention branch
    setup_bias_kernel<<<6144, 256>>>(rpi, rpbt, biasb);
    cudaStreamWaitEvent(0, eW, 0);
    gemm_bf16<0, 2, 1><<<dim3(LTOK / 128, 3), 256, SMEM_G128>>>(
        xn, qw, qkv_b, qkvb, 288, nullptr);
    attn_kernel<<<NWIN * HEADS * 8, 512, SMEM_ATTN>>>(qkvb, biasb, ob);

    // join + tail
    cudaStreamWaitEvent(0, eConv, 0);
    gemm_proj_ln<<<LTOK / 128, 256, SMEM_G128>>>(
        ob, pw, proj_b, x, y2, att, n2g, n2b, x1, xn2);
    gemm_bf16<1, 2, 1><<<dim3(LTOK / 128, 4), 256, SMEM_G128>>>(
        xn2, f1w, fc1_b, hb, 384, nullptr);
    gemm_bf16<3, 1, 4><<<dim3(LTOK / 64, 1), 256, SMEM_G64P>>>(
        hb, f2w, fc2_b, out, 96, x1);
}